// round 12
// baseline (speedup 1.0000x reference)
#include <cuda_runtime.h>
#include <math.h>
#include <stdint.h>

// Problem constants (fixed shapes)
#define Bc   2
#define Nn   8192
#define Ff   128
#define Ee   131072
#define Hh   256
#define NHh  4
#define Dd   64
#define FEATN 268
#define FEATP 288          // padded K for GEMM1
#define BE   (Bc*Ee)       // 262144 edge rows
#define BNr  (Bc*Nn)       // 16384 node rows

// ---------------- static scratch ----------------
static __device__ float g_ef[(size_t)BE * Hh];     // raw (pre-LN) edge features
static __device__ float g_stats[(size_t)BE * 2];   // per row: sum, sumsq (atomic-accumulated)
static __device__ float g_geo[(size_t)BE * 32];
static __device__ float g_cdiff[BE * 3];
static __device__ float g_wsc[BE];
static __device__ float g_agg[BNr * Hh];
static __device__ float g_nodemid[BNr * Hh];
// pre-transposed, pre-tf32 weights: BT[n][k]
static __device__ uint32_t g_w1T[Hh * FEATP];
static __device__ uint32_t g_w2T[2 * 128 * 128];
static __device__ uint32_t g_cw1T[Hh * Hh];
static __device__ uint32_t g_nw1T[Hh * (Hh + Ff)];
static __device__ uint32_t g_nw2T[Ff * Hh];

// ---------------- helpers ----------------
__device__ __forceinline__ uint32_t f2tf(float x) {
    uint32_t r; asm("cvt.rna.tf32.f32 %0, %1;" : "=r"(r) : "f"(x)); return r;
}
__device__ __forceinline__ void ldsm4(uint32_t& r0, uint32_t& r1, uint32_t& r2, uint32_t& r3, uint32_t a) {
    asm volatile("ldmatrix.sync.aligned.m8n8.x4.shared.b16 {%0,%1,%2,%3}, [%4];"
                 : "=r"(r0), "=r"(r1), "=r"(r2), "=r"(r3) : "r"(a));
}
__device__ __forceinline__ void mma8(float* c, const uint32_t* a, const uint32_t* b) {
    asm volatile("mma.sync.aligned.m16n8k8.row.col.f32.tf32.tf32.f32 "
                 "{%0,%1,%2,%3}, {%4,%5,%6,%7}, {%8,%9}, {%0,%1,%2,%3};"
                 : "+f"(c[0]), "+f"(c[1]), "+f"(c[2]), "+f"(c[3])
                 : "r"(a[0]), "r"(a[1]), "r"(a[2]), "r"(a[3]), "r"(b[0]), "r"(b[1]));
}
__device__ __forceinline__ float silu_f(float x) { return x / (1.f + expf(-x)); }
__device__ __forceinline__ void red4(float* addr, float4 v) {
    asm volatile("red.global.add.v4.f32 [%0], {%1,%2,%3,%4};"
                 :: "l"(addr), "f"(v.x), "f"(v.y), "f"(v.z), "f"(v.w) : "memory");
}

// ---------------- combined init ----------------
__global__ void k_misc(const float* __restrict__ coord, float* __restrict__ outc,
                       const float* __restrict__ w1, const float* __restrict__ w2,
                       const float* __restrict__ cw1, const float* __restrict__ nw1,
                       const float* __restrict__ nw2) {
    int idx = blockIdx.x * blockDim.x + threadIdx.x;
    if (idx < BNr * Hh) g_agg[idx] = 0.f;
    if (idx < BE) g_wsc[idx] = 0.f;
    if (idx < BE * 2) g_stats[idx] = 0.f;
    if (idx < Bc * Nn * 3) outc[idx] = coord[idx];
    if (idx < Hh * FEATP) {
        int n = idx / FEATP, f = idx - n * FEATP;
        g_w1T[idx] = (f < FEATN) ? f2tf(w1[(((n >> 6) * FEATN) + f) * Dd + (n & 63)]) : 0u;
    }
    if (idx < 2 * 128 * 128) {
        int p = idx >> 14, n = (idx >> 7) & 127, k = idx & 127;
        g_w2T[idx] = ((k >> 6) == (n >> 6))
            ? f2tf(w2[((p << 1) + (n >> 6)) * (Dd * Dd) + (k & 63) * Dd + (n & 63)]) : 0u;
    }
    if (idx < Hh * Hh) {
        int n = idx >> 8, k = idx & 255;
        g_cw1T[idx] = f2tf(cw1[k * Hh + n]);
    }
    if (idx < Hh * (Hh + Ff)) {
        int n = idx / (Hh + Ff), k = idx - n * (Hh + Ff);
        g_nw1T[idx] = f2tf(nw1[k * Hh + n]);
    }
    if (idx < Ff * Hh) {
        int n = idx >> 8, k = idx & 255;
        g_nw2T[idx] = f2tf(nw2[k * Ff + n]);
    }
}

// geometry features per edge (thread per edge)
__global__ void k_geo(const float* __restrict__ coord, const int* __restrict__ ei) {
    int e = blockIdx.x * blockDim.x + threadIdx.x;
    if (e >= BE) return;
    int b = (e >= Ee) ? 1 : 0, j = e - b * Ee;
    int i = ei[j], k = ei[Ee + j];
    const float* ci = coord + ((size_t)b * Nn + i) * 3;
    const float* ck = coord + ((size_t)b * Nn + k) * 3;
    float cix = ci[0], ciy = ci[1], ciz = ci[2];
    float ckx = ck[0], cky = ck[1], ckz = ck[2];
    float dx = cix - ckx, dy = ciy - cky, dz = ciz - ckz;
    float radial = dx * dx + dy * dy + dz * dz;
    float dist = sqrtf(radial);
    float dotv = cix * ckx + ciy * cky + ciz * ckz;
    float inva = 1.f / (dist + 1e-8f);
    float ax = dx * inva, ay = dy * inva, az = dz * inva;
    float crx = ciy * ckz - ciz * cky;
    float cry = ciz * ckx - cix * ckz;
    float crz = cix * cky - ciy * ckx;
    float nb = sqrtf(crx * crx + cry * cry + crz * crz);
    float invb = 1.f / (nb + 1e-8f);
    float bx = crx * invb, by = cry * invb, bz = crz * invb;
    float cx = ay * bz - az * by;
    float cy = az * bx - ax * bz;
    float cz = ax * by - ay * bx;
    float na  = sqrtf(ax * ax + ay * ay + az * az);
    float nbv = sqrtf(bx * bx + by * by + bz * bz);
    float ncv = sqrtf(cx * cx + cy * cy + cz * cz);
    bool bad = (na < 1e-6f) || (nbv < 1e-6f) || (ncv < 1e-6f);
    if (bad) { ax = 1.f; bx = 0.f; cx = 0.f;
               ay = 0.f; by = 1.f; cy = 0.f;
               az = 0.f; bz = 0.f; cz = 1.f; }
    float4* g = (float4*)(g_geo + (size_t)e * 32);
    g[0] = make_float4(radial, dist, dotv, ax);
    g[1] = make_float4(bx, cx, ay, by);
    g[2] = make_float4(cy, az, bz, cz);
    float4 z = make_float4(0.f, 0.f, 0.f, 0.f);
    g[3] = z; g[4] = z; g[5] = z; g[6] = z; g[7] = z;
    g_cdiff[e * 3 + 0] = dx;
    g_cdiff[e * 3 + 1] = dy;
    g_cdiff[e * 3 + 2] = dz;
}

// ---------------- tf32 tensor-core GEMM (double-buffered smem) ----------------
// Block tile 128x128, BK=32, 8 warps (2x4), warp tile 64x32.
// EPI: 2 bias+silu, 3 bias+residual, 4 bias+silu+dot(extra)->atomic wsc (no store)
// MODE: 0 normal A, 2 node-split A (h 128 | agg 256), 3 A with inline LayerNorm (stats/gam/bet)
#define AST 36
#define BST 36
#define MST 132
#define GT_BUF (128 * (AST + BST))
#define GT_SMEM (2 * GT_BUF * 4)

template <int EPI, int MODE>
__global__ void __launch_bounds__(256, 2) k_gemm_t(
    const float* __restrict__ A, const float* __restrict__ A2,
    const uint32_t* __restrict__ BT, float* __restrict__ C,
    int K, int lda, int ldbT, int ldc,
    const float* __restrict__ bias, const float* __restrict__ extra, int ldr,
    float* __restrict__ wsc, const float* __restrict__ stats,
    const float* __restrict__ gam, const float* __restrict__ bet)
{
    extern __shared__ uint32_t smbuf[];
    const int tid = threadIdx.x, lane = tid & 31, wid = tid >> 5;
    const int wm = wid >> 2, wn = wid & 3;
    const int m0 = blockIdx.y * 128, n0 = blockIdx.x * 128;

    const int am = tid >> 3;
    const int ak = (tid & 7) << 2;

    const uint32_t* BTg = BT + (size_t)n0 * ldbT;

    const float* pA[4]; const float* pS[4];
    float mu_r[4], rs_r[4];
#pragma unroll
    for (int i = 0; i < 4; i++) {
        int r = m0 + am + 32 * i;
        if (MODE == 2) {
            pA[i] = A + (size_t)r * 128;
            pS[i] = A2 + (size_t)r * 256;
        } else {
            pA[i] = A + (size_t)r * lda;
        }
        if (MODE == 3) {
            float2 st = *(const float2*)(stats + 2 * (size_t)r);
            float mu = st.x * (1.f / 256.f);
            float var = st.y * (1.f / 256.f) - mu * mu;
            mu_r[i] = mu;
            rs_r[i] = rsqrtf(var + 1e-5f);
        }
    }
    auto loadA = [&](int i, int kcol) -> float4 {
        if (MODE == 2) {
            if (kcol < 128) return *(const float4*)(pA[i] + kcol);
            return *(const float4*)(pS[i] + (kcol - 128));
        }
        return *(const float4*)(pA[i] + kcol);
    };

    float acc[4][4][4];
#pragma unroll
    for (int i = 0; i < 4; i++)
#pragma unroll
        for (int j = 0; j < 4; j++) { acc[i][j][0] = 0.f; acc[i][j][1] = 0.f; acc[i][j][2] = 0.f; acc[i][j][3] = 0.f; }

    float4 pa[4]; uint4 pb[4];
#pragma unroll
    for (int i = 0; i < 4; i++) {
        pa[i] = loadA(i, ak);
        pb[i] = *(const uint4*)(BTg + (size_t)(am + 32 * i) * ldbT + ak);
    }

    const uint32_t as_base = (uint32_t)__cvta_generic_to_shared(smbuf);
    const uint32_t bs_base = as_base + 128 * AST * 4;
    const int a_r = wm * 64 + (lane & 15);
    const int a_q = (lane >> 4) << 2;
    const int b_r = wn * 32 + (lane & 7) + ((lane >> 4) << 3);
    const int b_q = ((lane >> 3) & 1) << 2;

    auto storeTiles = [&](int p, int kbase) {
        uint32_t* Ab = smbuf + p * GT_BUF;
        uint32_t* Bb = Ab + 128 * AST;
        float4 gm4, bt4;
        if (MODE == 3) {
            gm4 = *(const float4*)(gam + kbase + ak);
            bt4 = *(const float4*)(bet + kbase + ak);
        }
#pragma unroll
        for (int i = 0; i < 4; i++) {
            float4 v = pa[i];
            if (MODE == 3) {
                v.x = (v.x - mu_r[i]) * rs_r[i] * gm4.x + bt4.x;
                v.y = (v.y - mu_r[i]) * rs_r[i] * gm4.y + bt4.y;
                v.z = (v.z - mu_r[i]) * rs_r[i] * gm4.z + bt4.z;
                v.w = (v.w - mu_r[i]) * rs_r[i] * gm4.w + bt4.w;
            }
            *(uint4*)&Ab[(am + 32 * i) * AST + ak] =
                make_uint4(f2tf(v.x), f2tf(v.y), f2tf(v.z), f2tf(v.w));
            *(uint4*)&Bb[(am + 32 * i) * BST + ak] = pb[i];
        }
    };

    storeTiles(0, 0);
    __syncthreads();

    int p = 0;
    for (int k0 = 0; k0 < K; k0 += 32) {
        bool more = (k0 + 32 < K);
        if (more) {
#pragma unroll
            for (int i = 0; i < 4; i++) {
                pa[i] = loadA(i, k0 + 32 + ak);
                pb[i] = *(const uint4*)(BTg + (size_t)(am + 32 * i) * ldbT + k0 + 32 + ak);
            }
        }
        const uint32_t ab = as_base + p * (GT_BUF * 4);
        const uint32_t bb = bs_base + p * (GT_BUF * 4);
#pragma unroll
        for (int kk = 0; kk < 4; kk++) {
            uint32_t af[4][4], bf[4][2];
#pragma unroll
            for (int mi = 0; mi < 4; mi++)
                ldsm4(af[mi][0], af[mi][1], af[mi][2], af[mi][3],
                      ab + (((a_r + mi * 16) * AST + kk * 8 + a_q) << 2));
#pragma unroll
            for (int np = 0; np < 2; np++) {
                uint32_t r0, r1, r2, r3;
                ldsm4(r0, r1, r2, r3,
                      bb + (((b_r + np * 16) * BST + kk * 8 + b_q) << 2));
                bf[np * 2][0] = r0; bf[np * 2][1] = r1;
                bf[np * 2 + 1][0] = r2; bf[np * 2 + 1][1] = r3;
            }
#pragma unroll
            for (int mi = 0; mi < 4; mi++)
#pragma unroll
                for (int ni = 0; ni < 4; ni++)
                    mma8(acc[mi][ni], af[mi], bf[ni]);
        }
        if (more) storeTiles(p ^ 1, k0 + 32);
        __syncthreads();
        p ^= 1;
    }

    // ---------------- epilogue ----------------
    const int row0 = m0 + wm * 64 + (lane >> 2);
    const int colw = wn * 32 + ((lane & 3) << 1);
#pragma unroll
    for (int mi = 0; mi < 4; mi++) {
        float slo = 0.f, shi = 0.f;
        int r = row0 + mi * 16;
#pragma unroll
        for (int ni = 0; ni < 4; ni++) {
            int col = n0 + colw + ni * 8;
            float2 bb = *(const float2*)(bias + col);
            float v0 = acc[mi][ni][0] + bb.x, v1 = acc[mi][ni][1] + bb.y;
            float v2 = acc[mi][ni][2] + bb.x, v3 = acc[mi][ni][3] + bb.y;
            if (EPI == 2 || EPI == 4) {
                v0 = silu_f(v0); v1 = silu_f(v1); v2 = silu_f(v2); v3 = silu_f(v3);
            }
            if (EPI == 3) {
                float2 ra = *(const float2*)(extra + (size_t)r * ldr + col);
                float2 rb = *(const float2*)(extra + (size_t)(r + 8) * ldr + col);
                v0 += ra.x; v1 += ra.y; v2 += rb.x; v3 += rb.y;
            }
            if (EPI == 4) {
                float2 w = *(const float2*)(extra + col);
                slo += v0 * w.x + v1 * w.y;
                shi += v2 * w.x + v3 * w.y;
            } else {
                *(float2*)(C + (size_t)r * ldc + col)       = make_float2(v0, v1);
                *(float2*)(C + (size_t)(r + 8) * ldc + col) = make_float2(v2, v3);
            }
        }
        if (EPI == 4) {
            slo += __shfl_xor_sync(0xffffffffu, slo, 1);
            slo += __shfl_xor_sync(0xffffffffu, slo, 2);
            shi += __shfl_xor_sync(0xffffffffu, shi, 1);
            shi += __shfl_xor_sync(0xffffffffu, shi, 2);
            if ((lane & 3) == 0) {
                atomicAdd(wsc + r, slo);
                atomicAdd(wsc + r + 8, shi);
            }
        }
    }
}

// ---------------- fused GEMM1+GEMM2 (+LN partial stats via atomics) ----------------
__global__ void __launch_bounds__(256, 2) k_gemm12(
    const float* __restrict__ h, const uint32_t* __restrict__ w1T,
    const uint32_t* __restrict__ w2T, float* __restrict__ ef,
    const int* __restrict__ ei, const float* __restrict__ geo,
    const float* __restrict__ b1, const float* __restrict__ b2,
    float* __restrict__ stats)
{
    extern __shared__ uint32_t sm[];
    uint32_t* As = sm;
    uint32_t* Bs = sm + 128 * AST;
    uint32_t* Ms = sm + 128 * (AST + BST);
    const int tid = threadIdx.x, lane = tid & 31, wid = tid >> 5;
    const int wm = wid >> 2, wn = wid & 3;
    const int m0 = blockIdx.y * 128, n0 = blockIdx.x * 128;

    const int am = tid >> 3;
    const int ak = (tid & 7) << 2;

    const uint32_t* BTg = w1T + (size_t)n0 * FEATP;

    const float* pA[4]; const float* pS[4]; const float* pG[4];
    {
        int b = (m0 >= Ee) ? 1 : 0;
#pragma unroll
        for (int i = 0; i < 4; i++) {
            int r = m0 + am + 32 * i;
            int j = r - b * Ee;
            pA[i] = h + ((size_t)b * Nn + ei[j]) * Ff;
            pS[i] = h + ((size_t)b * Nn + ei[Ee + j]) * Ff;
            pG[i] = geo + (size_t)r * 32;
        }
    }
    auto loadA = [&](int i, int kcol) -> float4 {
        if (kcol < 128) return *(const float4*)(pA[i] + kcol);
        if (kcol < 256) return *(const float4*)(pS[i] + (kcol - 128));
        return *(const float4*)(pG[i] + (kcol - 256));
    };

    float acc[4][4][4];
#pragma unroll
    for (int i = 0; i < 4; i++)
#pragma unroll
        for (int j = 0; j < 4; j++) { acc[i][j][0] = 0.f; acc[i][j][1] = 0.f; acc[i][j][2] = 0.f; acc[i][j][3] = 0.f; }

    float4 pa[4]; uint4 pb[4];
#pragma unroll
    for (int i = 0; i < 4; i++) {
        pa[i] = loadA(i, ak);
        pb[i] = *(const uint4*)(BTg + (size_t)(am + 32 * i) * FEATP + ak);
    }

    const uint32_t as_base = (uint32_t)__cvta_generic_to_shared(As);
    const uint32_t bs_base = (uint32_t)__cvta_generic_to_shared(Bs);
    const uint32_t ms_base = (uint32_t)__cvta_generic_to_shared(Ms);
    const int a_r = wm * 64 + (lane & 15);
    const int a_q = (lane >> 4) << 2;
    const int b_r = wn * 32 + (lane & 7) + ((lane >> 4) << 3);
    const int b_q = ((lane >> 3) & 1) << 2;

    // ---- stage 1 mainloop, K=288 ----
    for (int k0 = 0; k0 < FEATP; k0 += 32) {
#pragma unroll
        for (int i = 0; i < 4; i++) {
            *(uint4*)&As[(am + 32 * i) * AST + ak] =
                make_uint4(f2tf(pa[i].x), f2tf(pa[i].y), f2tf(pa[i].z), f2tf(pa[i].w));
            *(uint4*)&Bs[(am + 32 * i) * BST + ak] = pb[i];
        }
        __syncthreads();
        if (k0 + 32 < FEATP) {
#pragma unroll
            for (int i = 0; i < 4; i++) {
                pa[i] = loadA(i, k0 + 32 + ak);
                pb[i] = *(const uint4*)(BTg + (size_t)(am + 32 * i) * FEATP + k0 + 32 + ak);
            }
        }
#pragma unroll
        for (int kk = 0; kk < 4; kk++) {
            uint32_t af[4][4], bf[4][2];
#pragma unroll
            for (int mi = 0; mi < 4; mi++)
                ldsm4(af[mi][0], af[mi][1], af[mi][2], af[mi][3],
                      as_base + (((a_r + mi * 16) * AST + kk * 8 + a_q) << 2));
#pragma unroll
            for (int np = 0; np < 2; np++) {
                uint32_t r0, r1, r2, r3;
                ldsm4(r0, r1, r2, r3,
                      bs_base + (((b_r + np * 16) * BST + kk * 8 + b_q) << 2));
                bf[np * 2][0] = r0; bf[np * 2][1] = r1;
                bf[np * 2 + 1][0] = r2; bf[np * 2 + 1][1] = r3;
            }
#pragma unroll
            for (int mi = 0; mi < 4; mi++)
#pragma unroll
                for (int ni = 0; ni < 4; ni++)
                    mma8(acc[mi][ni], af[mi], bf[ni]);
        }
        __syncthreads();
    }

    // ---- epilogue 1: silu + bias -> Ms (tf32), reset acc ----
    const int lrow0 = wm * 64 + (lane >> 2);
    const int lcolw = wn * 32 + ((lane & 3) << 1);
#pragma unroll
    for (int mi = 0; mi < 4; mi++) {
        int r = lrow0 + mi * 16;
#pragma unroll
        for (int ni = 0; ni < 4; ni++) {
            int col = lcolw + ni * 8;
            float2 bb = *(const float2*)(b1 + n0 + col);
            float v0 = silu_f(acc[mi][ni][0] + bb.x);
            float v1 = silu_f(acc[mi][ni][1] + bb.y);
            float v2 = silu_f(acc[mi][ni][2] + bb.x);
            float v3 = silu_f(acc[mi][ni][3] + bb.y);
            *(uint2*)&Ms[r * MST + col]       = make_uint2(f2tf(v0), f2tf(v1));
            *(uint2*)&Ms[(r + 8) * MST + col] = make_uint2(f2tf(v2), f2tf(v3));
            acc[mi][ni][0] = 0.f; acc[mi][ni][1] = 0.f;
            acc[mi][ni][2] = 0.f; acc[mi][ni][3] = 0.f;
        }
    }

    // ---- stage 2 mainloop, K=128, A from Ms, B = w2 pair tile ----
    const uint32_t* W2 = w2T + (size_t)blockIdx.x * (128 * 128);
    for (int k0 = 0; k0 < 128; k0 += 32) {
#pragma unroll
        for (int i = 0; i < 4; i++)
            *(uint4*)&Bs[(am + 32 * i) * BST + ak] =
                *(const uint4*)(W2 + (size_t)(am + 32 * i) * 128 + k0 + ak);
        __syncthreads();
#pragma unroll
        for (int kk = 0; kk < 4; kk++) {
            uint32_t af[4][4], bf[4][2];
#pragma unroll
            for (int mi = 0; mi < 4; mi++)
                ldsm4(af[mi][0], af[mi][1], af[mi][2], af[mi][3],
                      ms_base + (((a_r + mi * 16) * MST + k0 + kk * 8 + a_q) << 2));
#pragma unroll
            for (int np = 0; np < 2; np++) {
                uint32_t r0, r1, r2, r3;
                ldsm4(r0, r1, r2, r3,
                      bs_base + (((b_r + np * 16) * BST + kk * 8 + b_q) << 2));
                bf[np * 2][0] = r0; bf[np * 2][1] = r1;
                bf[np * 2 + 1][0] = r2; bf[np * 2 + 1][1] = r3;
            }
#pragma unroll
            for (int mi = 0; mi < 4; mi++)
#pragma unroll
                for (int ni = 0; ni < 4; ni++)
                    mma8(acc[mi][ni], af[mi], bf[ni]);
        }
        __syncthreads();
    }

    // ---- epilogue 2: + b2, store f32 to ef, LN partial stats via atomics ----
#pragma unroll
    for (int mi = 0; mi < 4; mi++) {
        int r = m0 + lrow0 + mi * 16;
        float s_lo = 0.f, ss_lo = 0.f, s_hi = 0.f, ss_hi = 0.f;
#pragma unroll
        for (int ni = 0; ni < 4; ni++) {
            int col = n0 + lcolw + ni * 8;
            float2 bb = *(const float2*)(b2 + col);
            float v0 = acc[mi][ni][0] + bb.x, v1 = acc[mi][ni][1] + bb.y;
            float v2 = acc[mi][ni][2] + bb.x, v3 = acc[mi][ni][3] + bb.y;
            *(float2*)(ef + (size_t)r * Hh + col)       = make_float2(v0, v1);
            *(float2*)(ef + (size_t)(r + 8) * Hh + col) = make_float2(v2, v3);
            s_lo += v0 + v1; ss_lo += v0 * v0 + v1 * v1;
            s_hi += v2 + v3; ss_hi += v2 * v2 + v3 * v3;
        }
        s_lo  += __shfl_xor_sync(0xffffffffu, s_lo, 1);
        s_lo  += __shfl_xor_sync(0xffffffffu, s_lo, 2);
        ss_lo += __shfl_xor_sync(0xffffffffu, ss_lo, 1);
        ss_lo += __shfl_xor_sync(0xffffffffu, ss_lo, 2);
        s_hi  += __shfl_xor_sync(0xffffffffu, s_hi, 1);
        s_hi  += __shfl_xor_sync(0xffffffffu, s_hi, 2);
        ss_hi += __shfl_xor_sync(0xffffffffu, ss_hi, 1);
        ss_hi += __shfl_xor_sync(0xffffffffu, ss_hi, 2);
        if ((lane & 3) == 0) {
            atomicAdd(stats + 2 * (size_t)r,           s_lo);
            atomicAdd(stats + 2 * (size_t)r + 1,       ss_lo);
            atomicAdd(stats + 2 * (size_t)(r + 8),     s_hi);
            atomicAdd(stats + 2 * (size_t)(r + 8) + 1, ss_hi);
        }
    }
}

// LN (from stats, registers only) + agg segment-sum. One warp per edge. No ef write.
__global__ void k_aggscatter(const float* __restrict__ gam, const float* __restrict__ bet,
                             const int* __restrict__ ei) {
    int wid = blockIdx.x * (blockDim.x >> 5) + (threadIdx.x >> 5);
    int lane = threadIdx.x & 31;
    if (wid >= BE) return;
    const float* row = g_ef + (size_t)wid * Hh;
    float2 st = *(const float2*)(g_stats + 2 * (size_t)wid);
    float mu = st.x * (1.f / 256.f);
    float var = st.y * (1.f / 256.f) - mu * mu;
    float rstd = rsqrtf(var + 1e-5f);
    float4 x0 = ((const float4*)row)[lane];
    float4 x1 = ((const float4*)row)[lane + 32];
    float4 g0 = ((const float4*)gam)[lane], g1 = ((const float4*)gam)[lane + 32];
    float4 b0 = ((const float4*)bet)[lane], b1 = ((const float4*)bet)[lane + 32];
    x0.x = (x0.x - mu) * rstd * g0.x + b0.x;
    x0.y = (x0.y - mu) * rstd * g0.y + b0.y;
    x0.z = (x0.z - mu) * rstd * g0.z + b0.z;
    x0.w = (x0.w - mu) * rstd * g0.w + b0.w;
    x1.x = (x1.x - mu) * rstd * g1.x + b1.x;
    x1.y = (x1.y - mu) * rstd * g1.y + b1.y;
    x1.z = (x1.z - mu) * rstd * g1.z + b1.z;
    x1.w = (x1.w - mu) * rstd * g1.w + b1.w;
    int b = (wid >= Ee) ? 1 : 0, j = wid - b * Ee;
    int i = ei[j];
    float* arow = g_agg + ((size_t)b * Nn + i) * Hh;
    red4(arow + 4 * lane, x0);
    red4(arow + 128 + 4 * lane, x1);
}

// coord scatter: thread per edge
__global__ void k_coordscatter(const int* __restrict__ ei, float* __restrict__ outc) {
    int e = blockIdx.x * blockDim.x + threadIdx.x;
    if (e >= BE) return;
    int b = (e >= Ee) ? 1 : 0, j = e - b * Ee;
    int i = ei[j];
    float wv = g_wsc[e];
    float* dst = outc + ((size_t)b * Nn + i) * 3;
    atomicAdd(dst + 0, g_cdiff[e * 3 + 0] * wv);
    atomicAdd(dst + 1, g_cdiff[e * 3 + 1] * wv);
    atomicAdd(dst + 2, g_cdiff[e * 3 + 2] * wv);
}

// ---------------- launch ----------------
extern "C" void kernel_launch(void* const* d_in, const int* in_sizes, int n_in,
                              void* d_out, int out_size) {
    const float* h     = (const float*)d_in[0];
    const float* coord = (const float*)d_in[1];
    const int*   ei    = (const int*)d_in[2];
    const float* ew1   = (const float*)d_in[3];
    const float* eb1   = (const float*)d_in[4];
    const float* ew2   = (const float*)d_in[5];
    const float* eb2   = (const float*)d_in[6];
    const float* lng   = (const float*)d_in[7];
    const float* lnb   = (const float*)d_in[8];
    const float* nw1   = (const float*)d_in[9];
    const float* nb1   = (const float*)d_in[10];
    const float* nw2   = (const float*)d_in[11];
    const float* nb2   = (const float*)d_in[12];
    const float* cw1   = (const float*)d_in[13];
    const float* cb1   = (const float*)d_in[14];
    const float* cw2   = (const float*)d_in[15];

    float* out_h = (float*)d_out;
    float* out_c = out_h + (size_t)BNr * Ff;

    void *p_ef, *p_stats, *p_geo, *p_w1T, *p_w2T, *p_cw1T, *p_nw1T, *p_nw2T,
         *p_agg, *p_nodemid, *p_wsc;
    cudaGetSymbolAddress(&p_ef,      g_ef);
    cudaGetSymbolAddress(&p_stats,   g_stats);
    cudaGetSymbolAddress(&p_geo,     g_geo);
    cudaGetSymbolAddress(&p_w1T,     g_w1T);
    cudaGetSymbolAddress(&p_w2T,     g_w2T);
    cudaGetSymbolAddress(&p_cw1T,    g_cw1T);
    cudaGetSymbolAddress(&p_nw1T,    g_nw1T);
    cudaGetSymbolAddress(&p_nw2T,    g_nw2T);
    cudaGetSymbolAddress(&p_agg,     g_agg);
    cudaGetSymbolAddress(&p_nodemid, g_nodemid);
    cudaGetSymbolAddress(&p_wsc,     g_wsc);
    float*          efp      = (float*)p_ef;
    float*          statsp   = (float*)p_stats;
    const float*    geop     = (const float*)p_geo;
    const uint32_t* w1Tp     = (const uint32_t*)p_w1T;
    const uint32_t* w2Tp     = (const uint32_t*)p_w2T;
    const uint32_t* cw1Tp    = (const uint32_t*)p_cw1T;
    const uint32_t* nw1Tp    = (const uint32_t*)p_nw1T;
    const uint32_t* nw2Tp    = (const uint32_t*)p_nw2T;
    const float*    aggp     = (const float*)p_agg;
    float*          nodemidp = (float*)p_nodemid;
    float*          wscp     = (float*)p_wsc;

    const int smem12 = 128 * (AST + BST + MST) * 4;   // ~104.4 KB -> 2 CTAs/SM
    cudaFuncSetAttribute(k_gemm12, cudaFuncAttributeMaxDynamicSharedMemorySize, smem12);
    cudaFuncSetAttribute(k_gemm_t<4, 3>, cudaFuncAttributeMaxDynamicSharedMemorySize, GT_SMEM);
    cudaFuncSetAttribute(k_gemm_t<2, 2>, cudaFuncAttributeMaxDynamicSharedMemorySize, GT_SMEM);
    cudaFuncSetAttribute(k_gemm_t<3, 0>, cudaFuncAttributeMaxDynamicSharedMemorySize, GT_SMEM);

    // init + weights transform (also zeroes stats/agg/wsc)
    k_misc<<<(BNr * Hh + 255) / 256, 256>>>(coord, out_c, ew1, ew2, cw1, nw1, nw2);
    k_geo<<<BE / 256, 256>>>(coord, ei);

    // fused GEMM1+GEMM2 (+ atomic LN stats)
    k_gemm12<<<dim3(2, BE / 128), 256, smem12>>>(h, w1Tp, w2Tp, efp, ei, geop, eb1, eb2, statsp);

    // agg scatter (LN applied in registers, read-only on ef)
    k_aggscatter<<<BE / 8, 256>>>(lng, lnb, ei);

    // GEMM3 fused: wsc += silu(LN(ef) @ cw1 + cb1) . cw2   (LN inline in A path)
    k_gemm_t<4, 3><<<dim3(2, BE / 128), 256, GT_SMEM>>>(
        efp, nullptr, cw1Tp, nullptr, Hh, Hh, Hh, 0, cb1, cw2, 0, wscp, statsp, lng, lnb);

    // coord scatter
    k_coordscatter<<<BE / 256, 256>>>(ei, out_c);

    // node MLP (input concat fused via split-A)
    k_gemm_t<2, 2><<<dim3(2, BNr / 128), 256, GT_SMEM>>>(
        h, aggp, nw1Tp, nodemidp, Hh + Ff, 0, Hh + Ff, Hh, nb1, nullptr, 0, nullptr,
        nullptr, nullptr, nullptr);
    k_gemm_t<3, 0><<<dim3(1, BNr / 128), 256, GT_SMEM>>>(
        nodemidp, nullptr, nw2Tp, out_h, Hh, Hh, Hh, Ff, nb2, h, Ff, nullptr,
        nullptr, nullptr, nullptr);
}

// round 13
// speedup vs baseline: 1.3371x; 1.3371x over previous
#include <cuda_runtime.h>
#include <math.h>
#include <stdint.h>

// Problem constants (fixed shapes)
#define Bc   2
#define Nn   8192
#define Ff   128
#define Ee   131072
#define Hh   256
#define NHh  4
#define Dd   64
#define FEATN 268
#define FEATP 288          // padded K for GEMM1
#define BE   (Bc*Ee)       // 262144 edge rows
#define BNr  (Bc*Nn)       // 16384 node rows

// ---------------- static scratch ----------------
static __device__ float g_ef[(size_t)BE * Hh];     // raw (pre-LN) edge features
static __device__ float g_stats[(size_t)BE * 2];   // per row: sum, sumsq (atomic-accumulated)
static __device__ float g_geo[(size_t)BE * 32];
static __device__ float g_cdiff[BE * 3];
static __device__ float g_wsc[BE];
static __device__ float g_agg[BNr * Hh];
static __device__ float g_nodemid[BNr * Hh];
// pre-transposed, pre-tf32 weights: BT[n][k]
static __device__ uint32_t g_w1T[Hh * FEATP];
static __device__ uint32_t g_w2T[2 * 128 * 128];
static __device__ uint32_t g_cw1T[Hh * Hh];
static __device__ uint32_t g_nw1T[Hh * (Hh + Ff)];
static __device__ uint32_t g_nw2T[Ff * Hh];

// ---------------- helpers ----------------
__device__ __forceinline__ uint32_t f2tf(float x) {
    uint32_t r; asm("cvt.rna.tf32.f32 %0, %1;" : "=r"(r) : "f"(x)); return r;
}
__device__ __forceinline__ void ldsm4(uint32_t& r0, uint32_t& r1, uint32_t& r2, uint32_t& r3, uint32_t a) {
    asm volatile("ldmatrix.sync.aligned.m8n8.x4.shared.b16 {%0,%1,%2,%3}, [%4];"
                 : "=r"(r0), "=r"(r1), "=r"(r2), "=r"(r3) : "r"(a));
}
__device__ __forceinline__ void mma8(float* c, const uint32_t* a, const uint32_t* b) {
    asm volatile("mma.sync.aligned.m16n8k8.row.col.f32.tf32.tf32.f32 "
                 "{%0,%1,%2,%3}, {%4,%5,%6,%7}, {%8,%9}, {%0,%1,%2,%3};"
                 : "+f"(c[0]), "+f"(c[1]), "+f"(c[2]), "+f"(c[3])
                 : "r"(a[0]), "r"(a[1]), "r"(a[2]), "r"(a[3]), "r"(b[0]), "r"(b[1]));
}
__device__ __forceinline__ float silu_f(float x) { return x / (1.f + expf(-x)); }
__device__ __forceinline__ void red4(float* addr, float4 v) {
    asm volatile("red.global.add.v4.f32 [%0], {%1,%2,%3,%4};"
                 :: "l"(addr), "f"(v.x), "f"(v.y), "f"(v.z), "f"(v.w) : "memory");
}

// ---------------- combined init ----------------
__global__ void k_misc(const float* __restrict__ coord, float* __restrict__ outc,
                       const float* __restrict__ w1, const float* __restrict__ w2,
                       const float* __restrict__ cw1, const float* __restrict__ nw1,
                       const float* __restrict__ nw2) {
    int idx = blockIdx.x * blockDim.x + threadIdx.x;
    if (idx < BNr * Hh) g_agg[idx] = 0.f;
    if (idx < BE) g_wsc[idx] = 0.f;
    if (idx < BE * 2) g_stats[idx] = 0.f;
    if (idx < Bc * Nn * 3) outc[idx] = coord[idx];
    if (idx < Hh * FEATP) {
        int n = idx / FEATP, f = idx - n * FEATP;
        g_w1T[idx] = (f < FEATN) ? f2tf(w1[(((n >> 6) * FEATN) + f) * Dd + (n & 63)]) : 0u;
    }
    if (idx < 2 * 128 * 128) {
        int p = idx >> 14, n = (idx >> 7) & 127, k = idx & 127;
        g_w2T[idx] = ((k >> 6) == (n >> 6))
            ? f2tf(w2[((p << 1) + (n >> 6)) * (Dd * Dd) + (k & 63) * Dd + (n & 63)]) : 0u;
    }
    if (idx < Hh * Hh) {
        int n = idx >> 8, k = idx & 255;
        g_cw1T[idx] = f2tf(cw1[k * Hh + n]);
    }
    if (idx < Hh * (Hh + Ff)) {
        int n = idx / (Hh + Ff), k = idx - n * (Hh + Ff);
        g_nw1T[idx] = f2tf(nw1[k * Hh + n]);
    }
    if (idx < Ff * Hh) {
        int n = idx >> 8, k = idx & 255;
        g_nw2T[idx] = f2tf(nw2[k * Ff + n]);
    }
}

// geometry features per edge (thread per edge)
__global__ void k_geo(const float* __restrict__ coord, const int* __restrict__ ei) {
    int e = blockIdx.x * blockDim.x + threadIdx.x;
    if (e >= BE) return;
    int b = (e >= Ee) ? 1 : 0, j = e - b * Ee;
    int i = ei[j], k = ei[Ee + j];
    const float* ci = coord + ((size_t)b * Nn + i) * 3;
    const float* ck = coord + ((size_t)b * Nn + k) * 3;
    float cix = ci[0], ciy = ci[1], ciz = ci[2];
    float ckx = ck[0], cky = ck[1], ckz = ck[2];
    float dx = cix - ckx, dy = ciy - cky, dz = ciz - ckz;
    float radial = dx * dx + dy * dy + dz * dz;
    float dist = sqrtf(radial);
    float dotv = cix * ckx + ciy * cky + ciz * ckz;
    float inva = 1.f / (dist + 1e-8f);
    float ax = dx * inva, ay = dy * inva, az = dz * inva;
    float crx = ciy * ckz - ciz * cky;
    float cry = ciz * ckx - cix * ckz;
    float crz = cix * cky - ciy * ckx;
    float nb = sqrtf(crx * crx + cry * cry + crz * crz);
    float invb = 1.f / (nb + 1e-8f);
    float bx = crx * invb, by = cry * invb, bz = crz * invb;
    float cx = ay * bz - az * by;
    float cy = az * bx - ax * bz;
    float cz = ax * by - ay * bx;
    float na  = sqrtf(ax * ax + ay * ay + az * az);
    float nbv = sqrtf(bx * bx + by * by + bz * bz);
    float ncv = sqrtf(cx * cx + cy * cy + cz * cz);
    bool bad = (na < 1e-6f) || (nbv < 1e-6f) || (ncv < 1e-6f);
    if (bad) { ax = 1.f; bx = 0.f; cx = 0.f;
               ay = 0.f; by = 1.f; cy = 0.f;
               az = 0.f; bz = 0.f; cz = 1.f; }
    float4* g = (float4*)(g_geo + (size_t)e * 32);
    g[0] = make_float4(radial, dist, dotv, ax);
    g[1] = make_float4(bx, cx, ay, by);
    g[2] = make_float4(cy, az, bz, cz);
    float4 z = make_float4(0.f, 0.f, 0.f, 0.f);
    g[3] = z; g[4] = z; g[5] = z; g[6] = z; g[7] = z;
    g_cdiff[e * 3 + 0] = dx;
    g_cdiff[e * 3 + 1] = dy;
    g_cdiff[e * 3 + 2] = dz;
}

// ---------------- tf32 tensor-core GEMM (double-buffered smem) ----------------
// Block tile 128x128, BK=32, 8 warps (2x4), warp tile 64x32.
// EPI: 2 bias+silu, 3 bias+residual, 4 bias+silu+dot(extra)->atomic wsc (no store)
// MODE: 0 normal A, 2 node-split A (h 128 | agg 256), 3 A with inline LayerNorm (stats/gam/bet)
#define AST 36
#define BST 36
#define MST 132
#define GT_BUF (128 * (AST + BST))
#define GT_SMEM (2 * GT_BUF * 4)

template <int EPI, int MODE>
__global__ void __launch_bounds__(256, 2) k_gemm_t(
    const float* __restrict__ A, const float* __restrict__ A2,
    const uint32_t* __restrict__ BT, float* __restrict__ C,
    int K, int lda, int ldbT, int ldc,
    const float* __restrict__ bias, const float* __restrict__ extra, int ldr,
    float* __restrict__ wsc, const float* __restrict__ stats,
    const float* __restrict__ gam, const float* __restrict__ bet)
{
    extern __shared__ uint32_t smbuf[];
    const int tid = threadIdx.x, lane = tid & 31, wid = tid >> 5;
    const int wm = wid >> 2, wn = wid & 3;
    const int m0 = blockIdx.y * 128, n0 = blockIdx.x * 128;

    const int am = tid >> 3;
    const int ak = (tid & 7) << 2;

    const uint32_t* BTg = BT + (size_t)n0 * ldbT;

    const float* pA[4]; const float* pS[4];
    float mu_r[4], rs_r[4];
#pragma unroll
    for (int i = 0; i < 4; i++) {
        int r = m0 + am + 32 * i;
        if (MODE == 2) {
            pA[i] = A + (size_t)r * 128;
            pS[i] = A2 + (size_t)r * 256;
        } else {
            pA[i] = A + (size_t)r * lda;
        }
        if (MODE == 3) {
            float2 st = *(const float2*)(stats + 2 * (size_t)r);
            float mu = st.x * (1.f / 256.f);
            float var = st.y * (1.f / 256.f) - mu * mu;
            mu_r[i] = mu;
            rs_r[i] = rsqrtf(var + 1e-5f);
        }
    }
    auto loadA = [&](int i, int kcol) -> float4 {
        if (MODE == 2) {
            if (kcol < 128) return *(const float4*)(pA[i] + kcol);
            return *(const float4*)(pS[i] + (kcol - 128));
        }
        return *(const float4*)(pA[i] + kcol);
    };

    float acc[4][4][4];
#pragma unroll
    for (int i = 0; i < 4; i++)
#pragma unroll
        for (int j = 0; j < 4; j++) { acc[i][j][0] = 0.f; acc[i][j][1] = 0.f; acc[i][j][2] = 0.f; acc[i][j][3] = 0.f; }

    float4 pa[4]; uint4 pb[4];
#pragma unroll
    for (int i = 0; i < 4; i++) {
        pa[i] = loadA(i, ak);
        pb[i] = *(const uint4*)(BTg + (size_t)(am + 32 * i) * ldbT + ak);
    }

    const uint32_t as_base = (uint32_t)__cvta_generic_to_shared(smbuf);
    const uint32_t bs_base = as_base + 128 * AST * 4;
    const int a_r = wm * 64 + (lane & 15);
    const int a_q = (lane >> 4) << 2;
    const int b_r = wn * 32 + (lane & 7) + ((lane >> 4) << 3);
    const int b_q = ((lane >> 3) & 1) << 2;

    auto storeTiles = [&](int p, int kbase) {
        uint32_t* Ab = smbuf + p * GT_BUF;
        uint32_t* Bb = Ab + 128 * AST;
        float4 gm4, bt4;
        if (MODE == 3) {
            gm4 = *(const float4*)(gam + kbase + ak);
            bt4 = *(const float4*)(bet + kbase + ak);
        }
#pragma unroll
        for (int i = 0; i < 4; i++) {
            float4 v = pa[i];
            if (MODE == 3) {
                v.x = (v.x - mu_r[i]) * rs_r[i] * gm4.x + bt4.x;
                v.y = (v.y - mu_r[i]) * rs_r[i] * gm4.y + bt4.y;
                v.z = (v.z - mu_r[i]) * rs_r[i] * gm4.z + bt4.z;
                v.w = (v.w - mu_r[i]) * rs_r[i] * gm4.w + bt4.w;
            }
            *(uint4*)&Ab[(am + 32 * i) * AST + ak] =
                make_uint4(f2tf(v.x), f2tf(v.y), f2tf(v.z), f2tf(v.w));
            *(uint4*)&Bb[(am + 32 * i) * BST + ak] = pb[i];
        }
    };

    storeTiles(0, 0);
    __syncthreads();

    int p = 0;
    for (int k0 = 0; k0 < K; k0 += 32) {
        bool more = (k0 + 32 < K);
        if (more) {
#pragma unroll
            for (int i = 0; i < 4; i++) {
                pa[i] = loadA(i, k0 + 32 + ak);
                pb[i] = *(const uint4*)(BTg + (size_t)(am + 32 * i) * ldbT + k0 + 32 + ak);
            }
        }
        const uint32_t ab = as_base + p * (GT_BUF * 4);
        const uint32_t bb = bs_base + p * (GT_BUF * 4);
#pragma unroll
        for (int kk = 0; kk < 4; kk++) {
            uint32_t af[4][4], bf[4][2];
#pragma unroll
            for (int mi = 0; mi < 4; mi++)
                ldsm4(af[mi][0], af[mi][1], af[mi][2], af[mi][3],
                      ab + (((a_r + mi * 16) * AST + kk * 8 + a_q) << 2));
#pragma unroll
            for (int np = 0; np < 2; np++) {
                uint32_t r0, r1, r2, r3;
                ldsm4(r0, r1, r2, r3,
                      bb + (((b_r + np * 16) * BST + kk * 8 + b_q) << 2));
                bf[np * 2][0] = r0; bf[np * 2][1] = r1;
                bf[np * 2 + 1][0] = r2; bf[np * 2 + 1][1] = r3;
            }
#pragma unroll
            for (int mi = 0; mi < 4; mi++)
#pragma unroll
                for (int ni = 0; ni < 4; ni++)
                    mma8(acc[mi][ni], af[mi], bf[ni]);
        }
        if (more) storeTiles(p ^ 1, k0 + 32);
        __syncthreads();
        p ^= 1;
    }

    // ---------------- epilogue ----------------
    const int row0 = m0 + wm * 64 + (lane >> 2);
    const int colw = wn * 32 + ((lane & 3) << 1);
#pragma unroll
    for (int mi = 0; mi < 4; mi++) {
        float slo = 0.f, shi = 0.f;
        int r = row0 + mi * 16;
#pragma unroll
        for (int ni = 0; ni < 4; ni++) {
            int col = n0 + colw + ni * 8;
            float2 bb = *(const float2*)(bias + col);
            float v0 = acc[mi][ni][0] + bb.x, v1 = acc[mi][ni][1] + bb.y;
            float v2 = acc[mi][ni][2] + bb.x, v3 = acc[mi][ni][3] + bb.y;
            if (EPI == 2 || EPI == 4) {
                v0 = silu_f(v0); v1 = silu_f(v1); v2 = silu_f(v2); v3 = silu_f(v3);
            }
            if (EPI == 3) {
                float2 ra = *(const float2*)(extra + (size_t)r * ldr + col);
                float2 rb = *(const float2*)(extra + (size_t)(r + 8) * ldr + col);
                v0 += ra.x; v1 += ra.y; v2 += rb.x; v3 += rb.y;
            }
            if (EPI == 4) {
                float2 w = *(const float2*)(extra + col);
                slo += v0 * w.x + v1 * w.y;
                shi += v2 * w.x + v3 * w.y;
            } else {
                *(float2*)(C + (size_t)r * ldc + col)       = make_float2(v0, v1);
                *(float2*)(C + (size_t)(r + 8) * ldc + col) = make_float2(v2, v3);
            }
        }
        if (EPI == 4) {
            slo += __shfl_xor_sync(0xffffffffu, slo, 1);
            slo += __shfl_xor_sync(0xffffffffu, slo, 2);
            shi += __shfl_xor_sync(0xffffffffu, shi, 1);
            shi += __shfl_xor_sync(0xffffffffu, shi, 2);
            if ((lane & 3) == 0) {
                atomicAdd(wsc + r, slo);
                atomicAdd(wsc + r + 8, shi);
            }
        }
    }
}

// ---------------- fused GEMM1+GEMM2 (+LN partial stats via atomics) ----------------
// NOTE: no __launch_bounds__ min-blocks here — forcing 128 regs spills the
// 64-float accumulator (R12 regression). Let ptxas pick.
__global__ void __launch_bounds__(256) k_gemm12(
    const float* __restrict__ h, const uint32_t* __restrict__ w1T,
    const uint32_t* __restrict__ w2T, float* __restrict__ ef,
    const int* __restrict__ ei, const float* __restrict__ geo,
    const float* __restrict__ b1, const float* __restrict__ b2,
    float* __restrict__ stats)
{
    extern __shared__ uint32_t sm[];
    uint32_t* As = sm;
    uint32_t* Bs = sm + 128 * AST;
    uint32_t* Ms = sm + 128 * (AST + BST);
    const int tid = threadIdx.x, lane = tid & 31, wid = tid >> 5;
    const int wm = wid >> 2, wn = wid & 3;
    const int m0 = blockIdx.y * 128, n0 = blockIdx.x * 128;

    const int am = tid >> 3;
    const int ak = (tid & 7) << 2;

    const uint32_t* BTg = w1T + (size_t)n0 * FEATP;

    const float* pA[4]; const float* pS[4]; const float* pG[4];
    {
        int b = (m0 >= Ee) ? 1 : 0;
#pragma unroll
        for (int i = 0; i < 4; i++) {
            int r = m0 + am + 32 * i;
            int j = r - b * Ee;
            pA[i] = h + ((size_t)b * Nn + ei[j]) * Ff;
            pS[i] = h + ((size_t)b * Nn + ei[Ee + j]) * Ff;
            pG[i] = geo + (size_t)r * 32;
        }
    }
    auto loadA = [&](int i, int kcol) -> float4 {
        if (kcol < 128) return *(const float4*)(pA[i] + kcol);
        if (kcol < 256) return *(const float4*)(pS[i] + (kcol - 128));
        return *(const float4*)(pG[i] + (kcol - 256));
    };

    float acc[4][4][4];
#pragma unroll
    for (int i = 0; i < 4; i++)
#pragma unroll
        for (int j = 0; j < 4; j++) { acc[i][j][0] = 0.f; acc[i][j][1] = 0.f; acc[i][j][2] = 0.f; acc[i][j][3] = 0.f; }

    float4 pa[4]; uint4 pb[4];
#pragma unroll
    for (int i = 0; i < 4; i++) {
        pa[i] = loadA(i, ak);
        pb[i] = *(const uint4*)(BTg + (size_t)(am + 32 * i) * FEATP + ak);
    }

    const uint32_t as_base = (uint32_t)__cvta_generic_to_shared(As);
    const uint32_t bs_base = (uint32_t)__cvta_generic_to_shared(Bs);
    const uint32_t ms_base = (uint32_t)__cvta_generic_to_shared(Ms);
    const int a_r = wm * 64 + (lane & 15);
    const int a_q = (lane >> 4) << 2;
    const int b_r = wn * 32 + (lane & 7) + ((lane >> 4) << 3);
    const int b_q = ((lane >> 3) & 1) << 2;

    // ---- stage 1 mainloop, K=288 ----
    for (int k0 = 0; k0 < FEATP; k0 += 32) {
#pragma unroll
        for (int i = 0; i < 4; i++) {
            *(uint4*)&As[(am + 32 * i) * AST + ak] =
                make_uint4(f2tf(pa[i].x), f2tf(pa[i].y), f2tf(pa[i].z), f2tf(pa[i].w));
            *(uint4*)&Bs[(am + 32 * i) * BST + ak] = pb[i];
        }
        __syncthreads();
        if (k0 + 32 < FEATP) {
#pragma unroll
            for (int i = 0; i < 4; i++) {
                pa[i] = loadA(i, k0 + 32 + ak);
                pb[i] = *(const uint4*)(BTg + (size_t)(am + 32 * i) * FEATP + k0 + 32 + ak);
            }
        }
#pragma unroll
        for (int kk = 0; kk < 4; kk++) {
            uint32_t af[4][4], bf[4][2];
#pragma unroll
            for (int mi = 0; mi < 4; mi++)
                ldsm4(af[mi][0], af[mi][1], af[mi][2], af[mi][3],
                      as_base + (((a_r + mi * 16) * AST + kk * 8 + a_q) << 2));
#pragma unroll
            for (int np = 0; np < 2; np++) {
                uint32_t r0, r1, r2, r3;
                ldsm4(r0, r1, r2, r3,
                      bs_base + (((b_r + np * 16) * BST + kk * 8 + b_q) << 2));
                bf[np * 2][0] = r0; bf[np * 2][1] = r1;
                bf[np * 2 + 1][0] = r2; bf[np * 2 + 1][1] = r3;
            }
#pragma unroll
            for (int mi = 0; mi < 4; mi++)
#pragma unroll
                for (int ni = 0; ni < 4; ni++)
                    mma8(acc[mi][ni], af[mi], bf[ni]);
        }
        __syncthreads();
    }

    // ---- epilogue 1: silu + bias -> Ms (tf32), reset acc ----
    const int lrow0 = wm * 64 + (lane >> 2);
    const int lcolw = wn * 32 + ((lane & 3) << 1);
#pragma unroll
    for (int mi = 0; mi < 4; mi++) {
        int r = lrow0 + mi * 16;
#pragma unroll
        for (int ni = 0; ni < 4; ni++) {
            int col = lcolw + ni * 8;
            float2 bb = *(const float2*)(b1 + n0 + col);
            float v0 = silu_f(acc[mi][ni][0] + bb.x);
            float v1 = silu_f(acc[mi][ni][1] + bb.y);
            float v2 = silu_f(acc[mi][ni][2] + bb.x);
            float v3 = silu_f(acc[mi][ni][3] + bb.y);
            *(uint2*)&Ms[r * MST + col]       = make_uint2(f2tf(v0), f2tf(v1));
            *(uint2*)&Ms[(r + 8) * MST + col] = make_uint2(f2tf(v2), f2tf(v3));
            acc[mi][ni][0] = 0.f; acc[mi][ni][1] = 0.f;
            acc[mi][ni][2] = 0.f; acc[mi][ni][3] = 0.f;
        }
    }

    // ---- stage 2 mainloop, K=128, A from Ms, B = w2 pair tile ----
    const uint32_t* W2 = w2T + (size_t)blockIdx.x * (128 * 128);
    for (int k0 = 0; k0 < 128; k0 += 32) {
#pragma unroll
        for (int i = 0; i < 4; i++)
            *(uint4*)&Bs[(am + 32 * i) * BST + ak] =
                *(const uint4*)(W2 + (size_t)(am + 32 * i) * 128 + k0 + ak);
        __syncthreads();
#pragma unroll
        for (int kk = 0; kk < 4; kk++) {
            uint32_t af[4][4], bf[4][2];
#pragma unroll
            for (int mi = 0; mi < 4; mi++)
                ldsm4(af[mi][0], af[mi][1], af[mi][2], af[mi][3],
                      ms_base + (((a_r + mi * 16) * MST + k0 + kk * 8 + a_q) << 2));
#pragma unroll
            for (int np = 0; np < 2; np++) {
                uint32_t r0, r1, r2, r3;
                ldsm4(r0, r1, r2, r3,
                      bs_base + (((b_r + np * 16) * BST + kk * 8 + b_q) << 2));
                bf[np * 2][0] = r0; bf[np * 2][1] = r1;
                bf[np * 2 + 1][0] = r2; bf[np * 2 + 1][1] = r3;
            }
#pragma unroll
            for (int mi = 0; mi < 4; mi++)
#pragma unroll
                for (int ni = 0; ni < 4; ni++)
                    mma8(acc[mi][ni], af[mi], bf[ni]);
        }
        __syncthreads();
    }

    // ---- epilogue 2: + b2, store f32 to ef, LN partial stats via atomics ----
#pragma unroll
    for (int mi = 0; mi < 4; mi++) {
        int r = m0 + lrow0 + mi * 16;
        float s_lo = 0.f, ss_lo = 0.f, s_hi = 0.f, ss_hi = 0.f;
#pragma unroll
        for (int ni = 0; ni < 4; ni++) {
            int col = n0 + lcolw + ni * 8;
            float2 bb = *(const float2*)(b2 + col);
            float v0 = acc[mi][ni][0] + bb.x, v1 = acc[mi][ni][1] + bb.y;
            float v2 = acc[mi][ni][2] + bb.x, v3 = acc[mi][ni][3] + bb.y;
            *(float2*)(ef + (size_t)r * Hh + col)       = make_float2(v0, v1);
            *(float2*)(ef + (size_t)(r + 8) * Hh + col) = make_float2(v2, v3);
            s_lo += v0 + v1; ss_lo += v0 * v0 + v1 * v1;
            s_hi += v2 + v3; ss_hi += v2 * v2 + v3 * v3;
        }
        s_lo  += __shfl_xor_sync(0xffffffffu, s_lo, 1);
        s_lo  += __shfl_xor_sync(0xffffffffu, s_lo, 2);
        ss_lo += __shfl_xor_sync(0xffffffffu, ss_lo, 1);
        ss_lo += __shfl_xor_sync(0xffffffffu, ss_lo, 2);
        s_hi  += __shfl_xor_sync(0xffffffffu, s_hi, 1);
        s_hi  += __shfl_xor_sync(0xffffffffu, s_hi, 2);
        ss_hi += __shfl_xor_sync(0xffffffffu, ss_hi, 1);
        ss_hi += __shfl_xor_sync(0xffffffffu, ss_hi, 2);
        if ((lane & 3) == 0) {
            atomicAdd(stats + 2 * (size_t)r,           s_lo);
            atomicAdd(stats + 2 * (size_t)r + 1,       ss_lo);
            atomicAdd(stats + 2 * (size_t)(r + 8),     s_hi);
            atomicAdd(stats + 2 * (size_t)(r + 8) + 1, ss_hi);
        }
    }
}

// Combined scatter (runs AFTER GEMM3): LN from stats in registers + agg segment-sum
// + coord scatter (wsc ready). One warp per edge.
__global__ void k_scatter2(const float* __restrict__ gam, const float* __restrict__ bet,
                           const int* __restrict__ ei, float* __restrict__ outc) {
    int wid = blockIdx.x * (blockDim.x >> 5) + (threadIdx.x >> 5);
    int lane = threadIdx.x & 31;
    if (wid >= BE) return;
    const float* row = g_ef + (size_t)wid * Hh;
    float2 st = *(const float2*)(g_stats + 2 * (size_t)wid);
    float mu = st.x * (1.f / 256.f);
    float var = st.y * (1.f / 256.f) - mu * mu;
    float rstd = rsqrtf(var + 1e-5f);
    float4 x0 = ((const float4*)row)[lane];
    float4 x1 = ((const float4*)row)[lane + 32];
    float4 g0 = ((const float4*)gam)[lane], g1 = ((const float4*)gam)[lane + 32];
    float4 b0 = ((const float4*)bet)[lane], b1 = ((const float4*)bet)[lane + 32];
    x0.x = (x0.x - mu) * rstd * g0.x + b0.x;
    x0.y = (x0.y - mu) * rstd * g0.y + b0.y;
    x0.z = (x0.z - mu) * rstd * g0.z + b0.z;
    x0.w = (x0.w - mu) * rstd * g0.w + b0.w;
    x1.x = (x1.x - mu) * rstd * g1.x + b1.x;
    x1.y = (x1.y - mu) * rstd * g1.y + b1.y;
    x1.z = (x1.z - mu) * rstd * g1.z + b1.z;
    x1.w = (x1.w - mu) * rstd * g1.w + b1.w;
    int b = (wid >= Ee) ? 1 : 0, j = wid - b * Ee;
    int i = ei[j];
    float* arow = g_agg + ((size_t)b * Nn + i) * Hh;
    red4(arow + 4 * lane, x0);
    red4(arow + 128 + 4 * lane, x1);
    if (lane < 3) {
        float wv = g_wsc[wid];
        atomicAdd(&outc[((size_t)b * Nn + i) * 3 + lane], g_cdiff[wid * 3 + lane] * wv);
    }
}

// ---------------- launch ----------------
extern "C" void kernel_launch(void* const* d_in, const int* in_sizes, int n_in,
                              void* d_out, int out_size) {
    const float* h     = (const float*)d_in[0];
    const float* coord = (const float*)d_in[1];
    const int*   ei    = (const int*)d_in[2];
    const float* ew1   = (const float*)d_in[3];
    const float* eb1   = (const float*)d_in[4];
    const float* ew2   = (const float*)d_in[5];
    const float* eb2   = (const float*)d_in[6];
    const float* lng   = (const float*)d_in[7];
    const float* lnb   = (const float*)d_in[8];
    const float* nw1   = (const float*)d_in[9];
    const float* nb1   = (const float*)d_in[10];
    const float* nw2   = (const float*)d_in[11];
    const float* nb2   = (const float*)d_in[12];
    const float* cw1   = (const float*)d_in[13];
    const float* cb1   = (const float*)d_in[14];
    const float* cw2   = (const float*)d_in[15];

    float* out_h = (float*)d_out;
    float* out_c = out_h + (size_t)BNr * Ff;

    void *p_ef, *p_stats, *p_geo, *p_w1T, *p_w2T, *p_cw1T, *p_nw1T, *p_nw2T,
         *p_agg, *p_nodemid, *p_wsc;
    cudaGetSymbolAddress(&p_ef,      g_ef);
    cudaGetSymbolAddress(&p_stats,   g_stats);
    cudaGetSymbolAddress(&p_geo,     g_geo);
    cudaGetSymbolAddress(&p_w1T,     g_w1T);
    cudaGetSymbolAddress(&p_w2T,     g_w2T);
    cudaGetSymbolAddress(&p_cw1T,    g_cw1T);
    cudaGetSymbolAddress(&p_nw1T,    g_nw1T);
    cudaGetSymbolAddress(&p_nw2T,    g_nw2T);
    cudaGetSymbolAddress(&p_agg,     g_agg);
    cudaGetSymbolAddress(&p_nodemid, g_nodemid);
    cudaGetSymbolAddress(&p_wsc,     g_wsc);
    float*          efp      = (float*)p_ef;
    float*          statsp   = (float*)p_stats;
    const float*    geop     = (const float*)p_geo;
    const uint32_t* w1Tp     = (const uint32_t*)p_w1T;
    const uint32_t* w2Tp     = (const uint32_t*)p_w2T;
    const uint32_t* cw1Tp    = (const uint32_t*)p_cw1T;
    const uint32_t* nw1Tp    = (const uint32_t*)p_nw1T;
    const uint32_t* nw2Tp    = (const uint32_t*)p_nw2T;
    const float*    aggp     = (const float*)p_agg;
    float*          nodemidp = (float*)p_nodemid;
    float*          wscp     = (float*)p_wsc;

    const int smem12 = 128 * (AST + BST + MST) * 4;   // ~104.4 KB
    cudaFuncSetAttribute(k_gemm12, cudaFuncAttributeMaxDynamicSharedMemorySize, smem12);
    cudaFuncSetAttribute(k_gemm_t<4, 3>, cudaFuncAttributeMaxDynamicSharedMemorySize, GT_SMEM);
    cudaFuncSetAttribute(k_gemm_t<2, 2>, cudaFuncAttributeMaxDynamicSharedMemorySize, GT_SMEM);
    cudaFuncSetAttribute(k_gemm_t<3, 0>, cudaFuncAttributeMaxDynamicSharedMemorySize, GT_SMEM);

    // init + weights transform (also zeroes stats/agg/wsc)
    k_misc<<<(BNr * Hh + 255) / 256, 256>>>(coord, out_c, ew1, ew2, cw1, nw1, nw2);
    k_geo<<<BE / 256, 256>>>(coord, ei);

    // fused GEMM1+GEMM2 (+ atomic LN stats)
    k_gemm12<<<dim3(2, BE / 128), 256, smem12>>>(h, w1Tp, w2Tp, efp, ei, geop, eb1, eb2, statsp);

    // GEMM3 fused: wsc += silu(LN(ef) @ cw1 + cb1) . cw2   (LN inline in A path)
    k_gemm_t<4, 3><<<dim3(2, BE / 128), 256, GT_SMEM>>>(
        efp, nullptr, cw1Tp, nullptr, Hh, Hh, Hh, 0, cb1, cw2, 0, wscp, statsp, lng, lnb);

    // combined scatter: LN+agg segment-sum + coord scatter (wsc ready)
    k_scatter2<<<BE / 8, 256>>>(lng, lnb, ei, out_c);

    // node MLP (input concat fused via split-A)
    k_gemm_t<2, 2><<<dim3(2, BNr / 128), 256, GT_SMEM>>>(
        h, aggp, nw1Tp, nodemidp, Hh + Ff, 0, Hh + Ff, Hh, nb1, nullptr, 0, nullptr,
        nullptr, nullptr, nullptr);
    k_gemm_t<3, 0><<<dim3(1, BNr / 128), 256, GT_SMEM>>>(
        nodemidp, nullptr, nw2Tp, out_h, Hh, Hh, Hh, Ff, nb2, h, Ff, nullptr,
        nullptr, nullptr, nullptr);
}

// round 14
// speedup vs baseline: 2.0321x; 1.5197x over previous
#include <cuda_runtime.h>
#include <cuda_fp16.h>
#include <math.h>
#include <stdint.h>

// Problem constants (fixed shapes)
#define Bc   2
#define Nn   8192
#define Ff   128
#define Ee   131072
#define Hh   256
#define NHh  4
#define Dd   64
#define FEATN 268
#define FEATP 288          // padded K for GEMM1
#define BE   (Bc*Ee)       // 262144 edge rows
#define BNr  (Bc*Nn)       // 16384 node rows

// ---------------- static scratch ----------------
static __device__ float g_ef[(size_t)BE * Hh];     // raw (pre-LN) edge features
static __device__ float g_stats[(size_t)BE * 2];   // per row: sum, sumsq (atomic-accumulated)
static __device__ float g_geo[(size_t)BE * 32];
static __device__ float g_cdiff[BE * 3];
static __device__ float g_wsc[BE];
static __device__ float g_agg[BNr * Hh];
static __device__ float g_nodemid[BNr * Hh];
// pre-transposed, pre-packed half2 weights: BT2[n][k/2] (uint = half2, .x = even k)
static __device__ uint32_t g_w1T2[Hh * (FEATP / 2)];        // 256 x 144
static __device__ uint32_t g_w2T2[2 * 128 * 64];            // pair-block-diag, 128 x 64
static __device__ uint32_t g_cw1T2[Hh * (Hh / 2)];          // 256 x 128
static __device__ uint32_t g_nw1T2[Hh * ((Hh + Ff) / 2)];   // 256 x 192
static __device__ uint32_t g_nw2T2[Ff * (Hh / 2)];          // 128 x 128

// ---------------- helpers ----------------
__device__ __forceinline__ uint32_t f2h2(float a, float b) {
    __half2 h = __floats2half2_rn(a, b);
    return *(uint32_t*)&h;
}
__device__ __forceinline__ void ldsm4(uint32_t& r0, uint32_t& r1, uint32_t& r2, uint32_t& r3, uint32_t a) {
    asm volatile("ldmatrix.sync.aligned.m8n8.x4.shared.b16 {%0,%1,%2,%3}, [%4];"
                 : "=r"(r0), "=r"(r1), "=r"(r2), "=r"(r3) : "r"(a));
}
__device__ __forceinline__ void mma16(float* c, const uint32_t* a, const uint32_t* b) {
    asm volatile("mma.sync.aligned.m16n8k16.row.col.f32.f16.f16.f32 "
                 "{%0,%1,%2,%3}, {%4,%5,%6,%7}, {%8,%9}, {%0,%1,%2,%3};"
                 : "+f"(c[0]), "+f"(c[1]), "+f"(c[2]), "+f"(c[3])
                 : "r"(a[0]), "r"(a[1]), "r"(a[2]), "r"(a[3]), "r"(b[0]), "r"(b[1]));
}
__device__ __forceinline__ float silu_f(float x) { return x / (1.f + expf(-x)); }
__device__ __forceinline__ void red4(float* addr, float4 v) {
    asm volatile("red.global.add.v4.f32 [%0], {%1,%2,%3,%4};"
                 :: "l"(addr), "f"(v.x), "f"(v.y), "f"(v.z), "f"(v.w) : "memory");
}

// ---------------- combined init: zero bufs, copy coord, pack half2 weights ----------------
__global__ void k_misc(const float* __restrict__ coord, float* __restrict__ outc,
                       const float* __restrict__ w1, const float* __restrict__ w2,
                       const float* __restrict__ cw1, const float* __restrict__ nw1,
                       const float* __restrict__ nw2) {
    int idx = blockIdx.x * blockDim.x + threadIdx.x;
    if (idx < BNr * Hh) g_agg[idx] = 0.f;
    if (idx < BE) g_wsc[idx] = 0.f;
    if (idx < BE * 2) g_stats[idx] = 0.f;
    if (idx < Bc * Nn * 3) outc[idx] = coord[idx];
    if (idx < Hh * (FEATP / 2)) {              // w1T2[n][f2]
        int n = idx / (FEATP / 2), f2 = idx - n * (FEATP / 2);
        int f0 = 2 * f2, f1 = f0 + 1;
        float a = (f0 < FEATN) ? w1[(((n >> 6) * FEATN) + f0) * Dd + (n & 63)] : 0.f;
        float b = (f1 < FEATN) ? w1[(((n >> 6) * FEATN) + f1) * Dd + (n & 63)] : 0.f;
        g_w1T2[idx] = f2h2(a, b);
    }
    if (idx < 2 * 128 * 64) {                  // w2T2[p][n][k2]
        int p = idx >> 13, rem = idx & 8191;
        int n = rem >> 6, k2 = rem & 63;
        int k0 = 2 * k2, k1 = k0 + 1;
        float a = ((k0 >> 6) == (n >> 6))
            ? w2[((p << 1) + (n >> 6)) * (Dd * Dd) + (k0 & 63) * Dd + (n & 63)] : 0.f;
        float b = ((k1 >> 6) == (n >> 6))
            ? w2[((p << 1) + (n >> 6)) * (Dd * Dd) + (k1 & 63) * Dd + (n & 63)] : 0.f;
        g_w2T2[idx] = f2h2(a, b);
    }
    if (idx < Hh * (Hh / 2)) {                 // cw1T2[n][k2]
        int n = idx >> 7, k2 = idx & 127;
        g_cw1T2[idx] = f2h2(cw1[(2 * k2) * Hh + n], cw1[(2 * k2 + 1) * Hh + n]);
    }
    if (idx < Hh * ((Hh + Ff) / 2)) {          // nw1T2[n][k2]
        int n = idx / 192, k2 = idx - n * 192;
        g_nw1T2[idx] = f2h2(nw1[(2 * k2) * Hh + n], nw1[(2 * k2 + 1) * Hh + n]);
    }
    if (idx < Ff * (Hh / 2)) {                 // nw2T2[n][k2]
        int n = idx >> 7, k2 = idx & 127;
        g_nw2T2[idx] = f2h2(nw2[(2 * k2) * Ff + n], nw2[(2 * k2 + 1) * Ff + n]);
    }
}

// geometry features per edge (thread per edge)
__global__ void k_geo(const float* __restrict__ coord, const int* __restrict__ ei) {
    int e = blockIdx.x * blockDim.x + threadIdx.x;
    if (e >= BE) return;
    int b = (e >= Ee) ? 1 : 0, j = e - b * Ee;
    int i = ei[j], k = ei[Ee + j];
    const float* ci = coord + ((size_t)b * Nn + i) * 3;
    const float* ck = coord + ((size_t)b * Nn + k) * 3;
    float cix = ci[0], ciy = ci[1], ciz = ci[2];
    float ckx = ck[0], cky = ck[1], ckz = ck[2];
    float dx = cix - ckx, dy = ciy - cky, dz = ciz - ckz;
    float radial = dx * dx + dy * dy + dz * dz;
    float dist = sqrtf(radial);
    float dotv = cix * ckx + ciy * cky + ciz * ckz;
    float inva = 1.f / (dist + 1e-8f);
    float ax = dx * inva, ay = dy * inva, az = dz * inva;
    float crx = ciy * ckz - ciz * cky;
    float cry = ciz * ckx - cix * ckz;
    float crz = cix * cky - ciy * ckx;
    float nb = sqrtf(crx * crx + cry * cry + crz * crz);
    float invb = 1.f / (nb + 1e-8f);
    float bx = crx * invb, by = cry * invb, bz = crz * invb;
    float cx = ay * bz - az * by;
    float cy = az * bx - ax * bz;
    float cz = ax * by - ay * bx;
    float na  = sqrtf(ax * ax + ay * ay + az * az);
    float nbv = sqrtf(bx * bx + by * by + bz * bz);
    float ncv = sqrtf(cx * cx + cy * cy + cz * cz);
    bool bad = (na < 1e-6f) || (nbv < 1e-6f) || (ncv < 1e-6f);
    if (bad) { ax = 1.f; bx = 0.f; cx = 0.f;
               ay = 0.f; by = 1.f; cy = 0.f;
               az = 0.f; bz = 0.f; cz = 1.f; }
    float4* g = (float4*)(g_geo + (size_t)e * 32);
    g[0] = make_float4(radial, dist, dotv, ax);
    g[1] = make_float4(bx, cx, ay, by);
    g[2] = make_float4(cy, az, bz, cz);
    float4 z = make_float4(0.f, 0.f, 0.f, 0.f);
    g[3] = z; g[4] = z; g[5] = z; g[6] = z; g[7] = z;
    g_cdiff[e * 3 + 0] = dx;
    g_cdiff[e * 3 + 1] = dy;
    g_cdiff[e * 3 + 2] = dz;
}

// ---------------- fp16 tensor-core GEMM (double-buffered smem) ----------------
// Block tile 128x128, BK=32 halves, 8 warps (2x4), warp tile 64x32, m16n8k16.
// Smem tiles: 128 rows x 32 halves (64B data) at 80B stride (20 uints) - conflict-free ldsm.
// EPI: 2 bias+silu, 3 bias+residual, 4 bias+silu+dot(extra)->atomic wsc (no store)
// MODE: 0 normal A, 2 node-split A (h 128 | agg 256), 3 A with inline LayerNorm
#define AST 20
#define BST 20
#define MST 68
#define GT_BUF (128 * (AST + BST))
#define GT_SMEM (2 * GT_BUF * 4)

template <int EPI, int MODE>
__global__ void __launch_bounds__(256, 2) k_gemm_t(
    const float* __restrict__ A, const float* __restrict__ A2,
    const uint32_t* __restrict__ BT2, float* __restrict__ C,
    int K, int lda, int ldbT2, int ldc,
    const float* __restrict__ bias, const float* __restrict__ extra, int ldr,
    float* __restrict__ wsc, const float* __restrict__ stats,
    const float* __restrict__ gam, const float* __restrict__ bet)
{
    extern __shared__ uint32_t smbuf[];
    const int tid = threadIdx.x, lane = tid & 31, wid = tid >> 5;
    const int wm = wid >> 2, wn = wid & 3;
    const int m0 = blockIdx.y * 128, n0 = blockIdx.x * 128;

    const int am = tid >> 3;             // A loader: rows am+32i
    const int ak = (tid & 7) << 2;       // A loader: float col
    const int brow = tid >> 1;           // B loader: row 0..127
    const int buc = (tid & 1) << 3;      // B loader: uint col 0 or 8

    const uint32_t* BTg = BT2 + (size_t)(n0 + brow) * ldbT2;

    const float* pA[4]; const float* pS[4];
    float mu_r[4], rs_r[4];
#pragma unroll
    for (int i = 0; i < 4; i++) {
        int r = m0 + am + 32 * i;
        if (MODE == 2) {
            pA[i] = A + (size_t)r * 128;
            pS[i] = A2 + (size_t)r * 256;
        } else {
            pA[i] = A + (size_t)r * lda;
        }
        if (MODE == 3) {
            float2 st = *(const float2*)(stats + 2 * (size_t)r);
            float mu = st.x * (1.f / 256.f);
            float var = st.y * (1.f / 256.f) - mu * mu;
            mu_r[i] = mu;
            rs_r[i] = rsqrtf(var + 1e-5f);
        }
    }
    auto loadA = [&](int i, int kcol) -> float4 {
        if (MODE == 2) {
            if (kcol < 128) return *(const float4*)(pA[i] + kcol);
            return *(const float4*)(pS[i] + (kcol - 128));
        }
        return *(const float4*)(pA[i] + kcol);
    };

    float acc[4][4][4];
#pragma unroll
    for (int i = 0; i < 4; i++)
#pragma unroll
        for (int j = 0; j < 4; j++) { acc[i][j][0] = 0.f; acc[i][j][1] = 0.f; acc[i][j][2] = 0.f; acc[i][j][3] = 0.f; }

    float4 pa[4]; uint4 pb[2];
#pragma unroll
    for (int i = 0; i < 4; i++) pa[i] = loadA(i, ak);
    pb[0] = *(const uint4*)(BTg + buc);
    pb[1] = *(const uint4*)(BTg + buc + 4);

    const uint32_t as_base = (uint32_t)__cvta_generic_to_shared(smbuf);
    const uint32_t bs_base = as_base + 128 * AST * 4;
    const int a_r = wm * 64 + (lane & 15);
    const int a_q = (lane >> 4) << 2;
    const int b_r = wn * 32 + (lane & 7) + ((lane >> 4) << 3);
    const int b_q = ((lane >> 3) & 1) << 2;

    auto storeTiles = [&](int p, int kbase) {
        uint32_t* Ab = smbuf + p * GT_BUF;
        uint32_t* Bb = Ab + 128 * AST;
        float4 gm4, bt4;
        if (MODE == 3) {
            gm4 = *(const float4*)(gam + kbase + ak);
            bt4 = *(const float4*)(bet + kbase + ak);
        }
#pragma unroll
        for (int i = 0; i < 4; i++) {
            float4 v = pa[i];
            if (MODE == 3) {
                v.x = (v.x - mu_r[i]) * rs_r[i] * gm4.x + bt4.x;
                v.y = (v.y - mu_r[i]) * rs_r[i] * gm4.y + bt4.y;
                v.z = (v.z - mu_r[i]) * rs_r[i] * gm4.z + bt4.z;
                v.w = (v.w - mu_r[i]) * rs_r[i] * gm4.w + bt4.w;
            }
            *(uint2*)&Ab[(am + 32 * i) * AST + (ak >> 1)] =
                make_uint2(f2h2(v.x, v.y), f2h2(v.z, v.w));
        }
        *(uint4*)&Bb[brow * BST + buc]     = pb[0];
        *(uint4*)&Bb[brow * BST + buc + 4] = pb[1];
    };

    storeTiles(0, 0);
    __syncthreads();

    int p = 0;
    for (int k0 = 0; k0 < K; k0 += 32) {
        bool more = (k0 + 32 < K);
        if (more) {
#pragma unroll
            for (int i = 0; i < 4; i++) pa[i] = loadA(i, k0 + 32 + ak);
            int ku = (k0 + 32) >> 1;
            pb[0] = *(const uint4*)(BTg + ku + buc);
            pb[1] = *(const uint4*)(BTg + ku + buc + 4);
        }
        const uint32_t ab = as_base + p * (GT_BUF * 4);
        const uint32_t bb = bs_base + p * (GT_BUF * 4);
#pragma unroll
        for (int kk = 0; kk < 2; kk++) {
            uint32_t af[4][4], bf[4][2];
#pragma unroll
            for (int mi = 0; mi < 4; mi++)
                ldsm4(af[mi][0], af[mi][1], af[mi][2], af[mi][3],
                      ab + (((a_r + mi * 16) * AST + kk * 8 + a_q) << 2));
#pragma unroll
            for (int np = 0; np < 2; np++) {
                uint32_t r0, r1, r2, r3;
                ldsm4(r0, r1, r2, r3,
                      bb + (((b_r + np * 16) * BST + kk * 8 + b_q) << 2));
                bf[np * 2][0] = r0; bf[np * 2][1] = r1;
                bf[np * 2 + 1][0] = r2; bf[np * 2 + 1][1] = r3;
            }
#pragma unroll
            for (int mi = 0; mi < 4; mi++)
#pragma unroll
                for (int ni = 0; ni < 4; ni++)
                    mma16(acc[mi][ni], af[mi], bf[ni]);
        }
        if (more) storeTiles(p ^ 1, k0 + 32);
        __syncthreads();
        p ^= 1;
    }

    // ---------------- epilogue ----------------
    const int row0 = m0 + wm * 64 + (lane >> 2);
    const int colw = wn * 32 + ((lane & 3) << 1);
#pragma unroll
    for (int mi = 0; mi < 4; mi++) {
        float slo = 0.f, shi = 0.f;
        int r = row0 + mi * 16;
#pragma unroll
        for (int ni = 0; ni < 4; ni++) {
            int col = n0 + colw + ni * 8;
            float2 bb = *(const float2*)(bias + col);
            float v0 = acc[mi][ni][0] + bb.x, v1 = acc[mi][ni][1] + bb.y;
            float v2 = acc[mi][ni][2] + bb.x, v3 = acc[mi][ni][3] + bb.y;
            if (EPI == 2 || EPI == 4) {
                v0 = silu_f(v0); v1 = silu_f(v1); v2 = silu_f(v2); v3 = silu_f(v3);
            }
            if (EPI == 3) {
                float2 ra = *(const float2*)(extra + (size_t)r * ldr + col);
                float2 rb = *(const float2*)(extra + (size_t)(r + 8) * ldr + col);
                v0 += ra.x; v1 += ra.y; v2 += rb.x; v3 += rb.y;
            }
            if (EPI == 4) {
                float2 w = *(const float2*)(extra + col);
                slo += v0 * w.x + v1 * w.y;
                shi += v2 * w.x + v3 * w.y;
            } else {
                *(float2*)(C + (size_t)r * ldc + col)       = make_float2(v0, v1);
                *(float2*)(C + (size_t)(r + 8) * ldc + col) = make_float2(v2, v3);
            }
        }
        if (EPI == 4) {
            slo += __shfl_xor_sync(0xffffffffu, slo, 1);
            slo += __shfl_xor_sync(0xffffffffu, slo, 2);
            shi += __shfl_xor_sync(0xffffffffu, shi, 1);
            shi += __shfl_xor_sync(0xffffffffu, shi, 2);
            if ((lane & 3) == 0) {
                atomicAdd(wsc + r, slo);
                atomicAdd(wsc + r + 8, shi);
            }
        }
    }
}

// ---------------- fused GEMM1+GEMM2 (fp16, +LN stats via atomics) ----------------
// smem: As(10KB) + Bs(10KB) + Ms(128 x 68 uints = 34.8KB) = ~55KB
__global__ void __launch_bounds__(256) k_gemm12(
    const float* __restrict__ h, const uint32_t* __restrict__ w1T2,
    const uint32_t* __restrict__ w2T2, float* __restrict__ ef,
    const int* __restrict__ ei, const float* __restrict__ geo,
    const float* __restrict__ b1, const float* __restrict__ b2,
    float* __restrict__ stats)
{
    extern __shared__ uint32_t sm[];
    uint32_t* As = sm;
    uint32_t* Bs = sm + 128 * AST;
    uint32_t* Ms = sm + 128 * (AST + BST);
    const int tid = threadIdx.x, lane = tid & 31, wid = tid >> 5;
    const int wm = wid >> 2, wn = wid & 3;
    const int m0 = blockIdx.y * 128, n0 = blockIdx.x * 128;

    const int am = tid >> 3;
    const int ak = (tid & 7) << 2;
    const int brow = tid >> 1;
    const int buc = (tid & 1) << 3;

    const uint32_t* BTg = w1T2 + (size_t)(n0 + brow) * (FEATP / 2);

    const float* pA[4]; const float* pS[4]; const float* pG[4];
    {
        int b = (m0 >= Ee) ? 1 : 0;
#pragma unroll
        for (int i = 0; i < 4; i++) {
            int r = m0 + am + 32 * i;
            int j = r - b * Ee;
            pA[i] = h + ((size_t)b * Nn + ei[j]) * Ff;
            pS[i] = h + ((size_t)b * Nn + ei[Ee + j]) * Ff;
            pG[i] = geo + (size_t)r * 32;
        }
    }
    auto loadA = [&](int i, int kcol) -> float4 {
        if (kcol < 128) return *(const float4*)(pA[i] + kcol);
        if (kcol < 256) return *(const float4*)(pS[i] + (kcol - 128));
        return *(const float4*)(pG[i] + (kcol - 256));
    };

    float acc[4][4][4];
#pragma unroll
    for (int i = 0; i < 4; i++)
#pragma unroll
        for (int j = 0; j < 4; j++) { acc[i][j][0] = 0.f; acc[i][j][1] = 0.f; acc[i][j][2] = 0.f; acc[i][j][3] = 0.f; }

    float4 pa[4]; uint4 pb[2];
#pragma unroll
    for (int i = 0; i < 4; i++) pa[i] = loadA(i, ak);
    pb[0] = *(const uint4*)(BTg + buc);
    pb[1] = *(const uint4*)(BTg + buc + 4);

    const uint32_t as_base = (uint32_t)__cvta_generic_to_shared(As);
    const uint32_t bs_base = (uint32_t)__cvta_generic_to_shared(Bs);
    const uint32_t ms_base = (uint32_t)__cvta_generic_to_shared(Ms);
    const int a_r = wm * 64 + (lane & 15);
    const int a_q = (lane >> 4) << 2;
    const int b_r = wn * 32 + (lane & 7) + ((lane >> 4) << 3);
    const int b_q = ((lane >> 3) & 1) << 2;

    // ---- stage 1 mainloop, K=288 halves ----
    for (int k0 = 0; k0 < FEATP; k0 += 32) {
#pragma unroll
        for (int i = 0; i < 4; i++)
            *(uint2*)&As[(am + 32 * i) * AST + (ak >> 1)] =
                make_uint2(f2h2(pa[i].x, pa[i].y), f2h2(pa[i].z, pa[i].w));
        *(uint4*)&Bs[brow * BST + buc]     = pb[0];
        *(uint4*)&Bs[brow * BST + buc + 4] = pb[1];
        __syncthreads();
        if (k0 + 32 < FEATP) {
#pragma unroll
            for (int i = 0; i < 4; i++) pa[i] = loadA(i, k0 + 32 + ak);
            int ku = (k0 + 32) >> 1;
            pb[0] = *(const uint4*)(BTg + ku + buc);
            pb[1] = *(const uint4*)(BTg + ku + buc + 4);
        }
#pragma unroll
        for (int kk = 0; kk < 2; kk++) {
            uint32_t af[4][4], bf[4][2];
#pragma unroll
            for (int mi = 0; mi < 4; mi++)
                ldsm4(af[mi][0], af[mi][1], af[mi][2], af[mi][3],
                      as_base + (((a_r + mi * 16) * AST + kk * 8 + a_q) << 2));
#pragma unroll
            for (int np = 0; np < 2; np++) {
                uint32_t r0, r1, r2, r3;
                ldsm4(r0, r1, r2, r3,
                      bs_base + (((b_r + np * 16) * BST + kk * 8 + b_q) << 2));
                bf[np * 2][0] = r0; bf[np * 2][1] = r1;
                bf[np * 2 + 1][0] = r2; bf[np * 2 + 1][1] = r3;
            }
#pragma unroll
            for (int mi = 0; mi < 4; mi++)
#pragma unroll
                for (int ni = 0; ni < 4; ni++)
                    mma16(acc[mi][ni], af[mi], bf[ni]);
        }
        __syncthreads();
    }

    // ---- epilogue 1: silu + bias -> Ms (half2), reset acc ----
    const int lrow0 = wm * 64 + (lane >> 2);
    const int lcolw = wn * 32 + ((lane & 3) << 1);
#pragma unroll
    for (int mi = 0; mi < 4; mi++) {
        int r = lrow0 + mi * 16;
#pragma unroll
        for (int ni = 0; ni < 4; ni++) {
            int col = lcolw + ni * 8;
            float2 bb = *(const float2*)(b1 + n0 + col);
            float v0 = silu_f(acc[mi][ni][0] + bb.x);
            float v1 = silu_f(acc[mi][ni][1] + bb.y);
            float v2 = silu_f(acc[mi][ni][2] + bb.x);
            float v3 = silu_f(acc[mi][ni][3] + bb.y);
            Ms[r * MST + (col >> 1)]       = f2h2(v0, v1);
            Ms[(r + 8) * MST + (col >> 1)] = f2h2(v2, v3);
            acc[mi][ni][0] = 0.f; acc[mi][ni][1] = 0.f;
            acc[mi][ni][2] = 0.f; acc[mi][ni][3] = 0.f;
        }
    }

    // ---- stage 2 mainloop, K=128 halves, A from Ms, B = w2 pair tile ----
    const uint32_t* W22 = w2T2 + (size_t)blockIdx.x * (128 * 64) + (size_t)brow * 64;
    for (int k0 = 0; k0 < 128; k0 += 32) {
        int ku = k0 >> 1;
        *(uint4*)&Bs[brow * BST + buc]     = *(const uint4*)(W22 + ku + buc);
        *(uint4*)&Bs[brow * BST + buc + 4] = *(const uint4*)(W22 + ku + buc + 4);
        __syncthreads();
#pragma unroll
        for (int kk = 0; kk < 2; kk++) {
            uint32_t af[4][4], bf[4][2];
#pragma unroll
            for (int mi = 0; mi < 4; mi++)
                ldsm4(af[mi][0], af[mi][1], af[mi][2], af[mi][3],
                      ms_base + (((a_r + mi * 16) * MST + ku + kk * 8 + a_q) << 2));
#pragma unroll
            for (int np = 0; np < 2; np++) {
                uint32_t r0, r1, r2, r3;
                ldsm4(r0, r1, r2, r3,
                      bs_base + (((b_r + np * 16) * BST + kk * 8 + b_q) << 2));
                bf[np * 2][0] = r0; bf[np * 2][1] = r1;
                bf[np * 2 + 1][0] = r2; bf[np * 2 + 1][1] = r3;
            }
#pragma unroll
            for (int mi = 0; mi < 4; mi++)
#pragma unroll
                for (int ni = 0; ni < 4; ni++)
                    mma16(acc[mi][ni], af[mi], bf[ni]);
        }
        __syncthreads();
    }

    // ---- epilogue 2: + b2, store f32 to ef, LN partial stats via atomics ----
#pragma unroll
    for (int mi = 0; mi < 4; mi++) {
        int r = m0 + lrow0 + mi * 16;
        float s_lo = 0.f, ss_lo = 0.f, s_hi = 0.f, ss_hi = 0.f;
#pragma unroll
        for (int ni = 0; ni < 4; ni++) {
            int col = n0 + lcolw + ni * 8;
            float2 bb = *(const float2*)(b2 + col);
            float v0 = acc[mi][ni][0] + bb.x, v1 = acc[mi][ni][1] + bb.y;
            float v2 = acc[mi][ni][2] + bb.x, v3 = acc[mi][ni][3] + bb.y;
            *(float2*)(ef + (size_t)r * Hh + col)       = make_float2(v0, v1);
            *(float2*)(ef + (size_t)(r + 8) * Hh + col) = make_float2(v2, v3);
            s_lo += v0 + v1; ss_lo += v0 * v0 + v1 * v1;
            s_hi += v2 + v3; ss_hi += v2 * v2 + v3 * v3;
        }
        s_lo  += __shfl_xor_sync(0xffffffffu, s_lo, 1);
        s_lo  += __shfl_xor_sync(0xffffffffu, s_lo, 2);
        ss_lo += __shfl_xor_sync(0xffffffffu, ss_lo, 1);
        ss_lo += __shfl_xor_sync(0xffffffffu, ss_lo, 2);
        s_hi  += __shfl_xor_sync(0xffffffffu, s_hi, 1);
        s_hi  += __shfl_xor_sync(0xffffffffu, s_hi, 2);
        ss_hi += __shfl_xor_sync(0xffffffffu, ss_hi, 1);
        ss_hi += __shfl_xor_sync(0xffffffffu, ss_hi, 2);
        if ((lane & 3) == 0) {
            atomicAdd(stats + 2 * (size_t)r,           s_lo);
            atomicAdd(stats + 2 * (size_t)r + 1,       ss_lo);
            atomicAdd(stats + 2 * (size_t)(r + 8),     s_hi);
            atomicAdd(stats + 2 * (size_t)(r + 8) + 1, ss_hi);
        }
    }
}

// Combined scatter (runs AFTER GEMM3): LN from stats + agg segment-sum + coord scatter.
__global__ void k_scatter2(const float* __restrict__ gam, const float* __restrict__ bet,
                           const int* __restrict__ ei, float* __restrict__ outc) {
    int wid = blockIdx.x * (blockDim.x >> 5) + (threadIdx.x >> 5);
    int lane = threadIdx.x & 31;
    if (wid >= BE) return;
    const float* row = g_ef + (size_t)wid * Hh;
    float2 st = *(const float2*)(g_stats + 2 * (size_t)wid);
    float mu = st.x * (1.f / 256.f);
    float var = st.y * (1.f / 256.f) - mu * mu;
    float rstd = rsqrtf(var + 1e-5f);
    float4 x0 = ((const float4*)row)[lane];
    float4 x1 = ((const float4*)row)[lane + 32];
    float4 g0 = ((const float4*)gam)[lane], g1 = ((const float4*)gam)[lane + 32];
    float4 b0 = ((const float4*)bet)[lane], b1 = ((const float4*)bet)[lane + 32];
    x0.x = (x0.x - mu) * rstd * g0.x + b0.x;
    x0.y = (x0.y - mu) * rstd * g0.y + b0.y;
    x0.z = (x0.z - mu) * rstd * g0.z + b0.z;
    x0.w = (x0.w - mu) * rstd * g0.w + b0.w;
    x1.x = (x1.x - mu) * rstd * g1.x + b1.x;
    x1.y = (x1.y - mu) * rstd * g1.y + b1.y;
    x1.z = (x1.z - mu) * rstd * g1.z + b1.z;
    x1.w = (x1.w - mu) * rstd * g1.w + b1.w;
    int b = (wid >= Ee) ? 1 : 0, j = wid - b * Ee;
    int i = ei[j];
    float* arow = g_agg + ((size_t)b * Nn + i) * Hh;
    red4(arow + 4 * lane, x0);
    red4(arow + 128 + 4 * lane, x1);
    if (lane < 3) {
        float wv = g_wsc[wid];
        atomicAdd(&outc[((size_t)b * Nn + i) * 3 + lane], g_cdiff[wid * 3 + lane] * wv);
    }
}

// ---------------- launch ----------------
extern "C" void kernel_launch(void* const* d_in, const int* in_sizes, int n_in,
                              void* d_out, int out_size) {
    const float* h     = (const float*)d_in[0];
    const float* coord = (const float*)d_in[1];
    const int*   ei    = (const int*)d_in[2];
    const float* ew1   = (const float*)d_in[3];
    const float* eb1   = (const float*)d_in[4];
    const float* ew2   = (const float*)d_in[5];
    const float* eb2   = (const float*)d_in[6];
    const float* lng   = (const float*)d_in[7];
    const float* lnb   = (const float*)d_in[8];
    const float* nw1   = (const float*)d_in[9];
    const float* nb1   = (const float*)d_in[10];
    const float* nw2   = (const float*)d_in[11];
    const float* nb2   = (const float*)d_in[12];
    const float* cw1   = (const float*)d_in[13];
    const float* cb1   = (const float*)d_in[14];
    const float* cw2   = (const float*)d_in[15];

    float* out_h = (float*)d_out;
    float* out_c = out_h + (size_t)BNr * Ff;

    void *p_ef, *p_stats, *p_geo, *p_w1T2, *p_w2T2, *p_cw1T2, *p_nw1T2, *p_nw2T2,
         *p_agg, *p_nodemid, *p_wsc;
    cudaGetSymbolAddress(&p_ef,      g_ef);
    cudaGetSymbolAddress(&p_stats,   g_stats);
    cudaGetSymbolAddress(&p_geo,     g_geo);
    cudaGetSymbolAddress(&p_w1T2,    g_w1T2);
    cudaGetSymbolAddress(&p_w2T2,    g_w2T2);
    cudaGetSymbolAddress(&p_cw1T2,   g_cw1T2);
    cudaGetSymbolAddress(&p_nw1T2,   g_nw1T2);
    cudaGetSymbolAddress(&p_nw2T2,   g_nw2T2);
    cudaGetSymbolAddress(&p_agg,     g_agg);
    cudaGetSymbolAddress(&p_nodemid, g_nodemid);
    cudaGetSymbolAddress(&p_wsc,     g_wsc);
    float*          efp      = (float*)p_ef;
    float*          statsp   = (float*)p_stats;
    const float*    geop     = (const float*)p_geo;
    const uint32_t* w1T2p    = (const uint32_t*)p_w1T2;
    const uint32_t* w2T2p    = (const uint32_t*)p_w2T2;
    const uint32_t* cw1T2p   = (const uint32_t*)p_cw1T2;
    const uint32_t* nw1T2p   = (const uint32_t*)p_nw1T2;
    const uint32_t* nw2T2p   = (const uint32_t*)p_nw2T2;
    const float*    aggp     = (const float*)p_agg;
    float*          nodemidp = (float*)p_nodemid;
    float*          wscp     = (float*)p_wsc;

    const int smem12 = 128 * (AST + BST + MST) * 4;   // ~55 KB
    cudaFuncSetAttribute(k_gemm12, cudaFuncAttributeMaxDynamicSharedMemorySize, smem12);
    cudaFuncSetAttribute(k_gemm_t<4, 3>, cudaFuncAttributeMaxDynamicSharedMemorySize, GT_SMEM);
    cudaFuncSetAttribute(k_gemm_t<2, 2>, cudaFuncAttributeMaxDynamicSharedMemorySize, GT_SMEM);
    cudaFuncSetAttribute(k_gemm_t<3, 0>, cudaFuncAttributeMaxDynamicSharedMemorySize, GT_SMEM);

    // init + weight packing (also zeroes stats/agg/wsc)
    k_misc<<<(BNr * Hh + 255) / 256, 256>>>(coord, out_c, ew1, ew2, cw1, nw1, nw2);
    k_geo<<<BE / 256, 256>>>(coord, ei);

    // fused GEMM1+GEMM2 (+ atomic LN stats)
    k_gemm12<<<dim3(2, BE / 128), 256, smem12>>>(h, w1T2p, w2T2p, efp, ei, geop, eb1, eb2, statsp);

    // GEMM3 fused: wsc += silu(LN(ef) @ cw1 + cb1) . cw2   (LN inline in A path)
    k_gemm_t<4, 3><<<dim3(2, BE / 128), 256, GT_SMEM>>>(
        efp, nullptr, cw1T2p, nullptr, Hh, Hh, Hh / 2, 0, cb1, cw2, 0, wscp, statsp, lng, lnb);

    // combined scatter: LN+agg segment-sum + coord scatter (wsc ready)
    k_scatter2<<<BE / 8, 256>>>(lng, lnb, ei, out_c);

    // node MLP (input concat fused via split-A)
    k_gemm_t<2, 2><<<dim3(2, BNr / 128), 256, GT_SMEM>>>(
        h, aggp, nw1T2p, nodemidp, Hh + Ff, 0, (Hh + Ff) / 2, Hh, nb1, nullptr, 0, nullptr,
        nullptr, nullptr, nullptr);
    k_gemm_t<3, 0><<<dim3(1, BNr / 128), 256, GT_SMEM>>>(
        nodemidp, nullptr, nw2T2p, out_h, Hh, Hh, Hh / 2, Ff, nb2, h, Ff, nullptr,
        nullptr, nullptr, nullptr);
}

// round 15
// speedup vs baseline: 2.0434x; 1.0056x over previous
#include <cuda_runtime.h>
#include <cuda_fp16.h>
#include <math.h>
#include <stdint.h>

// Problem constants (fixed shapes)
#define Bc   2
#define Nn   8192
#define Ff   128
#define Ee   131072
#define Hh   256
#define NHh  4
#define Dd   64
#define FEATN 268
#define FEATP 288          // padded K for GEMM1
#define BE   (Bc*Ee)       // 262144 edge rows
#define BNr  (Bc*Nn)       // 16384 node rows

// ---------------- static scratch ----------------
static __device__ uint32_t g_ef2[(size_t)BE * (Hh / 2)];   // raw (pre-LN) edge features, half2-packed
static __device__ float g_stats[(size_t)BE * 2];           // per row: sum, sumsq (atomic-accumulated)
static __device__ float g_geo[(size_t)BE * 32];
static __device__ float g_cdiff[BE * 3];
static __device__ float g_wsc[BE];
static __device__ float g_agg[BNr * Hh];
static __device__ float g_nodemid[BNr * Hh];
// pre-transposed, pre-packed half2 weights: BT2[n][k/2] (uint = half2, .x = even k)
static __device__ uint32_t g_w1T2[Hh * (FEATP / 2)];        // 256 x 144
static __device__ uint32_t g_w2T2[2 * 128 * 64];            // pair-block-diag, 128 x 64
static __device__ uint32_t g_cw1T2[Hh * (Hh / 2)];          // 256 x 128
static __device__ uint32_t g_nw1T2[Hh * ((Hh + Ff) / 2)];   // 256 x 192
static __device__ uint32_t g_nw2T2[Ff * (Hh / 2)];          // 128 x 128

// ---------------- helpers ----------------
__device__ __forceinline__ uint32_t f2h2(float a, float b) {
    __half2 h = __floats2half2_rn(a, b);
    return *(uint32_t*)&h;
}
__device__ __forceinline__ float2 h22f2(uint32_t u) {
    return __half22float2(*(__half2*)&u);
}
__device__ __forceinline__ void ldsm4(uint32_t& r0, uint32_t& r1, uint32_t& r2, uint32_t& r3, uint32_t a) {
    asm volatile("ldmatrix.sync.aligned.m8n8.x4.shared.b16 {%0,%1,%2,%3}, [%4];"
                 : "=r"(r0), "=r"(r1), "=r"(r2), "=r"(r3) : "r"(a));
}
__device__ __forceinline__ void mma16(float* c, const uint32_t* a, const uint32_t* b) {
    asm volatile("mma.sync.aligned.m16n8k16.row.col.f32.f16.f16.f32 "
                 "{%0,%1,%2,%3}, {%4,%5,%6,%7}, {%8,%9}, {%0,%1,%2,%3};"
                 : "+f"(c[0]), "+f"(c[1]), "+f"(c[2]), "+f"(c[3])
                 : "r"(a[0]), "r"(a[1]), "r"(a[2]), "r"(a[3]), "r"(b[0]), "r"(b[1]));
}
__device__ __forceinline__ float silu_f(float x) { return x / (1.f + expf(-x)); }
__device__ __forceinline__ void red4(float* addr, float4 v) {
    asm volatile("red.global.add.v4.f32 [%0], {%1,%2,%3,%4};"
                 :: "l"(addr), "f"(v.x), "f"(v.y), "f"(v.z), "f"(v.w) : "memory");
}

// ---------------- combined init: zero bufs, copy coord, pack half2 weights ----------------
__global__ void k_misc(const float* __restrict__ coord, float* __restrict__ outc,
                       const float* __restrict__ w1, const float* __restrict__ w2,
                       const float* __restrict__ cw1, const float* __restrict__ nw1,
                       const float* __restrict__ nw2) {
    int idx = blockIdx.x * blockDim.x + threadIdx.x;
    if (idx < BNr * Hh) g_agg[idx] = 0.f;
    if (idx < BE) g_wsc[idx] = 0.f;
    if (idx < BE * 2) g_stats[idx] = 0.f;
    if (idx < Bc * Nn * 3) outc[idx] = coord[idx];
    if (idx < Hh * (FEATP / 2)) {              // w1T2[n][f2]
        int n = idx / (FEATP / 2), f2 = idx - n * (FEATP / 2);
        int f0 = 2 * f2, f1 = f0 + 1;
        float a = (f0 < FEATN) ? w1[(((n >> 6) * FEATN) + f0) * Dd + (n & 63)] : 0.f;
        float b = (f1 < FEATN) ? w1[(((n >> 6) * FEATN) + f1) * Dd + (n & 63)] : 0.f;
        g_w1T2[idx] = f2h2(a, b);
    }
    if (idx < 2 * 128 * 64) {                  // w2T2[p][n][k2]
        int p = idx >> 13, rem = idx & 8191;
        int n = rem >> 6, k2 = rem & 63;
        int k0 = 2 * k2, k1 = k0 + 1;
        float a = ((k0 >> 6) == (n >> 6))
            ? w2[((p << 1) + (n >> 6)) * (Dd * Dd) + (k0 & 63) * Dd + (n & 63)] : 0.f;
        float b = ((k1 >> 6) == (n >> 6))
            ? w2[((p << 1) + (n >> 6)) * (Dd * Dd) + (k1 & 63) * Dd + (n & 63)] : 0.f;
        g_w2T2[idx] = f2h2(a, b);
    }
    if (idx < Hh * (Hh / 2)) {                 // cw1T2[n][k2]
        int n = idx >> 7, k2 = idx & 127;
        g_cw1T2[idx] = f2h2(cw1[(2 * k2) * Hh + n], cw1[(2 * k2 + 1) * Hh + n]);
    }
    if (idx < Hh * ((Hh + Ff) / 2)) {          // nw1T2[n][k2]
        int n = idx / 192, k2 = idx - n * 192;
        g_nw1T2[idx] = f2h2(nw1[(2 * k2) * Hh + n], nw1[(2 * k2 + 1) * Hh + n]);
    }
    if (idx < Ff * (Hh / 2)) {                 // nw2T2[n][k2]
        int n = idx >> 7, k2 = idx & 127;
        g_nw2T2[idx] = f2h2(nw2[(2 * k2) * Ff + n], nw2[(2 * k2 + 1) * Ff + n]);
    }
}

// geometry features per edge (thread per edge)
__global__ void k_geo(const float* __restrict__ coord, const int* __restrict__ ei) {
    int e = blockIdx.x * blockDim.x + threadIdx.x;
    if (e >= BE) return;
    int b = (e >= Ee) ? 1 : 0, j = e - b * Ee;
    int i = ei[j], k = ei[Ee + j];
    const float* ci = coord + ((size_t)b * Nn + i) * 3;
    const float* ck = coord + ((size_t)b * Nn + k) * 3;
    float cix = ci[0], ciy = ci[1], ciz = ci[2];
    float ckx = ck[0], cky = ck[1], ckz = ck[2];
    float dx = cix - ckx, dy = ciy - cky, dz = ciz - ckz;
    float radial = dx * dx + dy * dy + dz * dz;
    float dist = sqrtf(radial);
    float dotv = cix * ckx + ciy * cky + ciz * ckz;
    float inva = 1.f / (dist + 1e-8f);
    float ax = dx * inva, ay = dy * inva, az = dz * inva;
    float crx = ciy * ckz - ciz * cky;
    float cry = ciz * ckx - cix * ckz;
    float crz = cix * cky - ciy * ckx;
    float nb = sqrtf(crx * crx + cry * cry + crz * crz);
    float invb = 1.f / (nb + 1e-8f);
    float bx = crx * invb, by = cry * invb, bz = crz * invb;
    float cx = ay * bz - az * by;
    float cy = az * bx - ax * bz;
    float cz = ax * by - ay * bx;
    float na  = sqrtf(ax * ax + ay * ay + az * az);
    float nbv = sqrtf(bx * bx + by * by + bz * bz);
    float ncv = sqrtf(cx * cx + cy * cy + cz * cz);
    bool bad = (na < 1e-6f) || (nbv < 1e-6f) || (ncv < 1e-6f);
    if (bad) { ax = 1.f; bx = 0.f; cx = 0.f;
               ay = 0.f; by = 1.f; cy = 0.f;
               az = 0.f; bz = 0.f; cz = 1.f; }
    float4* g = (float4*)(g_geo + (size_t)e * 32);
    g[0] = make_float4(radial, dist, dotv, ax);
    g[1] = make_float4(bx, cx, ay, by);
    g[2] = make_float4(cy, az, bz, cz);
    float4 z = make_float4(0.f, 0.f, 0.f, 0.f);
    g[3] = z; g[4] = z; g[5] = z; g[6] = z; g[7] = z;
    g_cdiff[e * 3 + 0] = dx;
    g_cdiff[e * 3 + 1] = dy;
    g_cdiff[e * 3 + 2] = dz;
}

// ---------------- fp16 tensor-core GEMM (double-buffered smem) ----------------
// Block tile 128x128, BK=32 halves, 8 warps (2x4), warp tile 64x32, m16n8k16.
// EPI: 2 bias+silu, 3 bias+residual, 4 bias+silu+dot(extra)->atomic wsc (no store)
// MODE: 0 normal A (f32), 2 node-split A (h 128 | agg 256),
//       3 half2-packed A (g_ef2) with inline LayerNorm (stats/gam/bet)
#define AST 20
#define BST 20
#define MST 68
#define GT_BUF (128 * (AST + BST))
#define GT_SMEM (2 * GT_BUF * 4)

template <int EPI, int MODE>
__global__ void __launch_bounds__(256, 2) k_gemm_t(
    const float* __restrict__ A, const float* __restrict__ A2,
    const uint32_t* __restrict__ BT2, float* __restrict__ C,
    int K, int lda, int ldbT2, int ldc,
    const float* __restrict__ bias, const float* __restrict__ extra, int ldr,
    float* __restrict__ wsc, const float* __restrict__ stats,
    const float* __restrict__ gam, const float* __restrict__ bet,
    const uint32_t* __restrict__ AH)
{
    extern __shared__ uint32_t smbuf[];
    const int tid = threadIdx.x, lane = tid & 31, wid = tid >> 5;
    const int wm = wid >> 2, wn = wid & 3;
    const int m0 = blockIdx.y * 128, n0 = blockIdx.x * 128;

    const int am = tid >> 3;             // A loader: rows am+32i
    const int ak = (tid & 7) << 2;       // A loader: element col
    const int brow = tid >> 1;           // B loader: row 0..127
    const int buc = (tid & 1) << 3;      // B loader: uint col 0 or 8

    const uint32_t* BTg = BT2 + (size_t)(n0 + brow) * ldbT2;

    const float* pA[4]; const float* pS[4]; const uint32_t* pH[4];
    float mu_r[4], rs_r[4];
#pragma unroll
    for (int i = 0; i < 4; i++) {
        int r = m0 + am + 32 * i;
        if (MODE == 2) {
            pA[i] = A + (size_t)r * 128;
            pS[i] = A2 + (size_t)r * 256;
        } else if (MODE == 3) {
            pH[i] = AH + (size_t)r * (Hh / 2);
            float2 st = *(const float2*)(stats + 2 * (size_t)r);
            float mu = st.x * (1.f / 256.f);
            float var = st.y * (1.f / 256.f) - mu * mu;
            mu_r[i] = mu;
            rs_r[i] = rsqrtf(var + 1e-5f);
        } else {
            pA[i] = A + (size_t)r * lda;
        }
    }
    auto loadA = [&](int i, int kcol) -> float4 {
        if (MODE == 2) {
            if (kcol < 128) return *(const float4*)(pA[i] + kcol);
            return *(const float4*)(pS[i] + (kcol - 128));
        }
        if (MODE == 3) {
            uint2 u = *(const uint2*)(pH[i] + (kcol >> 1));
            float2 f0 = h22f2(u.x), f1 = h22f2(u.y);
            return make_float4(f0.x, f0.y, f1.x, f1.y);
        }
        return *(const float4*)(pA[i] + kcol);
    };

    float acc[4][4][4];
#pragma unroll
    for (int i = 0; i < 4; i++)
#pragma unroll
        for (int j = 0; j < 4; j++) { acc[i][j][0] = 0.f; acc[i][j][1] = 0.f; acc[i][j][2] = 0.f; acc[i][j][3] = 0.f; }

    float4 pa[4]; uint4 pb[2];
#pragma unroll
    for (int i = 0; i < 4; i++) pa[i] = loadA(i, ak);
    pb[0] = *(const uint4*)(BTg + buc);
    pb[1] = *(const uint4*)(BTg + buc + 4);

    const uint32_t as_base = (uint32_t)__cvta_generic_to_shared(smbuf);
    const uint32_t bs_base = as_base + 128 * AST * 4;
    const int a_r = wm * 64 + (lane & 15);
    const int a_q = (lane >> 4) << 2;
    const int b_r = wn * 32 + (lane & 7) + ((lane >> 4) << 3);
    const int b_q = ((lane >> 3) & 1) << 2;

    auto storeTiles = [&](int p, int kbase) {
        uint32_t* Ab = smbuf + p * GT_BUF;
        uint32_t* Bb = Ab + 128 * AST;
        float4 gm4, bt4;
        if (MODE == 3) {
            gm4 = *(const float4*)(gam + kbase + ak);
            bt4 = *(const float4*)(bet + kbase + ak);
        }
#pragma unroll
        for (int i = 0; i < 4; i++) {
            float4 v = pa[i];
            if (MODE == 3) {
                v.x = (v.x - mu_r[i]) * rs_r[i] * gm4.x + bt4.x;
                v.y = (v.y - mu_r[i]) * rs_r[i] * gm4.y + bt4.y;
                v.z = (v.z - mu_r[i]) * rs_r[i] * gm4.z + bt4.z;
                v.w = (v.w - mu_r[i]) * rs_r[i] * gm4.w + bt4.w;
            }
            *(uint2*)&Ab[(am + 32 * i) * AST + (ak >> 1)] =
                make_uint2(f2h2(v.x, v.y), f2h2(v.z, v.w));
        }
        *(uint4*)&Bb[brow * BST + buc]     = pb[0];
        *(uint4*)&Bb[brow * BST + buc + 4] = pb[1];
    };

    storeTiles(0, 0);
    __syncthreads();

    int p = 0;
    for (int k0 = 0; k0 < K; k0 += 32) {
        bool more = (k0 + 32 < K);
        if (more) {
#pragma unroll
            for (int i = 0; i < 4; i++) pa[i] = loadA(i, k0 + 32 + ak);
            int ku = (k0 + 32) >> 1;
            pb[0] = *(const uint4*)(BTg + ku + buc);
            pb[1] = *(const uint4*)(BTg + ku + buc + 4);
        }
        const uint32_t ab = as_base + p * (GT_BUF * 4);
        const uint32_t bb = bs_base + p * (GT_BUF * 4);
#pragma unroll
        for (int kk = 0; kk < 2; kk++) {
            uint32_t af[4][4], bf[4][2];
#pragma unroll
            for (int mi = 0; mi < 4; mi++)
                ldsm4(af[mi][0], af[mi][1], af[mi][2], af[mi][3],
                      ab + (((a_r + mi * 16) * AST + kk * 8 + a_q) << 2));
#pragma unroll
            for (int np = 0; np < 2; np++) {
                uint32_t r0, r1, r2, r3;
                ldsm4(r0, r1, r2, r3,
                      bb + (((b_r + np * 16) * BST + kk * 8 + b_q) << 2));
                bf[np * 2][0] = r0; bf[np * 2][1] = r1;
                bf[np * 2 + 1][0] = r2; bf[np * 2 + 1][1] = r3;
            }
#pragma unroll
            for (int mi = 0; mi < 4; mi++)
#pragma unroll
                for (int ni = 0; ni < 4; ni++)
                    mma16(acc[mi][ni], af[mi], bf[ni]);
        }
        if (more) storeTiles(p ^ 1, k0 + 32);
        __syncthreads();
        p ^= 1;
    }

    // ---------------- epilogue ----------------
    const int row0 = m0 + wm * 64 + (lane >> 2);
    const int colw = wn * 32 + ((lane & 3) << 1);
#pragma unroll
    for (int mi = 0; mi < 4; mi++) {
        float slo = 0.f, shi = 0.f;
        int r = row0 + mi * 16;
#pragma unroll
        for (int ni = 0; ni < 4; ni++) {
            int col = n0 + colw + ni * 8;
            float2 bb = *(const float2*)(bias + col);
            float v0 = acc[mi][ni][0] + bb.x, v1 = acc[mi][ni][1] + bb.y;
            float v2 = acc[mi][ni][2] + bb.x, v3 = acc[mi][ni][3] + bb.y;
            if (EPI == 2 || EPI == 4) {
                v0 = silu_f(v0); v1 = silu_f(v1); v2 = silu_f(v2); v3 = silu_f(v3);
            }
            if (EPI == 3) {
                float2 ra = *(const float2*)(extra + (size_t)r * ldr + col);
                float2 rb = *(const float2*)(extra + (size_t)(r + 8) * ldr + col);
                v0 += ra.x; v1 += ra.y; v2 += rb.x; v3 += rb.y;
            }
            if (EPI == 4) {
                float2 w = *(const float2*)(extra + col);
                slo += v0 * w.x + v1 * w.y;
                shi += v2 * w.x + v3 * w.y;
            } else {
                *(float2*)(C + (size_t)r * ldc + col)       = make_float2(v0, v1);
                *(float2*)(C + (size_t)(r + 8) * ldc + col) = make_float2(v2, v3);
            }
        }
        if (EPI == 4) {
            slo += __shfl_xor_sync(0xffffffffu, slo, 1);
            slo += __shfl_xor_sync(0xffffffffu, slo, 2);
            shi += __shfl_xor_sync(0xffffffffu, shi, 1);
            shi += __shfl_xor_sync(0xffffffffu, shi, 2);
            if ((lane & 3) == 0) {
                atomicAdd(wsc + r, slo);
                atomicAdd(wsc + r + 8, shi);
            }
        }
    }
}

// ---------------- fused GEMM1+GEMM2 (fp16, +LN stats via atomics) ----------------
__global__ void __launch_bounds__(256) k_gemm12(
    const float* __restrict__ h, const uint32_t* __restrict__ w1T2,
    const uint32_t* __restrict__ w2T2, uint32_t* __restrict__ ef2,
    const int* __restrict__ ei, const float* __restrict__ geo,
    const float* __restrict__ b1, const float* __restrict__ b2,
    float* __restrict__ stats)
{
    extern __shared__ uint32_t sm[];
    uint32_t* As = sm;
    uint32_t* Bs = sm + 128 * AST;
    uint32_t* Ms = sm + 128 * (AST + BST);
    const int tid = threadIdx.x, lane = tid & 31, wid = tid >> 5;
    const int wm = wid >> 2, wn = wid & 3;
    const int m0 = blockIdx.y * 128, n0 = blockIdx.x * 128;

    const int am = tid >> 3;
    const int ak = (tid & 7) << 2;
    const int brow = tid >> 1;
    const int buc = (tid & 1) << 3;

    const uint32_t* BTg = w1T2 + (size_t)(n0 + brow) * (FEATP / 2);

    const float* pA[4]; const float* pS[4]; const float* pG[4];
    {
        int b = (m0 >= Ee) ? 1 : 0;
#pragma unroll
        for (int i = 0; i < 4; i++) {
            int r = m0 + am + 32 * i;
            int j = r - b * Ee;
            pA[i] = h + ((size_t)b * Nn + ei[j]) * Ff;
            pS[i] = h + ((size_t)b * Nn + ei[Ee + j]) * Ff;
            pG[i] = geo + (size_t)r * 32;
        }
    }
    auto loadA = [&](int i, int kcol) -> float4 {
        if (kcol < 128) return *(const float4*)(pA[i] + kcol);
        if (kcol < 256) return *(const float4*)(pS[i] + (kcol - 128));
        return *(const float4*)(pG[i] + (kcol - 256));
    };

    float acc[4][4][4];
#pragma unroll
    for (int i = 0; i < 4; i++)
#pragma unroll
        for (int j = 0; j < 4; j++) { acc[i][j][0] = 0.f; acc[i][j][1] = 0.f; acc[i][j][2] = 0.f; acc[i][j][3] = 0.f; }

    float4 pa[4]; uint4 pb[2];
#pragma unroll
    for (int i = 0; i < 4; i++) pa[i] = loadA(i, ak);
    pb[0] = *(const uint4*)(BTg + buc);
    pb[1] = *(const uint4*)(BTg + buc + 4);

    const uint32_t as_base = (uint32_t)__cvta_generic_to_shared(As);
    const uint32_t bs_base = (uint32_t)__cvta_generic_to_shared(Bs);
    const uint32_t ms_base = (uint32_t)__cvta_generic_to_shared(Ms);
    const int a_r = wm * 64 + (lane & 15);
    const int a_q = (lane >> 4) << 2;
    const int b_r = wn * 32 + (lane & 7) + ((lane >> 4) << 3);
    const int b_q = ((lane >> 3) & 1) << 2;

    // ---- stage 1 mainloop, K=288 ----
    for (int k0 = 0; k0 < FEATP; k0 += 32) {
#pragma unroll
        for (int i = 0; i < 4; i++)
            *(uint2*)&As[(am + 32 * i) * AST + (ak >> 1)] =
                make_uint2(f2h2(pa[i].x, pa[i].y), f2h2(pa[i].z, pa[i].w));
        *(uint4*)&Bs[brow * BST + buc]     = pb[0];
        *(uint4*)&Bs[brow * BST + buc + 4] = pb[1];
        __syncthreads();
        if (k0 + 32 < FEATP) {
#pragma unroll
            for (int i = 0; i < 4; i++) pa[i] = loadA(i, k0 + 32 + ak);
            int ku = (k0 + 32) >> 1;
            pb[0] = *(const uint4*)(BTg + ku + buc);
            pb[1] = *(const uint4*)(BTg + ku + buc + 4);
        }
#pragma unroll
        for (int kk = 0; kk < 2; kk++) {
            uint32_t af[4][4], bf[4][2];
#pragma unroll
            for (int mi = 0; mi < 4; mi++)
                ldsm4(af[mi][0], af[mi][1], af[mi][2], af[mi][3],
                      as_base + (((a_r + mi * 16) * AST + kk * 8 + a_q) << 2));
#pragma unroll
            for (int np = 0; np < 2; np++) {
                uint32_t r0, r1, r2, r3;
                ldsm4(r0, r1, r2, r3,
                      bs_base + (((b_r + np * 16) * BST + kk * 8 + b_q) << 2));
                bf[np * 2][0] = r0; bf[np * 2][1] = r1;
                bf[np * 2 + 1][0] = r2; bf[np * 2 + 1][1] = r3;
            }
#pragma unroll
            for (int mi = 0; mi < 4; mi++)
#pragma unroll
                for (int ni = 0; ni < 4; ni++)
                    mma16(acc[mi][ni], af[mi], bf[ni]);
        }
        __syncthreads();
    }

    // ---- epilogue 1: silu + bias -> Ms (half2), reset acc ----
    const int lrow0 = wm * 64 + (lane >> 2);
    const int lcolw = wn * 32 + ((lane & 3) << 1);
#pragma unroll
    for (int mi = 0; mi < 4; mi++) {
        int r = lrow0 + mi * 16;
#pragma unroll
        for (int ni = 0; ni < 4; ni++) {
            int col = lcolw + ni * 8;
            float2 bb = *(const float2*)(b1 + n0 + col);
            float v0 = silu_f(acc[mi][ni][0] + bb.x);
            float v1 = silu_f(acc[mi][ni][1] + bb.y);
            float v2 = silu_f(acc[mi][ni][2] + bb.x);
            float v3 = silu_f(acc[mi][ni][3] + bb.y);
            Ms[r * MST + (col >> 1)]       = f2h2(v0, v1);
            Ms[(r + 8) * MST + (col >> 1)] = f2h2(v2, v3);
            acc[mi][ni][0] = 0.f; acc[mi][ni][1] = 0.f;
            acc[mi][ni][2] = 0.f; acc[mi][ni][3] = 0.f;
        }
    }

    // ---- stage 2 mainloop, K=128, A from Ms, B = w2 pair tile ----
    const uint32_t* W22 = w2T2 + (size_t)blockIdx.x * (128 * 64) + (size_t)brow * 64;
    for (int k0 = 0; k0 < 128; k0 += 32) {
        int ku = k0 >> 1;
        *(uint4*)&Bs[brow * BST + buc]     = *(const uint4*)(W22 + ku + buc);
        *(uint4*)&Bs[brow * BST + buc + 4] = *(const uint4*)(W22 + ku + buc + 4);
        __syncthreads();
#pragma unroll
        for (int kk = 0; kk < 2; kk++) {
            uint32_t af[4][4], bf[4][2];
#pragma unroll
            for (int mi = 0; mi < 4; mi++)
                ldsm4(af[mi][0], af[mi][1], af[mi][2], af[mi][3],
                      ms_base + (((a_r + mi * 16) * MST + ku + kk * 8 + a_q) << 2));
#pragma unroll
            for (int np = 0; np < 2; np++) {
                uint32_t r0, r1, r2, r3;
                ldsm4(r0, r1, r2, r3,
                      bs_base + (((b_r + np * 16) * BST + kk * 8 + b_q) << 2));
                bf[np * 2][0] = r0; bf[np * 2][1] = r1;
                bf[np * 2 + 1][0] = r2; bf[np * 2 + 1][1] = r3;
            }
#pragma unroll
            for (int mi = 0; mi < 4; mi++)
#pragma unroll
                for (int ni = 0; ni < 4; ni++)
                    mma16(acc[mi][ni], af[mi], bf[ni]);
        }
        __syncthreads();
    }

    // ---- epilogue 2: + b2, store half2 to ef2, LN partial stats via atomics ----
#pragma unroll
    for (int mi = 0; mi < 4; mi++) {
        int r = m0 + lrow0 + mi * 16;
        float s_lo = 0.f, ss_lo = 0.f, s_hi = 0.f, ss_hi = 0.f;
#pragma unroll
        for (int ni = 0; ni < 4; ni++) {
            int col = n0 + lcolw + ni * 8;
            float2 bb = *(const float2*)(b2 + col);
            float v0 = acc[mi][ni][0] + bb.x, v1 = acc[mi][ni][1] + bb.y;
            float v2 = acc[mi][ni][2] + bb.x, v3 = acc[mi][ni][3] + bb.y;
            ef2[(size_t)r * (Hh / 2) + (col >> 1)]       = f2h2(v0, v1);
            ef2[(size_t)(r + 8) * (Hh / 2) + (col >> 1)] = f2h2(v2, v3);
            s_lo += v0 + v1; ss_lo += v0 * v0 + v1 * v1;
            s_hi += v2 + v3; ss_hi += v2 * v2 + v3 * v3;
        }
        s_lo  += __shfl_xor_sync(0xffffffffu, s_lo, 1);
        s_lo  += __shfl_xor_sync(0xffffffffu, s_lo, 2);
        ss_lo += __shfl_xor_sync(0xffffffffu, ss_lo, 1);
        ss_lo += __shfl_xor_sync(0xffffffffu, ss_lo, 2);
        s_hi  += __shfl_xor_sync(0xffffffffu, s_hi, 1);
        s_hi  += __shfl_xor_sync(0xffffffffu, s_hi, 2);
        ss_hi += __shfl_xor_sync(0xffffffffu, ss_hi, 1);
        ss_hi += __shfl_xor_sync(0xffffffffu, ss_hi, 2);
        if ((lane & 3) == 0) {
            atomicAdd(stats + 2 * (size_t)r,           s_lo);
            atomicAdd(stats + 2 * (size_t)r + 1,       ss_lo);
            atomicAdd(stats + 2 * (size_t)(r + 8),     s_hi);
            atomicAdd(stats + 2 * (size_t)(r + 8) + 1, ss_hi);
        }
    }
}

// Combined scatter (runs AFTER GEMM3): LN from stats + agg segment-sum + coord scatter.
// ef2 is half2-packed: one uint4 per lane covers the whole 256-col row.
__global__ void k_scatter2(const float* __restrict__ gam, const float* __restrict__ bet,
                           const int* __restrict__ ei, float* __restrict__ outc) {
    int wid = blockIdx.x * (blockDim.x >> 5) + (threadIdx.x >> 5);
    int lane = threadIdx.x & 31;
    if (wid >= BE) return;
    const uint32_t* row = g_ef2 + (size_t)wid * (Hh / 2);
    float2 st = *(const float2*)(g_stats + 2 * (size_t)wid);
    float mu = st.x * (1.f / 256.f);
    float var = st.y * (1.f / 256.f) - mu * mu;
    float rstd = rsqrtf(var + 1e-5f);
    uint4 u = ((const uint4*)row)[lane];   // cols 8*lane .. 8*lane+7
    float2 f0 = h22f2(u.x), f1 = h22f2(u.y), f2v = h22f2(u.z), f3 = h22f2(u.w);
    float4 g0 = ((const float4*)gam)[2 * lane], g1 = ((const float4*)gam)[2 * lane + 1];
    float4 b0 = ((const float4*)bet)[2 * lane], b1 = ((const float4*)bet)[2 * lane + 1];
    float4 x0, x1;
    x0.x = (f0.x - mu) * rstd * g0.x + b0.x;
    x0.y = (f0.y - mu) * rstd * g0.y + b0.y;
    x0.z = (f1.x - mu) * rstd * g0.z + b0.z;
    x0.w = (f1.y - mu) * rstd * g0.w + b0.w;
    x1.x = (f2v.x - mu) * rstd * g1.x + b1.x;
    x1.y = (f2v.y - mu) * rstd * g1.y + b1.y;
    x1.z = (f3.x - mu) * rstd * g1.z + b1.z;
    x1.w = (f3.y - mu) * rstd * g1.w + b1.w;
    int b = (wid >= Ee) ? 1 : 0, j = wid - b * Ee;
    int i = ei[j];
    float* arow = g_agg + ((size_t)b * Nn + i) * Hh;
    red4(arow + 8 * lane, x0);
    red4(arow + 8 * lane + 4, x1);
    if (lane < 3) {
        float wv = g_wsc[wid];
        atomicAdd(&outc[((size_t)b * Nn + i) * 3 + lane], g_cdiff[wid * 3 + lane] * wv);
    }
}

// ---------------- launch ----------------
extern "C" void kernel_launch(void* const* d_in, const int* in_sizes, int n_in,
                              void* d_out, int out_size) {
    const float* h     = (const float*)d_in[0];
    const float* coord = (const float*)d_in[1];
    const int*   ei    = (const int*)d_in[2];
    const float* ew1   = (const float*)d_in[3];
    const float* eb1   = (const float*)d_in[4];
    const float* ew2   = (const float*)d_in[5];
    const float* eb2   = (const float*)d_in[6];
    const float* lng   = (const float*)d_in[7];
    const float* lnb   = (const float*)d_in[8];
    const float* nw1   = (const float*)d_in[9];
    const float* nb1   = (const float*)d_in[10];
    const float* nw2   = (const float*)d_in[11];
    const float* nb2   = (const float*)d_in[12];
    const float* cw1   = (const float*)d_in[13];
    const float* cb1   = (const float*)d_in[14];
    const float* cw2   = (const float*)d_in[15];

    float* out_h = (float*)d_out;
    float* out_c = out_h + (size_t)BNr * Ff;

    void *p_ef2, *p_stats, *p_geo, *p_w1T2, *p_w2T2, *p_cw1T2, *p_nw1T2, *p_nw2T2,
         *p_agg, *p_nodemid, *p_wsc;
    cudaGetSymbolAddress(&p_ef2,     g_ef2);
    cudaGetSymbolAddress(&p_stats,   g_stats);
    cudaGetSymbolAddress(&p_geo,     g_geo);
    cudaGetSymbolAddress(&p_w1T2,    g_w1T2);
    cudaGetSymbolAddress(&p_w2T2,    g_w2T2);
    cudaGetSymbolAddress(&p_cw1T2,   g_cw1T2);
    cudaGetSymbolAddress(&p_nw1T2,   g_nw1T2);
    cudaGetSymbolAddress(&p_nw2T2,   g_nw2T2);
    cudaGetSymbolAddress(&p_agg,     g_agg);
    cudaGetSymbolAddress(&p_nodemid, g_nodemid);
    cudaGetSymbolAddress(&p_wsc,     g_wsc);
    uint32_t*       ef2p     = (uint32_t*)p_ef2;
    float*          statsp   = (float*)p_stats;
    const float*    geop     = (const float*)p_geo;
    const uint32_t* w1T2p    = (const uint32_t*)p_w1T2;
    const uint32_t* w2T2p    = (const uint32_t*)p_w2T2;
    const uint32_t* cw1T2p   = (const uint32_t*)p_cw1T2;
    const uint32_t* nw1T2p   = (const uint32_t*)p_nw1T2;
    const uint32_t* nw2T2p   = (const uint32_t*)p_nw2T2;
    const float*    aggp     = (const float*)p_agg;
    float*          nodemidp = (float*)p_nodemid;
    float*          wscp     = (float*)p_wsc;

    const int smem12 = 128 * (AST + BST + MST) * 4;   // ~55 KB
    cudaFuncSetAttribute(k_gemm12, cudaFuncAttributeMaxDynamicSharedMemorySize, smem12);
    cudaFuncSetAttribute(k_gemm_t<4, 3>, cudaFuncAttributeMaxDynamicSharedMemorySize, GT_SMEM);
    cudaFuncSetAttribute(k_gemm_t<2, 2>, cudaFuncAttributeMaxDynamicSharedMemorySize, GT_SMEM);
    cudaFuncSetAttribute(k_gemm_t<3, 0>, cudaFuncAttributeMaxDynamicSharedMemorySize, GT_SMEM);

    // init + weight packing (also zeroes stats/agg/wsc)
    k_misc<<<(BNr * Hh + 255) / 256, 256>>>(coord, out_c, ew1, ew2, cw1, nw1, nw2);
    k_geo<<<BE / 256, 256>>>(coord, ei);

    // fused GEMM1+GEMM2 (+ atomic LN stats), ef stored as half2
    k_gemm12<<<dim3(2, BE / 128), 256, smem12>>>(h, w1T2p, w2T2p, ef2p, ei, geop, eb1, eb2, statsp);

    // GEMM3 fused: wsc += silu(LN(ef) @ cw1 + cb1) . cw2   (LN inline in A path, half A)
    k_gemm_t<4, 3><<<dim3(2, BE / 128), 256, GT_SMEM>>>(
        nullptr, nullptr, cw1T2p, nullptr, Hh, Hh, Hh / 2, 0, cb1, cw2, 0, wscp, statsp,
        lng, lnb, ef2p);

    // combined scatter: LN+agg segment-sum + coord scatter (wsc ready)
    k_scatter2<<<BE / 8, 256>>>(lng, lnb, ei, out_c);

    // node MLP (input concat fused via split-A)
    k_gemm_t<2, 2><<<dim3(2, BNr / 128), 256, GT_SMEM>>>(
        h, aggp, nw1T2p, nodemidp, Hh + Ff, 0, (Hh + Ff) / 2, Hh, nb1, nullptr, 0, nullptr,
        nullptr, nullptr, nullptr, nullptr);
    k_gemm_t<3, 0><<<dim3(1, BNr / 128), 256, GT_SMEM>>>(
        nodemidp, nullptr, nw2T2p, out_h, Hh, Hh, Hh / 2, Ff, nb2, h, Ff, nullptr,
        nullptr, nullptr, nullptr, nullptr);
}

// round 16
// speedup vs baseline: 2.0637x; 1.0099x over previous
#include <cuda_runtime.h>
#include <cuda_fp16.h>
#include <math.h>
#include <stdint.h>

// Problem constants (fixed shapes)
#define Bc   2
#define Nn   8192
#define Ff   128
#define Ee   131072
#define Hh   256
#define NHh  4
#define Dd   64
#define FEATN 268
#define FEATP 288          // padded K for GEMM1
#define BE   (Bc*Ee)       // 262144 edge rows
#define BNr  (Bc*Nn)       // 16384 node rows

// ---------------- static scratch ----------------
static __device__ uint32_t g_ef2[(size_t)BE * (Hh / 2)];   // raw (pre-LN) edge features, half2-packed
static __device__ float g_stats[(size_t)BE * 2];           // per row: sum, sumsq (atomic-accumulated)
static __device__ float g_geo[(size_t)BE * 32];
static __device__ float g_cdiff[BE * 3];
static __device__ float g_wsc[BE];
static __device__ float g_agg[BNr * Hh];
static __device__ float g_nodemid[BNr * Hh];
// pre-transposed, pre-packed half2 weights: BT2[n][k/2]
static __device__ uint32_t g_w1T2[Hh * (FEATP / 2)];        // 256 x 144
static __device__ uint32_t g_w2T2[2 * 128 * 64];            // pair-block-diag, 128 x 64
static __device__ uint32_t g_cw1T2[Hh * (Hh / 2)];          // 256 x 128
static __device__ uint32_t g_nw1T2[Hh * ((Hh + Ff) / 2)];   // 256 x 192
static __device__ uint32_t g_nw2T2[Ff * (Hh / 2)];          // 128 x 128

// ---------------- helpers ----------------
__device__ __forceinline__ uint32_t f2h2(float a, float b) {
    __half2 h = __floats2half2_rn(a, b);
    return *(uint32_t*)&h;
}
__device__ __forceinline__ float2 h22f2(uint32_t u) {
    return __half22float2(*(__half2*)&u);
}
__device__ __forceinline__ void ldsm4(uint32_t& r0, uint32_t& r1, uint32_t& r2, uint32_t& r3, uint32_t a) {
    asm volatile("ldmatrix.sync.aligned.m8n8.x4.shared.b16 {%0,%1,%2,%3}, [%4];"
                 : "=r"(r0), "=r"(r1), "=r"(r2), "=r"(r3) : "r"(a));
}
__device__ __forceinline__ void mma16(float* c, const uint32_t* a, const uint32_t* b) {
    asm volatile("mma.sync.aligned.m16n8k16.row.col.f32.f16.f16.f32 "
                 "{%0,%1,%2,%3}, {%4,%5,%6,%7}, {%8,%9}, {%0,%1,%2,%3};"
                 : "+f"(c[0]), "+f"(c[1]), "+f"(c[2]), "+f"(c[3])
                 : "r"(a[0]), "r"(a[1]), "r"(a[2]), "r"(a[3]), "r"(b[0]), "r"(b[1]));
}
__device__ __forceinline__ float silu_f(float x) { return x / (1.f + expf(-x)); }
__device__ __forceinline__ void red4(float* addr, float4 v) {
    asm volatile("red.global.add.v4.f32 [%0], {%1,%2,%3,%4};"
                 :: "l"(addr), "f"(v.x), "f"(v.y), "f"(v.z), "f"(v.w) : "memory");
}

// ---------------- combined init ----------------
__global__ void k_misc(const float* __restrict__ coord, float* __restrict__ outc,
                       const float* __restrict__ w1, const float* __restrict__ w2,
                       const float* __restrict__ cw1, const float* __restrict__ nw1,
                       const float* __restrict__ nw2) {
    int idx = blockIdx.x * blockDim.x + threadIdx.x;
    if (idx < BNr * Hh) g_agg[idx] = 0.f;
    if (idx < BE) g_wsc[idx] = 0.f;
    if (idx < BE * 2) g_stats[idx] = 0.f;
    if (idx < Bc * Nn * 3) outc[idx] = coord[idx];
    if (idx < Hh * (FEATP / 2)) {
        int n = idx / (FEATP / 2), f2 = idx - n * (FEATP / 2);
        int f0 = 2 * f2, f1 = f0 + 1;
        float a = (f0 < FEATN) ? w1[(((n >> 6) * FEATN) + f0) * Dd + (n & 63)] : 0.f;
        float b = (f1 < FEATN) ? w1[(((n >> 6) * FEATN) + f1) * Dd + (n & 63)] : 0.f;
        g_w1T2[idx] = f2h2(a, b);
    }
    if (idx < 2 * 128 * 64) {
        int p = idx >> 13, rem = idx & 8191;
        int n = rem >> 6, k2 = rem & 63;
        int k0 = 2 * k2, k1 = k0 + 1;
        float a = ((k0 >> 6) == (n >> 6))
            ? w2[((p << 1) + (n >> 6)) * (Dd * Dd) + (k0 & 63) * Dd + (n & 63)] : 0.f;
        float b = ((k1 >> 6) == (n >> 6))
            ? w2[((p << 1) + (n >> 6)) * (Dd * Dd) + (k1 & 63) * Dd + (n & 63)] : 0.f;
        g_w2T2[idx] = f2h2(a, b);
    }
    if (idx < Hh * (Hh / 2)) {
        int n = idx >> 7, k2 = idx & 127;
        g_cw1T2[idx] = f2h2(cw1[(2 * k2) * Hh + n], cw1[(2 * k2 + 1) * Hh + n]);
    }
    if (idx < Hh * ((Hh + Ff) / 2)) {
        int n = idx / 192, k2 = idx - n * 192;
        g_nw1T2[idx] = f2h2(nw1[(2 * k2) * Hh + n], nw1[(2 * k2 + 1) * Hh + n]);
    }
    if (idx < Ff * (Hh / 2)) {
        int n = idx >> 7, k2 = idx & 127;
        g_nw2T2[idx] = f2h2(nw2[(2 * k2) * Ff + n], nw2[(2 * k2 + 1) * Ff + n]);
    }
}

// geometry features per edge (thread per edge)
__global__ void k_geo(const float* __restrict__ coord, const int* __restrict__ ei) {
    int e = blockIdx.x * blockDim.x + threadIdx.x;
    if (e >= BE) return;
    int b = (e >= Ee) ? 1 : 0, j = e - b * Ee;
    int i = ei[j], k = ei[Ee + j];
    const float* ci = coord + ((size_t)b * Nn + i) * 3;
    const float* ck = coord + ((size_t)b * Nn + k) * 3;
    float cix = ci[0], ciy = ci[1], ciz = ci[2];
    float ckx = ck[0], cky = ck[1], ckz = ck[2];
    float dx = cix - ckx, dy = ciy - cky, dz = ciz - ckz;
    float radial = dx * dx + dy * dy + dz * dz;
    float dist = sqrtf(radial);
    float dotv = cix * ckx + ciy * cky + ciz * ckz;
    float inva = 1.f / (dist + 1e-8f);
    float ax = dx * inva, ay = dy * inva, az = dz * inva;
    float crx = ciy * ckz - ciz * cky;
    float cry = ciz * ckx - cix * ckz;
    float crz = cix * cky - ciy * ckx;
    float nb = sqrtf(crx * crx + cry * cry + crz * crz);
    float invb = 1.f / (nb + 1e-8f);
    float bx = crx * invb, by = cry * invb, bz = crz * invb;
    float cx = ay * bz - az * by;
    float cy = az * bx - ax * bz;
    float cz = ax * by - ay * bx;
    float na  = sqrtf(ax * ax + ay * ay + az * az);
    float nbv = sqrtf(bx * bx + by * by + bz * bz);
    float ncv = sqrtf(cx * cx + cy * cy + cz * cz);
    bool bad = (na < 1e-6f) || (nbv < 1e-6f) || (ncv < 1e-6f);
    if (bad) { ax = 1.f; bx = 0.f; cx = 0.f;
               ay = 0.f; by = 1.f; cy = 0.f;
               az = 0.f; bz = 0.f; cz = 1.f; }
    float4* g = (float4*)(g_geo + (size_t)e * 32);
    g[0] = make_float4(radial, dist, dotv, ax);
    g[1] = make_float4(bx, cx, ay, by);
    g[2] = make_float4(cy, az, bz, cz);
    float4 z = make_float4(0.f, 0.f, 0.f, 0.f);
    g[3] = z; g[4] = z; g[5] = z; g[6] = z; g[7] = z;
    g_cdiff[e * 3 + 0] = dx;
    g_cdiff[e * 3 + 1] = dy;
    g_cdiff[e * 3 + 2] = dz;
}

// ---------------- shared tile constants ----------------
#define AST 20
#define BST 20
#define MST 68
#define GT_BUF (128 * (AST + BST))
#define GT_SMEM (2 * GT_BUF * 4)

// ---------------- generic fp16 GEMM (double-buffered) ----------------
// EPI: 2 bias+silu, 3 bias+residual. MODE: 0 normal f32 A, 2 node-split A.
template <int EPI, int MODE>
__global__ void __launch_bounds__(256, 2) k_gemm_t(
    const float* __restrict__ A, const float* __restrict__ A2,
    const uint32_t* __restrict__ BT2, float* __restrict__ C,
    int K, int lda, int ldbT2, int ldc,
    const float* __restrict__ bias, const float* __restrict__ extra, int ldr)
{
    extern __shared__ uint32_t smbuf[];
    const int tid = threadIdx.x, lane = tid & 31, wid = tid >> 5;
    const int wm = wid >> 2, wn = wid & 3;
    const int m0 = blockIdx.y * 128, n0 = blockIdx.x * 128;

    const int am = tid >> 3;
    const int ak = (tid & 7) << 2;
    const int brow = tid >> 1;
    const int buc = (tid & 1) << 3;

    const uint32_t* BTg = BT2 + (size_t)(n0 + brow) * ldbT2;

    const float* pA[4]; const float* pS[4];
#pragma unroll
    for (int i = 0; i < 4; i++) {
        int r = m0 + am + 32 * i;
        if (MODE == 2) {
            pA[i] = A + (size_t)r * 128;
            pS[i] = A2 + (size_t)r * 256;
        } else {
            pA[i] = A + (size_t)r * lda;
        }
    }
    auto loadA = [&](int i, int kcol) -> float4 {
        if (MODE == 2) {
            if (kcol < 128) return *(const float4*)(pA[i] + kcol);
            return *(const float4*)(pS[i] + (kcol - 128));
        }
        return *(const float4*)(pA[i] + kcol);
    };

    float acc[4][4][4];
#pragma unroll
    for (int i = 0; i < 4; i++)
#pragma unroll
        for (int j = 0; j < 4; j++) { acc[i][j][0] = 0.f; acc[i][j][1] = 0.f; acc[i][j][2] = 0.f; acc[i][j][3] = 0.f; }

    float4 pa[4]; uint4 pb[2];
#pragma unroll
    for (int i = 0; i < 4; i++) pa[i] = loadA(i, ak);
    pb[0] = *(const uint4*)(BTg + buc);
    pb[1] = *(const uint4*)(BTg + buc + 4);

    const uint32_t as_base = (uint32_t)__cvta_generic_to_shared(smbuf);
    const uint32_t bs_base = as_base + 128 * AST * 4;
    const int a_r = wm * 64 + (lane & 15);
    const int a_q = (lane >> 4) << 2;
    const int b_r = wn * 32 + (lane & 7) + ((lane >> 4) << 3);
    const int b_q = ((lane >> 3) & 1) << 2;

    auto storeTiles = [&](int p) {
        uint32_t* Ab = smbuf + p * GT_BUF;
        uint32_t* Bb = Ab + 128 * AST;
#pragma unroll
        for (int i = 0; i < 4; i++)
            *(uint2*)&Ab[(am + 32 * i) * AST + (ak >> 1)] =
                make_uint2(f2h2(pa[i].x, pa[i].y), f2h2(pa[i].z, pa[i].w));
        *(uint4*)&Bb[brow * BST + buc]     = pb[0];
        *(uint4*)&Bb[brow * BST + buc + 4] = pb[1];
    };

    storeTiles(0);
    __syncthreads();

    int p = 0;
    for (int k0 = 0; k0 < K; k0 += 32) {
        bool more = (k0 + 32 < K);
        if (more) {
#pragma unroll
            for (int i = 0; i < 4; i++) pa[i] = loadA(i, k0 + 32 + ak);
            int ku = (k0 + 32) >> 1;
            pb[0] = *(const uint4*)(BTg + ku + buc);
            pb[1] = *(const uint4*)(BTg + ku + buc + 4);
        }
        const uint32_t ab = as_base + p * (GT_BUF * 4);
        const uint32_t bb = bs_base + p * (GT_BUF * 4);
#pragma unroll
        for (int kk = 0; kk < 2; kk++) {
            uint32_t af[4][4], bf[4][2];
#pragma unroll
            for (int mi = 0; mi < 4; mi++)
                ldsm4(af[mi][0], af[mi][1], af[mi][2], af[mi][3],
                      ab + (((a_r + mi * 16) * AST + kk * 8 + a_q) << 2));
#pragma unroll
            for (int np = 0; np < 2; np++) {
                uint32_t r0, r1, r2, r3;
                ldsm4(r0, r1, r2, r3,
                      bb + (((b_r + np * 16) * BST + kk * 8 + b_q) << 2));
                bf[np * 2][0] = r0; bf[np * 2][1] = r1;
                bf[np * 2 + 1][0] = r2; bf[np * 2 + 1][1] = r3;
            }
#pragma unroll
            for (int mi = 0; mi < 4; mi++)
#pragma unroll
                for (int ni = 0; ni < 4; ni++)
                    mma16(acc[mi][ni], af[mi], bf[ni]);
        }
        if (more) storeTiles(p ^ 1);
        __syncthreads();
        p ^= 1;
    }

    const int row0 = m0 + wm * 64 + (lane >> 2);
    const int colw = wn * 32 + ((lane & 3) << 1);
#pragma unroll
    for (int mi = 0; mi < 4; mi++) {
        int r = row0 + mi * 16;
#pragma unroll
        for (int ni = 0; ni < 4; ni++) {
            int col = n0 + colw + ni * 8;
            float2 bb = *(const float2*)(bias + col);
            float v0 = acc[mi][ni][0] + bb.x, v1 = acc[mi][ni][1] + bb.y;
            float v2 = acc[mi][ni][2] + bb.x, v3 = acc[mi][ni][3] + bb.y;
            if (EPI == 2) {
                v0 = silu_f(v0); v1 = silu_f(v1); v2 = silu_f(v2); v3 = silu_f(v3);
            }
            if (EPI == 3) {
                float2 ra = *(const float2*)(extra + (size_t)r * ldr + col);
                float2 rb = *(const float2*)(extra + (size_t)(r + 8) * ldr + col);
                v0 += ra.x; v1 += ra.y; v2 += rb.x; v3 += rb.y;
            }
            *(float2*)(C + (size_t)r * ldc + col)       = make_float2(v0, v1);
            *(float2*)(C + (size_t)(r + 8) * ldc + col) = make_float2(v2, v3);
        }
    }
}

// ---------------- GEMM3: resident-A LN + silu-dot (wsc) ----------------
// A = LN(ef2) staged ONCE into smem (128 x 256 halves, stride 132 uints),
// then two N-half passes stream cw1 B tiles (double-buffered).
#define G3_AST 132
#define G3_A_UINTS (128 * G3_AST)
#define G3_BUF 2560                      // 128 * BST
#define G3_SMEM ((G3_A_UINTS + 2 * G3_BUF) * 4)

__global__ void __launch_bounds__(256, 2) k_gemm3(
    const uint32_t* __restrict__ ef2, const uint32_t* __restrict__ cw1T2,
    const float* __restrict__ stats, const float* __restrict__ gam,
    const float* __restrict__ bet, const float* __restrict__ cb1,
    const float* __restrict__ cw2, float* __restrict__ wsc)
{
    extern __shared__ uint32_t sm[];
    const int tid = threadIdx.x, lane = tid & 31, wid = tid >> 5;
    const int wm = wid >> 2, wn = wid & 3;
    const int m0 = blockIdx.y * 128;

    const int am = tid >> 3;
    const int ak = (tid & 7) << 2;
    const int brow = tid >> 1;
    const int buc = (tid & 1) << 3;

    // ---- prologue: LN(ef) -> As, full 256 cols ----
    {
        const uint32_t* pH[4]; float mu[4], rs[4];
#pragma unroll
        for (int i = 0; i < 4; i++) {
            int r = m0 + am + 32 * i;
            pH[i] = ef2 + (size_t)r * (Hh / 2);
            float2 st = *(const float2*)(stats + 2 * (size_t)r);
            float m = st.x * (1.f / 256.f);
            float var = st.y * (1.f / 256.f) - m * m;
            mu[i] = m;
            rs[i] = rsqrtf(var + 1e-5f);
        }
        for (int kc = 0; kc < 8; kc++) {
            int kcol = kc * 32 + ak;
            float4 gm4 = *(const float4*)(gam + kcol);
            float4 bt4 = *(const float4*)(bet + kcol);
#pragma unroll
            for (int i = 0; i < 4; i++) {
                uint2 u = *(const uint2*)(pH[i] + (kcol >> 1));
                float2 f0 = h22f2(u.x), f1 = h22f2(u.y);
                float v0 = (f0.x - mu[i]) * rs[i] * gm4.x + bt4.x;
                float v1 = (f0.y - mu[i]) * rs[i] * gm4.y + bt4.y;
                float v2 = (f1.x - mu[i]) * rs[i] * gm4.z + bt4.z;
                float v3 = (f1.y - mu[i]) * rs[i] * gm4.w + bt4.w;
                *(uint2*)&sm[(am + 32 * i) * G3_AST + (kcol >> 1)] =
                    make_uint2(f2h2(v0, v1), f2h2(v2, v3));
            }
        }
    }
    __syncthreads();

    const uint32_t as_base = (uint32_t)__cvta_generic_to_shared(sm);
    const uint32_t bs_base = as_base + G3_A_UINTS * 4;
    const int a_r = wm * 64 + (lane & 15);
    const int a_q = (lane >> 4) << 2;
    const int b_r = wn * 32 + (lane & 7) + ((lane >> 4) << 3);
    const int b_q = ((lane >> 3) & 1) << 2;
    const int row0 = m0 + wm * 64 + (lane >> 2);
    const int colw = wn * 32 + ((lane & 3) << 1);

    for (int nb = 0; nb < 2; nb++) {
        const uint32_t* BTg = cw1T2 + (size_t)(nb * 128 + brow) * (Hh / 2);

        float acc[4][4][4];
#pragma unroll
        for (int i = 0; i < 4; i++)
#pragma unroll
            for (int j = 0; j < 4; j++) { acc[i][j][0] = 0.f; acc[i][j][1] = 0.f; acc[i][j][2] = 0.f; acc[i][j][3] = 0.f; }

        uint4 pb0 = *(const uint4*)(BTg + buc);
        uint4 pb1 = *(const uint4*)(BTg + buc + 4);
        {
            uint32_t* Bb = sm + G3_A_UINTS;
            *(uint4*)&Bb[brow * BST + buc]     = pb0;
            *(uint4*)&Bb[brow * BST + buc + 4] = pb1;
        }
        __syncthreads();

        int p = 0;
        for (int k0 = 0; k0 < 256; k0 += 32) {
            bool more = (k0 + 32 < 256);
            if (more) {
                int ku = (k0 + 32) >> 1;
                pb0 = *(const uint4*)(BTg + ku + buc);
                pb1 = *(const uint4*)(BTg + ku + buc + 4);
            }
            const uint32_t bb = bs_base + p * (G3_BUF * 4);
            const int abase = k0 >> 1;
#pragma unroll
            for (int kk = 0; kk < 2; kk++) {
                uint32_t af[4][4], bf[4][2];
#pragma unroll
                for (int mi = 0; mi < 4; mi++)
                    ldsm4(af[mi][0], af[mi][1], af[mi][2], af[mi][3],
                          as_base + (((a_r + mi * 16) * G3_AST + abase + kk * 8 + a_q) << 2));
#pragma unroll
                for (int np = 0; np < 2; np++) {
                    uint32_t r0, r1, r2, r3;
                    ldsm4(r0, r1, r2, r3,
                          bb + (((b_r + np * 16) * BST + kk * 8 + b_q) << 2));
                    bf[np * 2][0] = r0; bf[np * 2][1] = r1;
                    bf[np * 2 + 1][0] = r2; bf[np * 2 + 1][1] = r3;
                }
#pragma unroll
                for (int mi = 0; mi < 4; mi++)
#pragma unroll
                    for (int ni = 0; ni < 4; ni++)
                        mma16(acc[mi][ni], af[mi], bf[ni]);
            }
            if (more) {
                uint32_t* Bb = sm + G3_A_UINTS + (p ^ 1) * G3_BUF;
                *(uint4*)&Bb[brow * BST + buc]     = pb0;
                *(uint4*)&Bb[brow * BST + buc + 4] = pb1;
            }
            __syncthreads();
            p ^= 1;
        }

        // epilogue: bias + silu + dot with cw2 -> atomic wsc
#pragma unroll
        for (int mi = 0; mi < 4; mi++) {
            float slo = 0.f, shi = 0.f;
            int r = row0 + mi * 16;
#pragma unroll
            for (int ni = 0; ni < 4; ni++) {
                int col = nb * 128 + colw + ni * 8;
                float2 bb = *(const float2*)(cb1 + col);
                float v0 = silu_f(acc[mi][ni][0] + bb.x);
                float v1 = silu_f(acc[mi][ni][1] + bb.y);
                float v2 = silu_f(acc[mi][ni][2] + bb.x);
                float v3 = silu_f(acc[mi][ni][3] + bb.y);
                float2 w = *(const float2*)(cw2 + col);
                slo += v0 * w.x + v1 * w.y;
                shi += v2 * w.x + v3 * w.y;
            }
            slo += __shfl_xor_sync(0xffffffffu, slo, 1);
            slo += __shfl_xor_sync(0xffffffffu, slo, 2);
            shi += __shfl_xor_sync(0xffffffffu, shi, 1);
            shi += __shfl_xor_sync(0xffffffffu, shi, 2);
            if ((lane & 3) == 0) {
                atomicAdd(wsc + r, slo);
                atomicAdd(wsc + r + 8, shi);
            }
        }
    }
}

// ---------------- fused GEMM1+GEMM2 (fp16, double-buffered, +LN stats) ----------------
#define G12_BUF (128 * (AST + BST))
#define G12_SMEM ((2 * G12_BUF + 128 * MST) * 4)

__global__ void __launch_bounds__(256) k_gemm12(
    const float* __restrict__ h, const uint32_t* __restrict__ w1T2,
    const uint32_t* __restrict__ w2T2, uint32_t* __restrict__ ef2,
    const int* __restrict__ ei, const float* __restrict__ geo,
    const float* __restrict__ b1, const float* __restrict__ b2,
    float* __restrict__ stats)
{
    extern __shared__ uint32_t sm[];
    uint32_t* Ms = sm + 2 * G12_BUF;
    const int tid = threadIdx.x, lane = tid & 31, wid = tid >> 5;
    const int wm = wid >> 2, wn = wid & 3;
    const int m0 = blockIdx.y * 128, n0 = blockIdx.x * 128;

    const int am = tid >> 3;
    const int ak = (tid & 7) << 2;
    const int brow = tid >> 1;
    const int buc = (tid & 1) << 3;

    const uint32_t* BTg = w1T2 + (size_t)(n0 + brow) * (FEATP / 2);

    const float* pA[4]; const float* pS[4]; const float* pG[4];
    {
        int b = (m0 >= Ee) ? 1 : 0;
#pragma unroll
        for (int i = 0; i < 4; i++) {
            int r = m0 + am + 32 * i;
            int j = r - b * Ee;
            pA[i] = h + ((size_t)b * Nn + ei[j]) * Ff;
            pS[i] = h + ((size_t)b * Nn + ei[Ee + j]) * Ff;
            pG[i] = geo + (size_t)r * 32;
        }
    }
    auto loadA = [&](int i, int kcol) -> float4 {
        if (kcol < 128) return *(const float4*)(pA[i] + kcol);
        if (kcol < 256) return *(const float4*)(pS[i] + (kcol - 128));
        return *(const float4*)(pG[i] + (kcol - 256));
    };

    float acc[4][4][4];
#pragma unroll
    for (int i = 0; i < 4; i++)
#pragma unroll
        for (int j = 0; j < 4; j++) { acc[i][j][0] = 0.f; acc[i][j][1] = 0.f; acc[i][j][2] = 0.f; acc[i][j][3] = 0.f; }

    float4 pa[4]; uint4 pb[2];
#pragma unroll
    for (int i = 0; i < 4; i++) pa[i] = loadA(i, ak);
    pb[0] = *(const uint4*)(BTg + buc);
    pb[1] = *(const uint4*)(BTg + buc + 4);

    const uint32_t as_base = (uint32_t)__cvta_generic_to_shared(sm);
    const uint32_t bs_base = as_base + 128 * AST * 4;
    const uint32_t ms_base = as_base + 2 * G12_BUF * 4;
    const int a_r = wm * 64 + (lane & 15);
    const int a_q = (lane >> 4) << 2;
    const int b_r = wn * 32 + (lane & 7) + ((lane >> 4) << 3);
    const int b_q = ((lane >> 3) & 1) << 2;

    auto storeTiles = [&](int p) {
        uint32_t* Ab = sm + p * G12_BUF;
        uint32_t* Bb = Ab + 128 * AST;
#pragma unroll
        for (int i = 0; i < 4; i++)
            *(uint2*)&Ab[(am + 32 * i) * AST + (ak >> 1)] =
                make_uint2(f2h2(pa[i].x, pa[i].y), f2h2(pa[i].z, pa[i].w));
        *(uint4*)&Bb[brow * BST + buc]     = pb[0];
        *(uint4*)&Bb[brow * BST + buc + 4] = pb[1];
    };

    // ---- stage 1 mainloop, K=288, double-buffered ----
    storeTiles(0);
    __syncthreads();
    int p = 0;
    for (int k0 = 0; k0 < FEATP; k0 += 32) {
        bool more = (k0 + 32 < FEATP);
        if (more) {
#pragma unroll
            for (int i = 0; i < 4; i++) pa[i] = loadA(i, k0 + 32 + ak);
            int ku = (k0 + 32) >> 1;
            pb[0] = *(const uint4*)(BTg + ku + buc);
            pb[1] = *(const uint4*)(BTg + ku + buc + 4);
        }
        const uint32_t ab = as_base + p * (G12_BUF * 4);
        const uint32_t bb = bs_base + p * (G12_BUF * 4);
#pragma unroll
        for (int kk = 0; kk < 2; kk++) {
            uint32_t af[4][4], bf[4][2];
#pragma unroll
            for (int mi = 0; mi < 4; mi++)
                ldsm4(af[mi][0], af[mi][1], af[mi][2], af[mi][3],
                      ab + (((a_r + mi * 16) * AST + kk * 8 + a_q) << 2));
#pragma unroll
            for (int np = 0; np < 2; np++) {
                uint32_t r0, r1, r2, r3;
                ldsm4(r0, r1, r2, r3,
                      bb + (((b_r + np * 16) * BST + kk * 8 + b_q) << 2));
                bf[np * 2][0] = r0; bf[np * 2][1] = r1;
                bf[np * 2 + 1][0] = r2; bf[np * 2 + 1][1] = r3;
            }
#pragma unroll
            for (int mi = 0; mi < 4; mi++)
#pragma unroll
                for (int ni = 0; ni < 4; ni++)
                    mma16(acc[mi][ni], af[mi], bf[ni]);
        }
        if (more) storeTiles(p ^ 1);
        __syncthreads();
        p ^= 1;
    }

    // ---- epilogue 1: silu + bias -> Ms (half2), reset acc ----
    const int lrow0 = wm * 64 + (lane >> 2);
    const int lcolw = wn * 32 + ((lane & 3) << 1);
#pragma unroll
    for (int mi = 0; mi < 4; mi++) {
        int r = lrow0 + mi * 16;
#pragma unroll
        for (int ni = 0; ni < 4; ni++) {
            int col = lcolw + ni * 8;
            float2 bb = *(const float2*)(b1 + n0 + col);
            float v0 = silu_f(acc[mi][ni][0] + bb.x);
            float v1 = silu_f(acc[mi][ni][1] + bb.y);
            float v2 = silu_f(acc[mi][ni][2] + bb.x);
            float v3 = silu_f(acc[mi][ni][3] + bb.y);
            Ms[r * MST + (col >> 1)]       = f2h2(v0, v1);
            Ms[(r + 8) * MST + (col >> 1)] = f2h2(v2, v3);
            acc[mi][ni][0] = 0.f; acc[mi][ni][1] = 0.f;
            acc[mi][ni][2] = 0.f; acc[mi][ni][3] = 0.f;
        }
    }

    // ---- stage 2 mainloop, K=128, A from Ms, B double-buffered ----
    const uint32_t* W22 = w2T2 + (size_t)blockIdx.x * (128 * 64) + (size_t)brow * 64;
    pb[0] = *(const uint4*)(W22 + buc);
    pb[1] = *(const uint4*)(W22 + buc + 4);
    {
        uint32_t* Bb = sm + 128 * AST;
        *(uint4*)&Bb[brow * BST + buc]     = pb[0];
        *(uint4*)&Bb[brow * BST + buc + 4] = pb[1];
    }
    __syncthreads();   // covers Ms writes + Bs0 store
    p = 0;
    for (int k0 = 0; k0 < 128; k0 += 32) {
        bool more = (k0 + 32 < 128);
        if (more) {
            int ku = (k0 + 32) >> 1;
            pb[0] = *(const uint4*)(W22 + ku + buc);
            pb[1] = *(const uint4*)(W22 + ku + buc + 4);
        }
        const uint32_t bb = bs_base + p * (G12_BUF * 4);
        const int ku0 = k0 >> 1;
#pragma unroll
        for (int kk = 0; kk < 2; kk++) {
            uint32_t af[4][4], bf[4][2];
#pragma unroll
            for (int mi = 0; mi < 4; mi++)
                ldsm4(af[mi][0], af[mi][1], af[mi][2], af[mi][3],
                      ms_base + (((a_r + mi * 16) * MST + ku0 + kk * 8 + a_q) << 2));
#pragma unroll
            for (int np = 0; np < 2; np++) {
                uint32_t r0, r1, r2, r3;
                ldsm4(r0, r1, r2, r3,
                      bb + (((b_r + np * 16) * BST + kk * 8 + b_q) << 2));
                bf[np * 2][0] = r0; bf[np * 2][1] = r1;
                bf[np * 2 + 1][0] = r2; bf[np * 2 + 1][1] = r3;
            }
#pragma unroll
            for (int mi = 0; mi < 4; mi++)
#pragma unroll
                for (int ni = 0; ni < 4; ni++)
                    mma16(acc[mi][ni], af[mi], bf[ni]);
        }
        if (more) {
            uint32_t* Bb = sm + (p ^ 1) * G12_BUF + 128 * AST;
            *(uint4*)&Bb[brow * BST + buc]     = pb[0];
            *(uint4*)&Bb[brow * BST + buc + 4] = pb[1];
        }
        __syncthreads();
        p ^= 1;
    }

    // ---- epilogue 2: + b2, store half2 to ef2, LN partial stats via atomics ----
#pragma unroll
    for (int mi = 0; mi < 4; mi++) {
        int r = m0 + lrow0 + mi * 16;
        float s_lo = 0.f, ss_lo = 0.f, s_hi = 0.f, ss_hi = 0.f;
#pragma unroll
        for (int ni = 0; ni < 4; ni++) {
            int col = n0 + lcolw + ni * 8;
            float2 bb = *(const float2*)(b2 + col);
            float v0 = acc[mi][ni][0] + bb.x, v1 = acc[mi][ni][1] + bb.y;
            float v2 = acc[mi][ni][2] + bb.x, v3 = acc[mi][ni][3] + bb.y;
            ef2[(size_t)r * (Hh / 2) + (col >> 1)]       = f2h2(v0, v1);
            ef2[(size_t)(r + 8) * (Hh / 2) + (col >> 1)] = f2h2(v2, v3);
            s_lo += v0 + v1; ss_lo += v0 * v0 + v1 * v1;
            s_hi += v2 + v3; ss_hi += v2 * v2 + v3 * v3;
        }
        s_lo  += __shfl_xor_sync(0xffffffffu, s_lo, 1);
        s_lo  += __shfl_xor_sync(0xffffffffu, s_lo, 2);
        ss_lo += __shfl_xor_sync(0xffffffffu, ss_lo, 1);
        ss_lo += __shfl_xor_sync(0xffffffffu, ss_lo, 2);
        s_hi  += __shfl_xor_sync(0xffffffffu, s_hi, 1);
        s_hi  += __shfl_xor_sync(0xffffffffu, s_hi, 2);
        ss_hi += __shfl_xor_sync(0xffffffffu, ss_hi, 1);
        ss_hi += __shfl_xor_sync(0xffffffffu, ss_hi, 2);
        if ((lane & 3) == 0) {
            atomicAdd(stats + 2 * (size_t)r,           s_lo);
            atomicAdd(stats + 2 * (size_t)r + 1,       ss_lo);
            atomicAdd(stats + 2 * (size_t)(r + 8),     s_hi);
            atomicAdd(stats + 2 * (size_t)(r + 8) + 1, ss_hi);
        }
    }
}

// Combined scatter (after GEMM3): LN from stats + agg segment-sum + coord scatter.
__global__ void k_scatter2(const float* __restrict__ gam, const float* __restrict__ bet,
                           const int* __restrict__ ei, float* __restrict__ outc) {
    int wid = blockIdx.x * (blockDim.x >> 5) + (threadIdx.x >> 5);
    int lane = threadIdx.x & 31;
    if (wid >= BE) return;
    const uint32_t* row = g_ef2 + (size_t)wid * (Hh / 2);
    float2 st = *(const float2*)(g_stats + 2 * (size_t)wid);
    float mu = st.x * (1.f / 256.f);
    float var = st.y * (1.f / 256.f) - mu * mu;
    float rstd = rsqrtf(var + 1e-5f);
    uint4 u = ((const uint4*)row)[lane];
    float2 f0 = h22f2(u.x), f1 = h22f2(u.y), f2v = h22f2(u.z), f3 = h22f2(u.w);
    float4 g0 = ((const float4*)gam)[2 * lane], g1 = ((const float4*)gam)[2 * lane + 1];
    float4 b0 = ((const float4*)bet)[2 * lane], b1 = ((const float4*)bet)[2 * lane + 1];
    float4 x0, x1;
    x0.x = (f0.x - mu) * rstd * g0.x + b0.x;
    x0.y = (f0.y - mu) * rstd * g0.y + b0.y;
    x0.z = (f1.x - mu) * rstd * g0.z + b0.z;
    x0.w = (f1.y - mu) * rstd * g0.w + b0.w;
    x1.x = (f2v.x - mu) * rstd * g1.x + b1.x;
    x1.y = (f2v.y - mu) * rstd * g1.y + b1.y;
    x1.z = (f3.x - mu) * rstd * g1.z + b1.z;
    x1.w = (f3.y - mu) * rstd * g1.w + b1.w;
    int b = (wid >= Ee) ? 1 : 0, j = wid - b * Ee;
    int i = ei[j];
    float* arow = g_agg + ((size_t)b * Nn + i) * Hh;
    red4(arow + 8 * lane, x0);
    red4(arow + 8 * lane + 4, x1);
    if (lane < 3) {
        float wv = g_wsc[wid];
        atomicAdd(&outc[((size_t)b * Nn + i) * 3 + lane], g_cdiff[wid * 3 + lane] * wv);
    }
}

// ---------------- launch ----------------
extern "C" void kernel_launch(void* const* d_in, const int* in_sizes, int n_in,
                              void* d_out, int out_size) {
    const float* h     = (const float*)d_in[0];
    const float* coord = (const float*)d_in[1];
    const int*   ei    = (const int*)d_in[2];
    const float* ew1   = (const float*)d_in[3];
    const float* eb1   = (const float*)d_in[4];
    const float* ew2   = (const float*)d_in[5];
    const float* eb2   = (const float*)d_in[6];
    const float* lng   = (const float*)d_in[7];
    const float* lnb   = (const float*)d_in[8];
    const float* nw1   = (const float*)d_in[9];
    const float* nb1   = (const float*)d_in[10];
    const float* nw2   = (const float*)d_in[11];
    const float* nb2   = (const float*)d_in[12];
    const float* cw1   = (const float*)d_in[13];
    const float* cb1   = (const float*)d_in[14];
    const float* cw2   = (const float*)d_in[15];

    float* out_h = (float*)d_out;
    float* out_c = out_h + (size_t)BNr * Ff;

    void *p_ef2, *p_stats, *p_geo, *p_w1T2, *p_w2T2, *p_cw1T2, *p_nw1T2, *p_nw2T2,
         *p_agg, *p_nodemid, *p_wsc;
    cudaGetSymbolAddress(&p_ef2,     g_ef2);
    cudaGetSymbolAddress(&p_stats,   g_stats);
    cudaGetSymbolAddress(&p_geo,     g_geo);
    cudaGetSymbolAddress(&p_w1T2,    g_w1T2);
    cudaGetSymbolAddress(&p_w2T2,    g_w2T2);
    cudaGetSymbolAddress(&p_cw1T2,   g_cw1T2);
    cudaGetSymbolAddress(&p_nw1T2,   g_nw1T2);
    cudaGetSymbolAddress(&p_nw2T2,   g_nw2T2);
    cudaGetSymbolAddress(&p_agg,     g_agg);
    cudaGetSymbolAddress(&p_nodemid, g_nodemid);
    cudaGetSymbolAddress(&p_wsc,     g_wsc);
    uint32_t*       ef2p     = (uint32_t*)p_ef2;
    float*          statsp   = (float*)p_stats;
    const float*    geop     = (const float*)p_geo;
    const uint32_t* w1T2p    = (const uint32_t*)p_w1T2;
    const uint32_t* w2T2p    = (const uint32_t*)p_w2T2;
    const uint32_t* cw1T2p   = (const uint32_t*)p_cw1T2;
    const uint32_t* nw1T2p   = (const uint32_t*)p_nw1T2;
    const uint32_t* nw2T2p   = (const uint32_t*)p_nw2T2;
    const float*    aggp     = (const float*)p_agg;
    float*          nodemidp = (float*)p_nodemid;
    float*          wscp     = (float*)p_wsc;

    cudaFuncSetAttribute(k_gemm12, cudaFuncAttributeMaxDynamicSharedMemorySize, G12_SMEM);
    cudaFuncSetAttribute(k_gemm3,  cudaFuncAttributeMaxDynamicSharedMemorySize, G3_SMEM);
    cudaFuncSetAttribute(k_gemm_t<2, 2>, cudaFuncAttributeMaxDynamicSharedMemorySize, GT_SMEM);
    cudaFuncSetAttribute(k_gemm_t<3, 0>, cudaFuncAttributeMaxDynamicSharedMemorySize, GT_SMEM);

    // init + weight packing (also zeroes stats/agg/wsc)
    k_misc<<<(BNr * Hh + 255) / 256, 256>>>(coord, out_c, ew1, ew2, cw1, nw1, nw2);
    k_geo<<<BE / 256, 256>>>(coord, ei);

    // fused GEMM1+GEMM2 (+ atomic LN stats), ef stored as half2
    k_gemm12<<<dim3(2, BE / 128), 256, G12_SMEM>>>(h, w1T2p, w2T2p, ef2p, ei, geop, eb1, eb2, statsp);

    // GEMM3: resident LN'd A, both N-halves, wsc dot
    k_gemm3<<<dim3(1, BE / 128), 256, G3_SMEM>>>(ef2p, cw1T2p, statsp, lng, lnb, cb1, cw2, wscp);

    // combined scatter: LN+agg segment-sum + coord scatter (wsc ready)
    k_scatter2<<<BE / 8, 256>>>(lng, lnb, ei, out_c);

    // node MLP (input concat fused via split-A)
    k_gemm_t<2, 2><<<dim3(2, BNr / 128), 256, GT_SMEM>>>(
        h, aggp, nw1T2p, nodemidp, Hh + Ff, 0, (Hh + Ff) / 2, Hh, nb1, nullptr, 0);
    k_gemm_t<3, 0><<<dim3(1, BNr / 128), 256, GT_SMEM>>>(
        nodemidp, nullptr, nw2T2p, out_h, Hh, Hh, Hh / 2, Ff, nb2, h, Ff);
}

// round 17
// speedup vs baseline: 2.1568x; 1.0451x over previous
#include <cuda_runtime.h>
#include <cuda_fp16.h>
#include <math.h>
#include <stdint.h>

// Problem constants (fixed shapes)
#define Bc   2
#define Nn   8192
#define Ff   128
#define Ee   131072
#define Hh   256
#define NHh  4
#define Dd   64
#define FEATN 268
#define FEATP 288          // padded K for GEMM1
#define BE   (Bc*Ee)       // 262144 edge rows
#define BNr  (Bc*Nn)       // 16384 node rows

// ---------------- static scratch ----------------
static __device__ uint32_t g_ef2[(size_t)BE * (Hh / 2)];   // raw (pre-LN) edge features, half2-packed
static __device__ float g_stats[(size_t)BE * 2];           // per row: sum, sumsq (atomic-accumulated)
static __device__ float g_geo[(size_t)BE * 32];
static __device__ float g_cdiff[BE * 3];
static __device__ float g_wsc[BE];
static __device__ float g_agg[BNr * Hh];
static __device__ float g_nodemid[BNr * Hh];
// pre-transposed, pre-packed half2 weights: BT2[n][k/2]
static __device__ uint32_t g_w1T2[Hh * (FEATP / 2)];        // 256 x 144
static __device__ uint32_t g_w2T2[2 * 128 * 64];            // pair-block-diag, 128 x 64
static __device__ uint32_t g_cw1T2[Hh * (Hh / 2)];          // 256 x 128
static __device__ uint32_t g_nw1T2[Hh * ((Hh + Ff) / 2)];   // 256 x 192
static __device__ uint32_t g_nw2T2[Ff * (Hh / 2)];          // 128 x 128

// ---------------- helpers ----------------
__device__ __forceinline__ uint32_t f2h2(float a, float b) {
    __half2 h = __floats2half2_rn(a, b);
    return *(uint32_t*)&h;
}
__device__ __forceinline__ float2 h22f2(uint32_t u) {
    return __half22float2(*(__half2*)&u);
}
__device__ __forceinline__ void ldsm4(uint32_t& r0, uint32_t& r1, uint32_t& r2, uint32_t& r3, uint32_t a) {
    asm volatile("ldmatrix.sync.aligned.m8n8.x4.shared.b16 {%0,%1,%2,%3}, [%4];"
                 : "=r"(r0), "=r"(r1), "=r"(r2), "=r"(r3) : "r"(a));
}
__device__ __forceinline__ void mma16(float* c, const uint32_t* a, const uint32_t* b) {
    asm volatile("mma.sync.aligned.m16n8k16.row.col.f32.f16.f16.f32 "
                 "{%0,%1,%2,%3}, {%4,%5,%6,%7}, {%8,%9}, {%0,%1,%2,%3};"
                 : "+f"(c[0]), "+f"(c[1]), "+f"(c[2]), "+f"(c[3])
                 : "r"(a[0]), "r"(a[1]), "r"(a[2]), "r"(a[3]), "r"(b[0]), "r"(b[1]));
}
__device__ __forceinline__ float silu_f(float x) { return x / (1.f + expf(-x)); }
__device__ __forceinline__ void red4(float* addr, float4 v) {
    asm volatile("red.global.add.v4.f32 [%0], {%1,%2,%3,%4};"
                 :: "l"(addr), "f"(v.x), "f"(v.y), "f"(v.z), "f"(v.w) : "memory");
}

// ---------------- combined init ----------------
__global__ void k_misc(const float* __restrict__ coord, float* __restrict__ outc,
                       const float* __restrict__ w1, const float* __restrict__ w2,
                       const float* __restrict__ cw1, const float* __restrict__ nw1,
                       const float* __restrict__ nw2) {
    int idx = blockIdx.x * blockDim.x + threadIdx.x;
    if (idx < BNr * Hh) g_agg[idx] = 0.f;
    if (idx < BE) g_wsc[idx] = 0.f;
    if (idx < BE * 2) g_stats[idx] = 0.f;
    if (idx < Bc * Nn * 3) outc[idx] = coord[idx];
    if (idx < Hh * (FEATP / 2)) {
        int n = idx / (FEATP / 2), f2 = idx - n * (FEATP / 2);
        int f0 = 2 * f2, f1 = f0 + 1;
        float a = (f0 < FEATN) ? w1[(((n >> 6) * FEATN) + f0) * Dd + (n & 63)] : 0.f;
        float b = (f1 < FEATN) ? w1[(((n >> 6) * FEATN) + f1) * Dd + (n & 63)] : 0.f;
        g_w1T2[idx] = f2h2(a, b);
    }
    if (idx < 2 * 128 * 64) {
        int p = idx >> 13, rem = idx & 8191;
        int n = rem >> 6, k2 = rem & 63;
        int k0 = 2 * k2, k1 = k0 + 1;
        float a = ((k0 >> 6) == (n >> 6))
            ? w2[((p << 1) + (n >> 6)) * (Dd * Dd) + (k0 & 63) * Dd + (n & 63)] : 0.f;
        float b = ((k1 >> 6) == (n >> 6))
            ? w2[((p << 1) + (n >> 6)) * (Dd * Dd) + (k1 & 63) * Dd + (n & 63)] : 0.f;
        g_w2T2[idx] = f2h2(a, b);
    }
    if (idx < Hh * (Hh / 2)) {
        int n = idx >> 7, k2 = idx & 127;
        g_cw1T2[idx] = f2h2(cw1[(2 * k2) * Hh + n], cw1[(2 * k2 + 1) * Hh + n]);
    }
    if (idx < Hh * ((Hh + Ff) / 2)) {
        int n = idx / 192, k2 = idx - n * 192;
        g_nw1T2[idx] = f2h2(nw1[(2 * k2) * Hh + n], nw1[(2 * k2 + 1) * Hh + n]);
    }
    if (idx < Ff * (Hh / 2)) {
        int n = idx >> 7, k2 = idx & 127;
        g_nw2T2[idx] = f2h2(nw2[(2 * k2) * Ff + n], nw2[(2 * k2 + 1) * Ff + n]);
    }
}

// geometry features per edge (thread per edge)
__global__ void k_geo(const float* __restrict__ coord, const int* __restrict__ ei) {
    int e = blockIdx.x * blockDim.x + threadIdx.x;
    if (e >= BE) return;
    int b = (e >= Ee) ? 1 : 0, j = e - b * Ee;
    int i = ei[j], k = ei[Ee + j];
    const float* ci = coord + ((size_t)b * Nn + i) * 3;
    const float* ck = coord + ((size_t)b * Nn + k) * 3;
    float cix = ci[0], ciy = ci[1], ciz = ci[2];
    float ckx = ck[0], cky = ck[1], ckz = ck[2];
    float dx = cix - ckx, dy = ciy - cky, dz = ciz - ckz;
    float radial = dx * dx + dy * dy + dz * dz;
    float dist = sqrtf(radial);
    float dotv = cix * ckx + ciy * cky + ciz * ckz;
    float inva = 1.f / (dist + 1e-8f);
    float ax = dx * inva, ay = dy * inva, az = dz * inva;
    float crx = ciy * ckz - ciz * cky;
    float cry = ciz * ckx - cix * ckz;
    float crz = cix * cky - ciy * ckx;
    float nb = sqrtf(crx * crx + cry * cry + crz * crz);
    float invb = 1.f / (nb + 1e-8f);
    float bx = crx * invb, by = cry * invb, bz = crz * invb;
    float cx = ay * bz - az * by;
    float cy = az * bx - ax * bz;
    float cz = ax * by - ay * bx;
    float na  = sqrtf(ax * ax + ay * ay + az * az);
    float nbv = sqrtf(bx * bx + by * by + bz * bz);
    float ncv = sqrtf(cx * cx + cy * cy + cz * cz);
    bool bad = (na < 1e-6f) || (nbv < 1e-6f) || (ncv < 1e-6f);
    if (bad) { ax = 1.f; bx = 0.f; cx = 0.f;
               ay = 0.f; by = 1.f; cy = 0.f;
               az = 0.f; bz = 0.f; cz = 1.f; }
    float4* g = (float4*)(g_geo + (size_t)e * 32);
    g[0] = make_float4(radial, dist, dotv, ax);
    g[1] = make_float4(bx, cx, ay, by);
    g[2] = make_float4(cy, az, bz, cz);
    float4 z = make_float4(0.f, 0.f, 0.f, 0.f);
    g[3] = z; g[4] = z; g[5] = z; g[6] = z; g[7] = z;
    g_cdiff[e * 3 + 0] = dx;
    g_cdiff[e * 3 + 1] = dy;
    g_cdiff[e * 3 + 2] = dz;
}

// ---------------- shared tile constants ----------------
#define AST 20
#define BST 20
#define MST 68
#define GT_BUF (128 * (AST + BST))
#define GT_SMEM (2 * GT_BUF * 4)

// ---------------- generic fp16 GEMM (double-buffered) ----------------
// EPI: 2 bias+silu, 3 bias+residual. MODE: 0 normal f32 A, 2 node-split A.
template <int EPI, int MODE>
__global__ void __launch_bounds__(256, 2) k_gemm_t(
    const float* __restrict__ A, const float* __restrict__ A2,
    const uint32_t* __restrict__ BT2, float* __restrict__ C,
    int K, int lda, int ldbT2, int ldc,
    const float* __restrict__ bias, const float* __restrict__ extra, int ldr)
{
    extern __shared__ uint32_t smbuf[];
    const int tid = threadIdx.x, lane = tid & 31, wid = tid >> 5;
    const int wm = wid >> 2, wn = wid & 3;
    const int m0 = blockIdx.y * 128, n0 = blockIdx.x * 128;

    const int am = tid >> 3;
    const int ak = (tid & 7) << 2;
    const int brow = tid >> 1;
    const int buc = (tid & 1) << 3;

    const uint32_t* BTg = BT2 + (size_t)(n0 + brow) * ldbT2;

    const float* pA[4]; const float* pS[4];
#pragma unroll
    for (int i = 0; i < 4; i++) {
        int r = m0 + am + 32 * i;
        if (MODE == 2) {
            pA[i] = A + (size_t)r * 128;
            pS[i] = A2 + (size_t)r * 256;
        } else {
            pA[i] = A + (size_t)r * lda;
        }
    }
    auto loadA = [&](int i, int kcol) -> float4 {
        if (MODE == 2) {
            if (kcol < 128) return *(const float4*)(pA[i] + kcol);
            return *(const float4*)(pS[i] + (kcol - 128));
        }
        return *(const float4*)(pA[i] + kcol);
    };

    float acc[4][4][4];
#pragma unroll
    for (int i = 0; i < 4; i++)
#pragma unroll
        for (int j = 0; j < 4; j++) { acc[i][j][0] = 0.f; acc[i][j][1] = 0.f; acc[i][j][2] = 0.f; acc[i][j][3] = 0.f; }

    float4 pa[4]; uint4 pb[2];
#pragma unroll
    for (int i = 0; i < 4; i++) pa[i] = loadA(i, ak);
    pb[0] = *(const uint4*)(BTg + buc);
    pb[1] = *(const uint4*)(BTg + buc + 4);

    const uint32_t as_base = (uint32_t)__cvta_generic_to_shared(smbuf);
    const uint32_t bs_base = as_base + 128 * AST * 4;
    const int a_r = wm * 64 + (lane & 15);
    const int a_q = (lane >> 4) << 2;
    const int b_r = wn * 32 + (lane & 7) + ((lane >> 4) << 3);
    const int b_q = ((lane >> 3) & 1) << 2;

    auto storeTiles = [&](int p) {
        uint32_t* Ab = smbuf + p * GT_BUF;
        uint32_t* Bb = Ab + 128 * AST;
#pragma unroll
        for (int i = 0; i < 4; i++)
            *(uint2*)&Ab[(am + 32 * i) * AST + (ak >> 1)] =
                make_uint2(f2h2(pa[i].x, pa[i].y), f2h2(pa[i].z, pa[i].w));
        *(uint4*)&Bb[brow * BST + buc]     = pb[0];
        *(uint4*)&Bb[brow * BST + buc + 4] = pb[1];
    };

    storeTiles(0);
    __syncthreads();

    int p = 0;
    for (int k0 = 0; k0 < K; k0 += 32) {
        bool more = (k0 + 32 < K);
        if (more) {
#pragma unroll
            for (int i = 0; i < 4; i++) pa[i] = loadA(i, k0 + 32 + ak);
            int ku = (k0 + 32) >> 1;
            pb[0] = *(const uint4*)(BTg + ku + buc);
            pb[1] = *(const uint4*)(BTg + ku + buc + 4);
        }
        const uint32_t ab = as_base + p * (GT_BUF * 4);
        const uint32_t bb = bs_base + p * (GT_BUF * 4);
#pragma unroll
        for (int kk = 0; kk < 2; kk++) {
            uint32_t af[4][4], bf[4][2];
#pragma unroll
            for (int mi = 0; mi < 4; mi++)
                ldsm4(af[mi][0], af[mi][1], af[mi][2], af[mi][3],
                      ab + (((a_r + mi * 16) * AST + kk * 8 + a_q) << 2));
#pragma unroll
            for (int np = 0; np < 2; np++) {
                uint32_t r0, r1, r2, r3;
                ldsm4(r0, r1, r2, r3,
                      bb + (((b_r + np * 16) * BST + kk * 8 + b_q) << 2));
                bf[np * 2][0] = r0; bf[np * 2][1] = r1;
                bf[np * 2 + 1][0] = r2; bf[np * 2 + 1][1] = r3;
            }
#pragma unroll
            for (int mi = 0; mi < 4; mi++)
#pragma unroll
                for (int ni = 0; ni < 4; ni++)
                    mma16(acc[mi][ni], af[mi], bf[ni]);
        }
        if (more) storeTiles(p ^ 1);
        __syncthreads();
        p ^= 1;
    }

    const int row0 = m0 + wm * 64 + (lane >> 2);
    const int colw = wn * 32 + ((lane & 3) << 1);
#pragma unroll
    for (int mi = 0; mi < 4; mi++) {
        int r = row0 + mi * 16;
#pragma unroll
        for (int ni = 0; ni < 4; ni++) {
            int col = n0 + colw + ni * 8;
            float2 bb = *(const float2*)(bias + col);
            float v0 = acc[mi][ni][0] + bb.x, v1 = acc[mi][ni][1] + bb.y;
            float v2 = acc[mi][ni][2] + bb.x, v3 = acc[mi][ni][3] + bb.y;
            if (EPI == 2) {
                v0 = silu_f(v0); v1 = silu_f(v1); v2 = silu_f(v2); v3 = silu_f(v3);
            }
            if (EPI == 3) {
                float2 ra = *(const float2*)(extra + (size_t)r * ldr + col);
                float2 rb = *(const float2*)(extra + (size_t)(r + 8) * ldr + col);
                v0 += ra.x; v1 += ra.y; v2 += rb.x; v3 += rb.y;
            }
            *(float2*)(C + (size_t)r * ldc + col)       = make_float2(v0, v1);
            *(float2*)(C + (size_t)(r + 8) * ldc + col) = make_float2(v2, v3);
        }
    }
}

// ---------------- GEMM3: resident-A LN + silu-dot (wsc) ----------------
#define G3_AST 132
#define G3_A_UINTS (128 * G3_AST)
#define G3_BUF 2560                      // 128 * BST
#define G3_SMEM ((G3_A_UINTS + 2 * G3_BUF) * 4)

__global__ void __launch_bounds__(256, 2) k_gemm3(
    const uint32_t* __restrict__ ef2, const uint32_t* __restrict__ cw1T2,
    const float* __restrict__ stats, const float* __restrict__ gam,
    const float* __restrict__ bet, const float* __restrict__ cb1,
    const float* __restrict__ cw2, float* __restrict__ wsc)
{
    extern __shared__ uint32_t sm[];
    const int tid = threadIdx.x, lane = tid & 31, wid = tid >> 5;
    const int wm = wid >> 2, wn = wid & 3;
    const int m0 = blockIdx.y * 128;

    const int am = tid >> 3;
    const int ak = (tid & 7) << 2;
    const int brow = tid >> 1;
    const int buc = (tid & 1) << 3;

    // ---- prologue: LN(ef) -> As, full 256 cols ----
    {
        const uint32_t* pH[4]; float mu[4], rs[4];
#pragma unroll
        for (int i = 0; i < 4; i++) {
            int r = m0 + am + 32 * i;
            pH[i] = ef2 + (size_t)r * (Hh / 2);
            float2 st = *(const float2*)(stats + 2 * (size_t)r);
            float m = st.x * (1.f / 256.f);
            float var = st.y * (1.f / 256.f) - m * m;
            mu[i] = m;
            rs[i] = rsqrtf(var + 1e-5f);
        }
        for (int kc = 0; kc < 8; kc++) {
            int kcol = kc * 32 + ak;
            float4 gm4 = *(const float4*)(gam + kcol);
            float4 bt4 = *(const float4*)(bet + kcol);
#pragma unroll
            for (int i = 0; i < 4; i++) {
                uint2 u = *(const uint2*)(pH[i] + (kcol >> 1));
                float2 f0 = h22f2(u.x), f1 = h22f2(u.y);
                float v0 = (f0.x - mu[i]) * rs[i] * gm4.x + bt4.x;
                float v1 = (f0.y - mu[i]) * rs[i] * gm4.y + bt4.y;
                float v2 = (f1.x - mu[i]) * rs[i] * gm4.z + bt4.z;
                float v3 = (f1.y - mu[i]) * rs[i] * gm4.w + bt4.w;
                *(uint2*)&sm[(am + 32 * i) * G3_AST + (kcol >> 1)] =
                    make_uint2(f2h2(v0, v1), f2h2(v2, v3));
            }
        }
    }
    __syncthreads();

    const uint32_t as_base = (uint32_t)__cvta_generic_to_shared(sm);
    const uint32_t bs_base = as_base + G3_A_UINTS * 4;
    const int a_r = wm * 64 + (lane & 15);
    const int a_q = (lane >> 4) << 2;
    const int b_r = wn * 32 + (lane & 7) + ((lane >> 4) << 3);
    const int b_q = ((lane >> 3) & 1) << 2;
    const int row0 = m0 + wm * 64 + (lane >> 2);
    const int colw = wn * 32 + ((lane & 3) << 1);

    for (int nb = 0; nb < 2; nb++) {
        const uint32_t* BTg = cw1T2 + (size_t)(nb * 128 + brow) * (Hh / 2);

        float acc[4][4][4];
#pragma unroll
        for (int i = 0; i < 4; i++)
#pragma unroll
            for (int j = 0; j < 4; j++) { acc[i][j][0] = 0.f; acc[i][j][1] = 0.f; acc[i][j][2] = 0.f; acc[i][j][3] = 0.f; }

        uint4 pb0 = *(const uint4*)(BTg + buc);
        uint4 pb1 = *(const uint4*)(BTg + buc + 4);
        {
            uint32_t* Bb = sm + G3_A_UINTS;
            *(uint4*)&Bb[brow * BST + buc]     = pb0;
            *(uint4*)&Bb[brow * BST + buc + 4] = pb1;
        }
        __syncthreads();

        int p = 0;
        for (int k0 = 0; k0 < 256; k0 += 32) {
            bool more = (k0 + 32 < 256);
            if (more) {
                int ku = (k0 + 32) >> 1;
                pb0 = *(const uint4*)(BTg + ku + buc);
                pb1 = *(const uint4*)(BTg + ku + buc + 4);
            }
            const uint32_t bb = bs_base + p * (G3_BUF * 4);
            const int abase = k0 >> 1;
#pragma unroll
            for (int kk = 0; kk < 2; kk++) {
                uint32_t af[4][4], bf[4][2];
#pragma unroll
                for (int mi = 0; mi < 4; mi++)
                    ldsm4(af[mi][0], af[mi][1], af[mi][2], af[mi][3],
                          as_base + (((a_r + mi * 16) * G3_AST + abase + kk * 8 + a_q) << 2));
#pragma unroll
                for (int np = 0; np < 2; np++) {
                    uint32_t r0, r1, r2, r3;
                    ldsm4(r0, r1, r2, r3,
                          bb + (((b_r + np * 16) * BST + kk * 8 + b_q) << 2));
                    bf[np * 2][0] = r0; bf[np * 2][1] = r1;
                    bf[np * 2 + 1][0] = r2; bf[np * 2 + 1][1] = r3;
                }
#pragma unroll
                for (int mi = 0; mi < 4; mi++)
#pragma unroll
                    for (int ni = 0; ni < 4; ni++)
                        mma16(acc[mi][ni], af[mi], bf[ni]);
            }
            if (more) {
                uint32_t* Bb = sm + G3_A_UINTS + (p ^ 1) * G3_BUF;
                *(uint4*)&Bb[brow * BST + buc]     = pb0;
                *(uint4*)&Bb[brow * BST + buc + 4] = pb1;
            }
            __syncthreads();
            p ^= 1;
        }

        // epilogue: bias + silu + dot with cw2 -> atomic wsc
#pragma unroll
        for (int mi = 0; mi < 4; mi++) {
            float slo = 0.f, shi = 0.f;
            int r = row0 + mi * 16;
#pragma unroll
            for (int ni = 0; ni < 4; ni++) {
                int col = nb * 128 + colw + ni * 8;
                float2 bb = *(const float2*)(cb1 + col);
                float v0 = silu_f(acc[mi][ni][0] + bb.x);
                float v1 = silu_f(acc[mi][ni][1] + bb.y);
                float v2 = silu_f(acc[mi][ni][2] + bb.x);
                float v3 = silu_f(acc[mi][ni][3] + bb.y);
                float2 w = *(const float2*)(cw2 + col);
                slo += v0 * w.x + v1 * w.y;
                shi += v2 * w.x + v3 * w.y;
            }
            slo += __shfl_xor_sync(0xffffffffu, slo, 1);
            slo += __shfl_xor_sync(0xffffffffu, slo, 2);
            shi += __shfl_xor_sync(0xffffffffu, shi, 1);
            shi += __shfl_xor_sync(0xffffffffu, shi, 2);
            if ((lane & 3) == 0) {
                atomicAdd(wsc + r, slo);
                atomicAdd(wsc + r + 8, shi);
            }
        }
    }
}

// ---------------- fused GEMM1+GEMM2 (fp16, single-buffered — R15 config) ----------------
#define G12_SMEM (128 * (AST + BST + MST) * 4)   // ~55 KB

__global__ void __launch_bounds__(256) k_gemm12(
    const float* __restrict__ h, const uint32_t* __restrict__ w1T2,
    const uint32_t* __restrict__ w2T2, uint32_t* __restrict__ ef2,
    const int* __restrict__ ei, const float* __restrict__ geo,
    const float* __restrict__ b1, const float* __restrict__ b2,
    float* __restrict__ stats)
{
    extern __shared__ uint32_t sm[];
    uint32_t* As = sm;
    uint32_t* Bs = sm + 128 * AST;
    uint32_t* Ms = sm + 128 * (AST + BST);
    const int tid = threadIdx.x, lane = tid & 31, wid = tid >> 5;
    const int wm = wid >> 2, wn = wid & 3;
    const int m0 = blockIdx.y * 128, n0 = blockIdx.x * 128;

    const int am = tid >> 3;
    const int ak = (tid & 7) << 2;
    const int brow = tid >> 1;
    const int buc = (tid & 1) << 3;

    const uint32_t* BTg = w1T2 + (size_t)(n0 + brow) * (FEATP / 2);

    const float* pA[4]; const float* pS[4]; const float* pG[4];
    {
        int b = (m0 >= Ee) ? 1 : 0;
#pragma unroll
        for (int i = 0; i < 4; i++) {
            int r = m0 + am + 32 * i;
            int j = r - b * Ee;
            pA[i] = h + ((size_t)b * Nn + ei[j]) * Ff;
            pS[i] = h + ((size_t)b * Nn + ei[Ee + j]) * Ff;
            pG[i] = geo + (size_t)r * 32;
        }
    }
    auto loadA = [&](int i, int kcol) -> float4 {
        if (kcol < 128) return *(const float4*)(pA[i] + kcol);
        if (kcol < 256) return *(const float4*)(pS[i] + (kcol - 128));
        return *(const float4*)(pG[i] + (kcol - 256));
    };

    float acc[4][4][4];
#pragma unroll
    for (int i = 0; i < 4; i++)
#pragma unroll
        for (int j = 0; j < 4; j++) { acc[i][j][0] = 0.f; acc[i][j][1] = 0.f; acc[i][j][2] = 0.f; acc[i][j][3] = 0.f; }

    float4 pa[4]; uint4 pb[2];
#pragma unroll
    for (int i = 0; i < 4; i++) pa[i] = loadA(i, ak);
    pb[0] = *(const uint4*)(BTg + buc);
    pb[1] = *(const uint4*)(BTg + buc + 4);

    const uint32_t as_base = (uint32_t)__cvta_generic_to_shared(As);
    const uint32_t bs_base = (uint32_t)__cvta_generic_to_shared(Bs);
    const uint32_t ms_base = (uint32_t)__cvta_generic_to_shared(Ms);
    const int a_r = wm * 64 + (lane & 15);
    const int a_q = (lane >> 4) << 2;
    const int b_r = wn * 32 + (lane & 7) + ((lane >> 4) << 3);
    const int b_q = ((lane >> 3) & 1) << 2;

    // ---- stage 1 mainloop, K=288 ----
    for (int k0 = 0; k0 < FEATP; k0 += 32) {
#pragma unroll
        for (int i = 0; i < 4; i++)
            *(uint2*)&As[(am + 32 * i) * AST + (ak >> 1)] =
                make_uint2(f2h2(pa[i].x, pa[i].y), f2h2(pa[i].z, pa[i].w));
        *(uint4*)&Bs[brow * BST + buc]     = pb[0];
        *(uint4*)&Bs[brow * BST + buc + 4] = pb[1];
        __syncthreads();
        if (k0 + 32 < FEATP) {
#pragma unroll
            for (int i = 0; i < 4; i++) pa[i] = loadA(i, k0 + 32 + ak);
            int ku = (k0 + 32) >> 1;
            pb[0] = *(const uint4*)(BTg + ku + buc);
            pb[1] = *(const uint4*)(BTg + ku + buc + 4);
        }
#pragma unroll
        for (int kk = 0; kk < 2; kk++) {
            uint32_t af[4][4], bf[4][2];
#pragma unroll
            for (int mi = 0; mi < 4; mi++)
                ldsm4(af[mi][0], af[mi][1], af[mi][2], af[mi][3],
                      as_base + (((a_r + mi * 16) * AST + kk * 8 + a_q) << 2));
#pragma unroll
            for (int np = 0; np < 2; np++) {
                uint32_t r0, r1, r2, r3;
                ldsm4(r0, r1, r2, r3,
                      bs_base + (((b_r + np * 16) * BST + kk * 8 + b_q) << 2));
                bf[np * 2][0] = r0; bf[np * 2][1] = r1;
                bf[np * 2 + 1][0] = r2; bf[np * 2 + 1][1] = r3;
            }
#pragma unroll
            for (int mi = 0; mi < 4; mi++)
#pragma unroll
                for (int ni = 0; ni < 4; ni++)
                    mma16(acc[mi][ni], af[mi], bf[ni]);
        }
        __syncthreads();
    }

    // ---- epilogue 1: silu + bias -> Ms (half2), reset acc ----
    const int lrow0 = wm * 64 + (lane >> 2);
    const int lcolw = wn * 32 + ((lane & 3) << 1);
#pragma unroll
    for (int mi = 0; mi < 4; mi++) {
        int r = lrow0 + mi * 16;
#pragma unroll
        for (int ni = 0; ni < 4; ni++) {
            int col = lcolw + ni * 8;
            float2 bb = *(const float2*)(b1 + n0 + col);
            float v0 = silu_f(acc[mi][ni][0] + bb.x);
            float v1 = silu_f(acc[mi][ni][1] + bb.y);
            float v2 = silu_f(acc[mi][ni][2] + bb.x);
            float v3 = silu_f(acc[mi][ni][3] + bb.y);
            Ms[r * MST + (col >> 1)]       = f2h2(v0, v1);
            Ms[(r + 8) * MST + (col >> 1)] = f2h2(v2, v3);
            acc[mi][ni][0] = 0.f; acc[mi][ni][1] = 0.f;
            acc[mi][ni][2] = 0.f; acc[mi][ni][3] = 0.f;
        }
    }

    // ---- stage 2 mainloop, K=128, A from Ms ----
    const uint32_t* W22 = w2T2 + (size_t)blockIdx.x * (128 * 64) + (size_t)brow * 64;
    for (int k0 = 0; k0 < 128; k0 += 32) {
        int ku = k0 >> 1;
        *(uint4*)&Bs[brow * BST + buc]     = *(const uint4*)(W22 + ku + buc);
        *(uint4*)&Bs[brow * BST + buc + 4] = *(const uint4*)(W22 + ku + buc + 4);
        __syncthreads();
#pragma unroll
        for (int kk = 0; kk < 2; kk++) {
            uint32_t af[4][4], bf[4][2];
#pragma unroll
            for (int mi = 0; mi < 4; mi++)
                ldsm4(af[mi][0], af[mi][1], af[mi][2], af[mi][3],
                      ms_base + (((a_r + mi * 16) * MST + ku + kk * 8 + a_q) << 2));
#pragma unroll
            for (int np = 0; np < 2; np++) {
                uint32_t r0, r1, r2, r3;
                ldsm4(r0, r1, r2, r3,
                      bs_base + (((b_r + np * 16) * BST + kk * 8 + b_q) << 2));
                bf[np * 2][0] = r0; bf[np * 2][1] = r1;
                bf[np * 2 + 1][0] = r2; bf[np * 2 + 1][1] = r3;
            }
#pragma unroll
            for (int mi = 0; mi < 4; mi++)
#pragma unroll
                for (int ni = 0; ni < 4; ni++)
                    mma16(acc[mi][ni], af[mi], bf[ni]);
        }
        __syncthreads();
    }

    // ---- epilogue 2: + b2, store half2 to ef2, LN partial stats via atomics ----
#pragma unroll
    for (int mi = 0; mi < 4; mi++) {
        int r = m0 + lrow0 + mi * 16;
        float s_lo = 0.f, ss_lo = 0.f, s_hi = 0.f, ss_hi = 0.f;
#pragma unroll
        for (int ni = 0; ni < 4; ni++) {
            int col = n0 + lcolw + ni * 8;
            float2 bb = *(const float2*)(b2 + col);
            float v0 = acc[mi][ni][0] + bb.x, v1 = acc[mi][ni][1] + bb.y;
            float v2 = acc[mi][ni][2] + bb.x, v3 = acc[mi][ni][3] + bb.y;
            ef2[(size_t)r * (Hh / 2) + (col >> 1)]       = f2h2(v0, v1);
            ef2[(size_t)(r + 8) * (Hh / 2) + (col >> 1)] = f2h2(v2, v3);
            s_lo += v0 + v1; ss_lo += v0 * v0 + v1 * v1;
            s_hi += v2 + v3; ss_hi += v2 * v2 + v3 * v3;
        }
        s_lo  += __shfl_xor_sync(0xffffffffu, s_lo, 1);
        s_lo  += __shfl_xor_sync(0xffffffffu, s_lo, 2);
        ss_lo += __shfl_xor_sync(0xffffffffu, ss_lo, 1);
        ss_lo += __shfl_xor_sync(0xffffffffu, ss_lo, 2);
        s_hi  += __shfl_xor_sync(0xffffffffu, s_hi, 1);
        s_hi  += __shfl_xor_sync(0xffffffffu, s_hi, 2);
        ss_hi += __shfl_xor_sync(0xffffffffu, ss_hi, 1);
        ss_hi += __shfl_xor_sync(0xffffffffu, ss_hi, 2);
        if ((lane & 3) == 0) {
            atomicAdd(stats + 2 * (size_t)r,           s_lo);
            atomicAdd(stats + 2 * (size_t)r + 1,       ss_lo);
            atomicAdd(stats + 2 * (size_t)(r + 8),     s_hi);
            atomicAdd(stats + 2 * (size_t)(r + 8) + 1, ss_hi);
        }
    }
}

// Combined scatter (after GEMM3): LN from stats + agg segment-sum + coord scatter.
__global__ void k_scatter2(const float* __restrict__ gam, const float* __restrict__ bet,
                           const int* __restrict__ ei, float* __restrict__ outc) {
    int wid = blockIdx.x * (blockDim.x >> 5) + (threadIdx.x >> 5);
    int lane = threadIdx.x & 31;
    if (wid >= BE) return;
    const uint32_t* row = g_ef2 + (size_t)wid * (Hh / 2);
    float2 st = *(const float2*)(g_stats + 2 * (size_t)wid);
    float mu = st.x * (1.f / 256.f);
    float var = st.y * (1.f / 256.f) - mu * mu;
    float rstd = rsqrtf(var + 1e-5f);
    uint4 u = ((const uint4*)row)[lane];
    float2 f0 = h22f2(u.x), f1 = h22f2(u.y), f2v = h22f2(u.z), f3 = h22f2(u.w);
    float4 g0 = ((const float4*)gam)[2 * lane], g1 = ((const float4*)gam)[2 * lane + 1];
    float4 b0 = ((const float4*)bet)[2 * lane], b1 = ((const float4*)bet)[2 * lane + 1];
    float4 x0, x1;
    x0.x = (f0.x - mu) * rstd * g0.x + b0.x;
    x0.y = (f0.y - mu) * rstd * g0.y + b0.y;
    x0.z = (f1.x - mu) * rstd * g0.z + b0.z;
    x0.w = (f1.y - mu) * rstd * g0.w + b0.w;
    x1.x = (f2v.x - mu) * rstd * g1.x + b1.x;
    x1.y = (f2v.y - mu) * rstd * g1.y + b1.y;
    x1.z = (f3.x - mu) * rstd * g1.z + b1.z;
    x1.w = (f3.y - mu) * rstd * g1.w + b1.w;
    int b = (wid >= Ee) ? 1 : 0, j = wid - b * Ee;
    int i = ei[j];
    float* arow = g_agg + ((size_t)b * Nn + i) * Hh;
    red4(arow + 8 * lane, x0);
    red4(arow + 8 * lane + 4, x1);
    if (lane < 3) {
        float wv = g_wsc[wid];
        atomicAdd(&outc[((size_t)b * Nn + i) * 3 + lane], g_cdiff[wid * 3 + lane] * wv);
    }
}

// ---------------- launch ----------------
extern "C" void kernel_launch(void* const* d_in, const int* in_sizes, int n_in,
                              void* d_out, int out_size) {
    const float* h     = (const float*)d_in[0];
    const float* coord = (const float*)d_in[1];
    const int*   ei    = (const int*)d_in[2];
    const float* ew1   = (const float*)d_in[3];
    const float* eb1   = (const float*)d_in[4];
    const float* ew2   = (const float*)d_in[5];
    const float* eb2   = (const float*)d_in[6];
    const float* lng   = (const float*)d_in[7];
    const float* lnb   = (const float*)d_in[8];
    const float* nw1   = (const float*)d_in[9];
    const float* nb1   = (const float*)d_in[10];
    const float* nw2   = (const float*)d_in[11];
    const float* nb2   = (const float*)d_in[12];
    const float* cw1   = (const float*)d_in[13];
    const float* cb1   = (const float*)d_in[14];
    const float* cw2   = (const float*)d_in[15];

    float* out_h = (float*)d_out;
    float* out_c = out_h + (size_t)BNr * Ff;

    void *p_ef2, *p_stats, *p_geo, *p_w1T2, *p_w2T2, *p_cw1T2, *p_nw1T2, *p_nw2T2,
         *p_agg, *p_nodemid, *p_wsc;
    cudaGetSymbolAddress(&p_ef2,     g_ef2);
    cudaGetSymbolAddress(&p_stats,   g_stats);
    cudaGetSymbolAddress(&p_geo,     g_geo);
    cudaGetSymbolAddress(&p_w1T2,    g_w1T2);
    cudaGetSymbolAddress(&p_w2T2,    g_w2T2);
    cudaGetSymbolAddress(&p_cw1T2,   g_cw1T2);
    cudaGetSymbolAddress(&p_nw1T2,   g_nw1T2);
    cudaGetSymbolAddress(&p_nw2T2,   g_nw2T2);
    cudaGetSymbolAddress(&p_agg,     g_agg);
    cudaGetSymbolAddress(&p_nodemid, g_nodemid);
    cudaGetSymbolAddress(&p_wsc,     g_wsc);
    uint32_t*       ef2p     = (uint32_t*)p_ef2;
    float*          statsp   = (float*)p_stats;
    const float*    geop     = (const float*)p_geo;
    const uint32_t* w1T2p    = (const uint32_t*)p_w1T2;
    const uint32_t* w2T2p    = (const uint32_t*)p_w2T2;
    const uint32_t* cw1T2p   = (const uint32_t*)p_cw1T2;
    const uint32_t* nw1T2p   = (const uint32_t*)p_nw1T2;
    const uint32_t* nw2T2p   = (const uint32_t*)p_nw2T2;
    const float*    aggp     = (const float*)p_agg;
    float*          nodemidp = (float*)p_nodemid;
    float*          wscp     = (float*)p_wsc;

    cudaFuncSetAttribute(k_gemm12, cudaFuncAttributeMaxDynamicSharedMemorySize, G12_SMEM);
    cudaFuncSetAttribute(k_gemm3,  cudaFuncAttributeMaxDynamicSharedMemorySize, G3_SMEM);
    cudaFuncSetAttribute(k_gemm_t<2, 2>, cudaFuncAttributeMaxDynamicSharedMemorySize, GT_SMEM);
    cudaFuncSetAttribute(k_gemm_t<3, 0>, cudaFuncAttributeMaxDynamicSharedMemorySize, GT_SMEM);

    // init + weight packing (also zeroes stats/agg/wsc)
    k_misc<<<(BNr * Hh + 255) / 256, 256>>>(coord, out_c, ew1, ew2, cw1, nw1, nw2);
    k_geo<<<BE / 256, 256>>>(coord, ei);

    // fused GEMM1+GEMM2 (+ atomic LN stats), ef stored as half2
    k_gemm12<<<dim3(2, BE / 128), 256, G12_SMEM>>>(h, w1T2p, w2T2p, ef2p, ei, geop, eb1, eb2, statsp);

    // GEMM3: resident LN'd A, both N-halves, wsc dot
    k_gemm3<<<dim3(1, BE / 128), 256, G3_SMEM>>>(ef2p, cw1T2p, statsp, lng, lnb, cb1, cw2, wscp);

    // combined scatter: LN+agg segment-sum + coord scatter (wsc ready)
    k_scatter2<<<BE / 8, 256>>>(lng, lnb, ei, out_c);

    // node MLP (input concat fused via split-A)
    k_gemm_t<2, 2><<<dim3(2, BNr / 128), 256, GT_SMEM>>>(
        h, aggp, nw1T2p, nodemidp, Hh + Ff, 0, (Hh + Ff) / 2, Hh, nb1, nullptr, 0);
    k_gemm_t<3, 0><<<dim3(1, BNr / 128), 256, GT_SMEM>>>(
        nodemidp, nullptr, nw2T2p, out_h, Hh, Hh, Hh / 2, Ff, nb2, h, Ff);
}